// round 1
// baseline (speedup 1.0000x reference)
#include <cuda_runtime.h>
#include <cstdint>

#define NR 65536
#define KIN 2376
#define KP 2400          // K padded to multiple of 32
#define HID 1024
#define COUT 37
#define NBP 64           // padded GEMM2 output cols
#define EPSV 1e-5f

#define BM 128
#define BN1 128
#define BN2 64
#define BK 32
#define ASTR 36          // As row stride (conflict-free: bank=(4g+tg)%32 distinct)
#define BSTR1 136        // Bs stride gemm1 (bank=(8tg+g)%32 distinct)
#define BSTR2 72         // Bs stride gemm2

// ---- scratch (static device globals; no allocation) ----
__device__ float g_X[(size_t)NR * KP];        // tf32-rounded input matrix
__device__ float g_Y[(size_t)NR * HID];       // GEMM1 output (pre-BN)
__device__ float g_W1c[KP * HID];             // tf32 W1, zero-padded rows
__device__ float g_W2p[HID * NBP];            // tf32 W2, zero-padded cols
__device__ float g_bn4_acc[8];
__device__ float g_bn4_scale[4];
__device__ float g_bn4_shift[4];
__device__ float g_colsum[HID];
__device__ float g_colsq[HID];
__device__ float g_bn1_scale[HID];
__device__ float g_bn1_shift[HID];

__device__ __forceinline__ float to_tf32(float x) {
    uint32_t u;
    asm("cvt.rna.tf32.f32 %0, %1;" : "=r"(u) : "f"(x));
    return __uint_as_float(u);
}

__device__ __forceinline__ void mma_tf32(float* c, const uint32_t* a, const uint32_t* b) {
    asm volatile(
        "mma.sync.aligned.m16n8k8.row.col.f32.tf32.tf32.f32 "
        "{%0,%1,%2,%3}, {%4,%5,%6,%7}, {%8,%9}, {%0,%1,%2,%3};"
        : "+f"(c[0]), "+f"(c[1]), "+f"(c[2]), "+f"(c[3])
        : "r"(a[0]), "r"(a[1]), "r"(a[2]), "r"(a[3]), "r"(b[0]), "r"(b[1]));
}

// ---- init: zero accumulators ----
__global__ void k_init() {
    int t = blockIdx.x * blockDim.x + threadIdx.x;
    if (t < 8) g_bn4_acc[t] = 0.f;
    if (t < HID) { g_colsum[t] = 0.f; g_colsq[t] = 0.f; }
}

// ---- BN4: reduce sums of center_size(boxes) ----
__global__ void k_bn4_reduce(const float* __restrict__ boxes) {
    float s[4] = {0, 0, 0, 0}, q[4] = {0, 0, 0, 0};
    for (int i = blockIdx.x * blockDim.x + threadIdx.x; i < NR;
         i += gridDim.x * blockDim.x) {
        const float* b = boxes + (size_t)i * 5;
        float x1 = b[1], y1 = b[2], x2 = b[3], y2 = b[4];
        float w = x2 - x1, h = y2 - y1;
        float cx = x1 + 0.5f * w, cy = y1 + 0.5f * h;
        float v0 = cx, v1 = cy, v2 = w, v3 = h;
        s[0] += v0; s[1] += v1; s[2] += v2; s[3] += v3;
        q[0] += v0 * v0; q[1] += v1 * v1; q[2] += v2 * v2; q[3] += v3 * v3;
    }
    #pragma unroll
    for (int o = 16; o; o >>= 1) {
        #pragma unroll
        for (int j = 0; j < 4; j++) {
            s[j] += __shfl_down_sync(0xFFFFFFFFu, s[j], o);
            q[j] += __shfl_down_sync(0xFFFFFFFFu, q[j], o);
        }
    }
    __shared__ float sm[8][8];
    int warp = threadIdx.x >> 5, lane = threadIdx.x & 31;
    if (lane == 0) {
        #pragma unroll
        for (int j = 0; j < 4; j++) { sm[warp][j] = s[j]; sm[warp][4 + j] = q[j]; }
    }
    __syncthreads();
    if (threadIdx.x == 0) {
        float a[8] = {0, 0, 0, 0, 0, 0, 0, 0};
        for (int w2 = 0; w2 < 8; w2++)
            for (int j = 0; j < 8; j++) a[j] += sm[w2][j];
        for (int j = 0; j < 8; j++) atomicAdd(&g_bn4_acc[j], a[j]);
    }
}

__global__ void k_bn4_fin(const float* __restrict__ g4, const float* __restrict__ b4) {
    int j = threadIdx.x;
    if (j < 4) {
        float m = g_bn4_acc[j] / (float)NR;
        float v = g_bn4_acc[4 + j] / (float)NR - m * m;
        float sc = g4[j] * rsqrtf(v + EPSV);
        g_bn4_scale[j] = sc;
        g_bn4_shift[j] = b4[j] - m * sc;
    }
}

// ---- prep: build X[N, KP] = tf32(features | dist@objW | relu(bn4@posW+posB) | 0pad) ----
__global__ __launch_bounds__(256) void k_prep(
    const float* __restrict__ dist, const float* __restrict__ boxes,
    const float* __restrict__ feat, const float* __restrict__ objW,
    const float* __restrict__ posW, const float* __restrict__ posB) {
    int row = blockIdx.x;
    int t = threadIdx.x;
    __shared__ float sd[36];
    __shared__ float s4[4];
    if (t < 36) sd[t] = dist[(size_t)row * 36 + t];
    if (t >= 64 && t < 68) {
        int j = t - 64;
        const float* b = boxes + (size_t)row * 5;
        float x1 = b[1], y1 = b[2], x2 = b[3], y2 = b[4];
        float w = x2 - x1, h = y2 - y1;
        float v = (j == 0) ? (x1 + 0.5f * w) : (j == 1) ? (y1 + 0.5f * h) : (j == 2) ? w : h;
        s4[j] = v * g_bn4_scale[j] + g_bn4_shift[j];
    }
    __syncthreads();

    float* xr = g_X + (size_t)row * KP;
    const float4* f4 = (const float4*)(feat + (size_t)row * 2048);
    float4* x4 = (float4*)xr;
    #pragma unroll 2
    for (int i = t; i < 512; i += 256) {
        float4 v = f4[i];
        v.x = to_tf32(v.x); v.y = to_tf32(v.y); v.z = to_tf32(v.z); v.w = to_tf32(v.w);
        x4[i] = v;
    }
    if (t < 200) {
        float acc = 0.f;
        #pragma unroll
        for (int k = 0; k < 36; k++) acc += sd[k] * __ldg(&objW[k * 200 + t]);
        xr[2048 + t] = to_tf32(acc);
    }
    if (t < 128) {
        float acc = __ldg(&posB[t]);
        #pragma unroll
        for (int k = 0; k < 4; k++) acc += s4[k] * __ldg(&posW[k * 128 + t]);
        xr[2248 + t] = to_tf32(fmaxf(acc, 0.f));
    }
    if (t >= 128 && t < 128 + (KP - KIN)) xr[KIN + (t - 128)] = 0.f;
}

// ---- weight conversion ----
__global__ void k_convw1(const float* __restrict__ w1) {
    int idx = blockIdx.x * blockDim.x + threadIdx.x;
    if (idx >= KP * HID) return;
    int k = idx / HID, n = idx - k * HID;
    g_W1c[idx] = (k < KIN) ? to_tf32(w1[(size_t)k * HID + n]) : 0.f;
}
__global__ void k_convw2(const float* __restrict__ w2) {
    int idx = blockIdx.x * blockDim.x + threadIdx.x;
    if (idx >= HID * NBP) return;
    int k = idx / NBP, n = idx - k * NBP;
    g_W2p[idx] = (n < COUT) ? to_tf32(w2[(size_t)k * COUT + n]) : 0.f;
}

// ---- GEMM1: Y = X @ W1c  (128x128x32 tiles, tf32 mma, double-buffered) ----
__global__ __launch_bounds__(256) void k_gemm1() {
    extern __shared__ float smem[];
    float* As = smem;                       // 2 * BM * ASTR
    float* Bs = smem + 2 * BM * ASTR;       // 2 * BK * BSTR1

    int t = threadIdx.x;
    int warp = t >> 5, lane = t & 31;
    int wr = warp >> 1, wc = warp & 1;      // 4x2 warp grid, warp tile 32x64
    int g = lane >> 2, tg = lane & 3;
    const size_t rowBase = (size_t)blockIdx.y * BM;
    const int colBase = blockIdx.x * BN1;
    const float* Ag = g_X + rowBase * KP;
    const float* Bg = g_W1c + colBase;

    float acc[2][8][4];
    #pragma unroll
    for (int i = 0; i < 2; i++)
        #pragma unroll
        for (int j = 0; j < 8; j++)
            #pragma unroll
            for (int c = 0; c < 4; c++) acc[i][j][c] = 0.f;

    float4 ra[4], rb[4];
    // prologue stage buffer 0
    #pragma unroll
    for (int i = 0; i < 4; i++) {
        int idx = t + i * 256;
        { int r = idx >> 3, c = idx & 7;  ra[i] = *(const float4*)(Ag + (size_t)r * KP + c * 4); }
        { int r = idx >> 5, c = idx & 31; rb[i] = *(const float4*)(Bg + (size_t)r * HID + c * 4); }
    }
    #pragma unroll
    for (int i = 0; i < 4; i++) {
        int idx = t + i * 256;
        { int r = idx >> 3, c = idx & 7;  *(float4*)&As[r * ASTR + c * 4] = ra[i]; }
        { int r = idx >> 5, c = idx & 31; *(float4*)&Bs[r * BSTR1 + c * 4] = rb[i]; }
    }
    __syncthreads();

    const int NIT = KP / BK;  // 75
    for (int it = 0; it < NIT; ++it) {
        int cur = it & 1;
        if (it + 1 < NIT) {
            int k0 = (it + 1) * BK;
            #pragma unroll
            for (int i = 0; i < 4; i++) {
                int idx = t + i * 256;
                { int r = idx >> 3, c = idx & 7;  ra[i] = *(const float4*)(Ag + (size_t)r * KP + k0 + c * 4); }
                { int r = idx >> 5, c = idx & 31; rb[i] = *(const float4*)(Bg + (size_t)(k0 + r) * HID + c * 4); }
            }
        }
        const float* Asb = As + cur * BM * ASTR;
        const float* Bsb = Bs + cur * BK * BSTR1;
        #pragma unroll
        for (int kk = 0; kk < 4; kk++) {
            uint32_t af[2][4];
            #pragma unroll
            for (int rt = 0; rt < 2; rt++) {
                int r0 = wr * 32 + rt * 16 + g;
                af[rt][0] = __float_as_uint(Asb[r0 * ASTR + kk * 8 + tg]);
                af[rt][1] = __float_as_uint(Asb[(r0 + 8) * ASTR + kk * 8 + tg]);
                af[rt][2] = __float_as_uint(Asb[r0 * ASTR + kk * 8 + tg + 4]);
                af[rt][3] = __float_as_uint(Asb[(r0 + 8) * ASTR + kk * 8 + tg + 4]);
            }
            #pragma unroll
            for (int s = 0; s < 8; s++) {
                int cc = wc * 64 + s * 8 + g;
                uint32_t bf[2];
                bf[0] = __float_as_uint(Bsb[(kk * 8 + tg) * BSTR1 + cc]);
                bf[1] = __float_as_uint(Bsb[(kk * 8 + tg + 4) * BSTR1 + cc]);
                mma_tf32(acc[0][s], af[0], bf);
                mma_tf32(acc[1][s], af[1], bf);
            }
        }
        if (it + 1 < NIT) {
            float* Asn = As + (cur ^ 1) * BM * ASTR;
            float* Bsn = Bs + (cur ^ 1) * BK * BSTR1;
            #pragma unroll
            for (int i = 0; i < 4; i++) {
                int idx = t + i * 256;
                { int r = idx >> 3, c = idx & 7;  *(float4*)&Asn[r * ASTR + c * 4] = ra[i]; }
                { int r = idx >> 5, c = idx & 31; *(float4*)&Bsn[r * BSTR1 + c * 4] = rb[i]; }
            }
        }
        __syncthreads();
    }

    // epilogue: write Y (dec_b1 cancels in BN)
    #pragma unroll
    for (int rt = 0; rt < 2; rt++) {
        int r0 = wr * 32 + rt * 16 + g;
        #pragma unroll
        for (int s = 0; s < 8; s++) {
            int cc = colBase + wc * 64 + s * 8 + 2 * tg;
            float* y0 = g_Y + (rowBase + r0) * HID + cc;
            y0[0] = acc[rt][s][0]; y0[1] = acc[rt][s][1];
            float* y1 = g_Y + (rowBase + r0 + 8) * HID + cc;
            y1[0] = acc[rt][s][2]; y1[1] = acc[rt][s][3];
        }
    }
}

// ---- BN1 column reduction over Y ----
__global__ void k_bn1_reduce() {
    int col = blockIdx.x * 128 + threadIdx.x;
    size_t r0 = (size_t)blockIdx.y * (NR / 64);
    const float* p = g_Y + r0 * HID + col;
    float s = 0.f, q = 0.f;
    for (int r = 0; r < NR / 64; r++) {
        float v = p[(size_t)r * HID];
        s += v; q += v * v;
    }
    atomicAdd(&g_colsum[col], s);
    atomicAdd(&g_colsq[col], q);
}

__global__ void k_bn1_fin(const float* __restrict__ g1, const float* __restrict__ b1) {
    int c = blockIdx.x * blockDim.x + threadIdx.x;
    if (c < HID) {
        float m = g_colsum[c] / (float)NR;
        float v = g_colsq[c] / (float)NR - m * m;
        float sc = g1[c] * rsqrtf(v + EPSV);
        g_bn1_scale[c] = sc;
        g_bn1_shift[c] = b1[c] - m * sc;
    }
}

// ---- GEMM2: out = relu(BN(Y)) @ W2p + b2  (128x64x32 tiles) ----
__global__ __launch_bounds__(256) void k_gemm2(const float* __restrict__ b2,
                                               float* __restrict__ out) {
    extern __shared__ float smem[];
    float* As = smem;                      // 2 * BM * ASTR
    float* Bs = smem + 2 * BM * ASTR;      // 2 * BK * BSTR2

    int t = threadIdx.x;
    int warp = t >> 5, lane = t & 31;
    int wr = warp >> 1, wc = warp & 1;     // warp tile 32x32
    int g = lane >> 2, tg = lane & 3;
    const size_t rowBase = (size_t)blockIdx.y * BM;
    const float* Ag = g_Y + rowBase * HID;
    const float* Bg = g_W2p;

    float acc[2][4][4];
    #pragma unroll
    for (int i = 0; i < 2; i++)
        #pragma unroll
        for (int j = 0; j < 4; j++)
            #pragma unroll
            for (int c = 0; c < 4; c++) acc[i][j][c] = 0.f;

    float4 ra[4], rb[2];
    // prologue
    #pragma unroll
    for (int i = 0; i < 4; i++) {
        int idx = t + i * 256;
        int r = idx >> 3, c = idx & 7;
        float4 v = *(const float4*)(Ag + (size_t)r * HID + c * 4);
        float4 sc = *(const float4*)&g_bn1_scale[c * 4];
        float4 sh = *(const float4*)&g_bn1_shift[c * 4];
        v.x = to_tf32(fmaxf(v.x * sc.x + sh.x, 0.f));
        v.y = to_tf32(fmaxf(v.y * sc.y + sh.y, 0.f));
        v.z = to_tf32(fmaxf(v.z * sc.z + sh.z, 0.f));
        v.w = to_tf32(fmaxf(v.w * sc.w + sh.w, 0.f));
        ra[i] = v;
    }
    #pragma unroll
    for (int i = 0; i < 2; i++) {
        int idx = t + i * 256;
        int r = idx >> 4, c = idx & 15;
        rb[i] = *(const float4*)(Bg + (size_t)r * NBP + c * 4);
    }
    #pragma unroll
    for (int i = 0; i < 4; i++) {
        int idx = t + i * 256;
        int r = idx >> 3, c = idx & 7;
        *(float4*)&As[r * ASTR + c * 4] = ra[i];
    }
    #pragma unroll
    for (int i = 0; i < 2; i++) {
        int idx = t + i * 256;
        int r = idx >> 4, c = idx & 15;
        *(float4*)&Bs[r * BSTR2 + c * 4] = rb[i];
    }
    __syncthreads();

    const int NIT = HID / BK;  // 32
    for (int it = 0; it < NIT; ++it) {
        int cur = it & 1;
        if (it + 1 < NIT) {
            int k0 = (it + 1) * BK;
            #pragma unroll
            for (int i = 0; i < 4; i++) {
                int idx = t + i * 256;
                int r = idx >> 3, c = idx & 7;
                float4 v = *(const float4*)(Ag + (size_t)r * HID + k0 + c * 4);
                float4 sc = *(const float4*)&g_bn1_scale[k0 + c * 4];
                float4 sh = *(const float4*)&g_bn1_shift[k0 + c * 4];
                v.x = to_tf32(fmaxf(v.x * sc.x + sh.x, 0.f));
                v.y = to_tf32(fmaxf(v.y * sc.y + sh.y, 0.f));
                v.z = to_tf32(fmaxf(v.z * sc.z + sh.z, 0.f));
                v.w = to_tf32(fmaxf(v.w * sc.w + sh.w, 0.f));
                ra[i] = v;
            }
            #pragma unroll
            for (int i = 0; i < 2; i++) {
                int idx = t + i * 256;
                int r = idx >> 4, c = idx & 15;
                rb[i] = *(const float4*)(Bg + (size_t)(k0 + r) * NBP + c * 4);
            }
        }
        const float* Asb = As + cur * BM * ASTR;
        const float* Bsb = Bs + cur * BK * BSTR2;
        #pragma unroll
        for (int kk = 0; kk < 4; kk++) {
            uint32_t af[2][4];
            #pragma unroll
            for (int rt = 0; rt < 2; rt++) {
                int r0 = wr * 32 + rt * 16 + g;
                af[rt][0] = __float_as_uint(Asb[r0 * ASTR + kk * 8 + tg]);
                af[rt][1] = __float_as_uint(Asb[(r0 + 8) * ASTR + kk * 8 + tg]);
                af[rt][2] = __float_as_uint(Asb[r0 * ASTR + kk * 8 + tg + 4]);
                af[rt][3] = __float_as_uint(Asb[(r0 + 8) * ASTR + kk * 8 + tg + 4]);
            }
            #pragma unroll
            for (int s = 0; s < 4; s++) {
                int cc = wc * 32 + s * 8 + g;
                uint32_t bf[2];
                bf[0] = __float_as_uint(Bsb[(kk * 8 + tg) * BSTR2 + cc]);
                bf[1] = __float_as_uint(Bsb[(kk * 8 + tg + 4) * BSTR2 + cc]);
                mma_tf32(acc[0][s], af[0], bf);
                mma_tf32(acc[1][s], af[1], bf);
            }
        }
        if (it + 1 < NIT) {
            float* Asn = As + (cur ^ 1) * BM * ASTR;
            float* Bsn = Bs + (cur ^ 1) * BK * BSTR2;
            #pragma unroll
            for (int i = 0; i < 4; i++) {
                int idx = t + i * 256;
                int r = idx >> 3, c = idx & 7;
                *(float4*)&Asn[r * ASTR + c * 4] = ra[i];
            }
            #pragma unroll
            for (int i = 0; i < 2; i++) {
                int idx = t + i * 256;
                int r = idx >> 4, c = idx & 15;
                *(float4*)&Bsn[r * BSTR2 + c * 4] = rb[i];
            }
        }
        __syncthreads();
    }

    // epilogue: add bias, write only cols < 37
    #pragma unroll
    for (int rt = 0; rt < 2; rt++) {
        int r0 = wr * 32 + rt * 16 + g;
        #pragma unroll
        for (int s = 0; s < 4; s++) {
            int col = wc * 32 + s * 8 + 2 * tg;
            size_t ro0 = (rowBase + r0) * COUT;
            size_t ro1 = (rowBase + r0 + 8) * COUT;
            if (col < COUT) {
                float bb = b2[col];
                out[ro0 + col] = acc[rt][s][0] + bb;
                out[ro1 + col] = acc[rt][s][2] + bb;
            }
            if (col + 1 < COUT) {
                float bb = b2[col + 1];
                out[ro0 + col + 1] = acc[rt][s][1] + bb;
                out[ro1 + col + 1] = acc[rt][s][3] + bb;
            }
        }
    }
}

extern "C" void kernel_launch(void* const* d_in, const int* in_sizes, int n_in,
                              void* d_out, int out_size) {
    const float* dist  = (const float*)d_in[0];
    const float* boxes = (const float*)d_in[1];
    const float* feat  = (const float*)d_in[2];
    const float* objW  = (const float*)d_in[3];
    const float* bn4g  = (const float*)d_in[4];
    const float* bn4b  = (const float*)d_in[5];
    const float* posW  = (const float*)d_in[6];
    const float* posB  = (const float*)d_in[7];
    const float* w1    = (const float*)d_in[8];
    // d_in[9] = dec_b1: cancels inside BatchNorm, unused
    const float* bn1g  = (const float*)d_in[10];
    const float* bn1b  = (const float*)d_in[11];
    const float* w2    = (const float*)d_in[12];
    const float* b2    = (const float*)d_in[13];
    float* out = (float*)d_out;

    const int SMEM1 = (2 * BM * ASTR + 2 * BK * BSTR1) * 4;  // 71680
    const int SMEM2 = (2 * BM * ASTR + 2 * BK * BSTR2) * 4;  // 55296
    cudaFuncSetAttribute(k_gemm1, cudaFuncAttributeMaxDynamicSharedMemorySize, SMEM1);
    cudaFuncSetAttribute(k_gemm2, cudaFuncAttributeMaxDynamicSharedMemorySize, SMEM2);

    k_init<<<4, 256>>>();
    k_bn4_reduce<<<256, 256>>>(boxes);
    k_bn4_fin<<<1, 32>>>(bn4g, bn4b);
    k_prep<<<NR, 256>>>(dist, boxes, feat, objW, posW, posB);
    k_convw1<<<(KP * HID + 255) / 256, 256>>>(w1);
    k_convw2<<<(HID * NBP + 255) / 256, 256>>>(w2);
    dim3 g1(HID / BN1, NR / BM);
    k_gemm1<<<g1, 256, SMEM1>>>();
    k_bn1_reduce<<<dim3(HID / 128, 64), 128>>>();
    k_bn1_fin<<<4, 256>>>(bn1g, bn1b);
    k_gemm2<<<dim3(1, NR / BM), 256, SMEM2>>>(b2, out);
}

// round 3
// speedup vs baseline: 1.6037x; 1.6037x over previous
#include <cuda_runtime.h>
#include <cuda_fp16.h>
#include <cstdint>

#define NR 65536
#define KIN 2376
#define KP 2400          // K padded (multiple of 32)
#define HID 1024
#define COUT 37
#define EPSV 1e-5f

// GEMM1 tiling: block 128x128, BK=32 halves, 8 warps of 32x64
#define STAGE_B 20480    // A 128*80 + B 128*80 bytes
#define SMEM_G1 (3 * STAGE_B)
// GEMM2: block 128x64, BK=32, 8 warps of 32x32
#define STAGE2_B 15360   // A 128*80 + B 64*80
#define SMEM_G2 (8192 + 3 * STAGE2_B)

// ---- scratch (static device globals; no allocation) ----
__device__ __half g_X[(size_t)NR * KP];       // fp16 input matrix [N, KP]
__device__ __half g_Y[(size_t)NR * HID];      // GEMM1 output fp16 (pre-BN)
__device__ __half g_W1t[(size_t)HID * KP];    // W1 transposed [n][k] fp16, zero-padded k
__device__ __half g_W2t[(size_t)64 * HID];    // W2 transposed [n][k] fp16, zero-padded n
__device__ float g_bn4_acc[8];
__device__ float g_bn4_scale[4];
__device__ float g_bn4_shift[4];
__device__ float g_colsum[HID];
__device__ float g_colsq[HID];
__device__ float g_bn1_scale[HID];
__device__ float g_bn1_shift[HID];

__device__ __forceinline__ uint32_t smem_u32(const void* p) {
    uint32_t a;
    asm("{ .reg .u64 t; cvta.to.shared.u64 t, %1; cvt.u32.u64 %0, t; }" : "=r"(a) : "l"(p));
    return a;
}
__device__ __forceinline__ void cpa16(uint32_t dst, const void* src) {
    asm volatile("cp.async.cg.shared.global [%0], [%1], 16;" :: "r"(dst), "l"(src));
}
__device__ __forceinline__ void cpa_commit() {
    asm volatile("cp.async.commit_group;" ::: "memory");
}
__device__ __forceinline__ void cpa_wait1() {
    asm volatile("cp.async.wait_group 1;" ::: "memory");
}

__device__ __forceinline__ void mma16816(float* c, const uint32_t* a, uint32_t b0, uint32_t b1) {
    asm volatile(
        "mma.sync.aligned.m16n8k16.row.col.f32.f16.f16.f32 "
        "{%0,%1,%2,%3}, {%4,%5,%6,%7}, {%8,%9}, {%0,%1,%2,%3};"
        : "+f"(c[0]), "+f"(c[1]), "+f"(c[2]), "+f"(c[3])
        : "r"(a[0]), "r"(a[1]), "r"(a[2]), "r"(a[3]), "r"(b0), "r"(b1));
}

// ---- init ----
__global__ void k_init() {
    int t = blockIdx.x * blockDim.x + threadIdx.x;
    if (t < 8) g_bn4_acc[t] = 0.f;
    if (t < HID) { g_colsum[t] = 0.f; g_colsq[t] = 0.f; }
}

// ---- BN4 stats ----
__global__ void k_bn4_reduce(const float* __restrict__ boxes) {
    float s[4] = {0, 0, 0, 0}, q[4] = {0, 0, 0, 0};
    for (int i = blockIdx.x * blockDim.x + threadIdx.x; i < NR;
         i += gridDim.x * blockDim.x) {
        const float* b = boxes + (size_t)i * 5;
        float x1 = b[1], y1 = b[2], x2 = b[3], y2 = b[4];
        float w = x2 - x1, h = y2 - y1;
        float v0 = x1 + 0.5f * w, v1 = y1 + 0.5f * h, v2 = w, v3 = h;
        s[0] += v0; s[1] += v1; s[2] += v2; s[3] += v3;
        q[0] += v0 * v0; q[1] += v1 * v1; q[2] += v2 * v2; q[3] += v3 * v3;
    }
    #pragma unroll
    for (int o = 16; o; o >>= 1) {
        #pragma unroll
        for (int j = 0; j < 4; j++) {
            s[j] += __shfl_down_sync(0xFFFFFFFFu, s[j], o);
            q[j] += __shfl_down_sync(0xFFFFFFFFu, q[j], o);
        }
    }
    __shared__ float sm[8][8];
    int warp = threadIdx.x >> 5, lane = threadIdx.x & 31;
    if (lane == 0) {
        #pragma unroll
        for (int j = 0; j < 4; j++) { sm[warp][j] = s[j]; sm[warp][4 + j] = q[j]; }
    }
    __syncthreads();
    if (threadIdx.x == 0) {
        float a[8] = {0, 0, 0, 0, 0, 0, 0, 0};
        for (int w2 = 0; w2 < 8; w2++)
            for (int j = 0; j < 8; j++) a[j] += sm[w2][j];
        for (int j = 0; j < 8; j++) atomicAdd(&g_bn4_acc[j], a[j]);
    }
}

__global__ void k_bn4_fin(const float* __restrict__ g4, const float* __restrict__ b4) {
    int j = threadIdx.x;
    if (j < 4) {
        float m = g_bn4_acc[j] / (float)NR;
        float v = g_bn4_acc[4 + j] / (float)NR - m * m;
        float sc = g4[j] * rsqrtf(v + EPSV);
        g_bn4_scale[j] = sc;
        g_bn4_shift[j] = b4[j] - m * sc;
    }
}

// ---- prep: build fp16 X[N, KP] ----
__global__ __launch_bounds__(256) void k_prep(
    const float* __restrict__ dist, const float* __restrict__ boxes,
    const float* __restrict__ feat, const float* __restrict__ objW,
    const float* __restrict__ posW, const float* __restrict__ posB) {
    int row = blockIdx.x;
    int t = threadIdx.x;
    __shared__ float sd[36];
    __shared__ float s4[4];
    if (t < 36) sd[t] = dist[(size_t)row * 36 + t];
    if (t >= 64 && t < 68) {
        int j = t - 64;
        const float* b = boxes + (size_t)row * 5;
        float x1 = b[1], y1 = b[2], x2 = b[3], y2 = b[4];
        float w = x2 - x1, h = y2 - y1;
        float v = (j == 0) ? (x1 + 0.5f * w) : (j == 1) ? (y1 + 0.5f * h) : (j == 2) ? w : h;
        s4[j] = v * g_bn4_scale[j] + g_bn4_shift[j];
    }
    __syncthreads();

    __half* xr = g_X + (size_t)row * KP;
    const float4* f4 = (const float4*)(feat + (size_t)row * 2048);
    #pragma unroll 2
    for (int i = t; i < 512; i += 256) {
        float4 v = f4[i];
        __half2 h01 = __floats2half2_rn(v.x, v.y);
        __half2 h23 = __floats2half2_rn(v.z, v.w);
        uint2 u;
        u.x = *(uint32_t*)&h01; u.y = *(uint32_t*)&h23;
        *(uint2*)(xr + i * 4) = u;
    }
    if (t < 200) {
        float acc = 0.f;
        #pragma unroll
        for (int k = 0; k < 36; k++) acc += sd[k] * __ldg(&objW[k * 200 + t]);
        xr[2048 + t] = __float2half(acc);
    }
    if (t < 128) {
        float acc = __ldg(&posB[t]);
        #pragma unroll
        for (int k = 0; k < 4; k++) acc += s4[k] * __ldg(&posW[k * 128 + t]);
        xr[2248 + t] = __float2half(fmaxf(acc, 0.f));
    }
    if (t >= 128 && t < 128 + (KP - KIN)) xr[KIN + (t - 128)] = __float2half(0.f);
}

// ---- W1 transpose to fp16 [n][k] ----
__global__ void k_transp_w1(const float* __restrict__ w1) {
    __shared__ float sm[32][33];
    int k0 = blockIdx.x * 32, n0 = blockIdx.y * 32;
    int tx = threadIdx.x, ty = threadIdx.y;
    int k = k0 + ty, n = n0 + tx;
    sm[ty][tx] = (k < KIN) ? w1[(size_t)k * HID + n] : 0.f;
    __syncthreads();
    g_W1t[(size_t)(n0 + ty) * KP + k0 + tx] = __float2half(sm[tx][ty]);
}

// ---- W2 transpose to fp16 [n=64][k=1024], zero-pad n>=37 ----
__global__ void k_transp_w2(const float* __restrict__ w2) {
    int idx = blockIdx.x * 256 + threadIdx.x;
    if (idx >= 64 * HID) return;
    int n = idx >> 10, k = idx & 1023;
    g_W2t[idx] = __float2half(n < COUT ? w2[(size_t)k * COUT + n] : 0.f);
}

// ---- GEMM1: Y = X @ W1  fp16 mma, 128x128 blocks, cp.async 3-stage ----
__device__ __forceinline__ void g1_load(uint32_t sbase, int s, const __half* Ag,
                                        const __half* Bg, int chunk, int t) {
    int k0 = chunk * 32;
    uint32_t aB = sbase + s * STAGE_B;
    uint32_t bB = aB + 10240;
    #pragma unroll
    for (int i = 0; i < 2; i++) {
        int idx = t + i * 256;
        int r = idx >> 2, c = idx & 3;
        cpa16(aB + r * 80 + c * 16, Ag + (size_t)r * KP + k0 + c * 8);
        cpa16(bB + r * 80 + c * 16, Bg + (size_t)r * KP + k0 + c * 8);
    }
}

__global__ __launch_bounds__(256) void k_gemm1() {
    extern __shared__ char sm1[];
    uint32_t sbase = smem_u32(sm1);
    int t = threadIdx.x;
    int warp = t >> 5, lane = t & 31;
    int wr = warp >> 1, wc = warp & 1;      // 4x2 warps, tile 32x64
    int g = lane >> 2, tg = lane & 3;
    const size_t rowBase = (size_t)blockIdx.y * 128;
    const int colBase = blockIdx.x * 128;
    const __half* Ag = g_X + rowBase * KP;
    const __half* Bg = g_W1t + (size_t)colBase * KP;

    float acc[2][8][4];
    #pragma unroll
    for (int i = 0; i < 2; i++)
        #pragma unroll
        for (int j = 0; j < 8; j++)
            #pragma unroll
            for (int c = 0; c < 4; c++) acc[i][j][c] = 0.f;

    g1_load(sbase, 0, Ag, Bg, 0, t); cpa_commit();
    g1_load(sbase, 1, Ag, Bg, 1, t); cpa_commit();

    const int NIT = KP / 32;   // 75
    for (int it = 0; it < NIT; ++it) {
        cpa_wait1();
        __syncthreads();
        if (it + 2 < NIT) g1_load(sbase, (it + 2) % 3, Ag, Bg, it + 2, t);
        cpa_commit();

        const char* aS = sm1 + (it % 3) * STAGE_B;
        const char* bS = aS + 10240;
        #pragma unroll
        for (int kk = 0; kk < 2; kk++) {
            int kb = (kk * 16 + 2 * tg) * 2;
            uint32_t a[2][4];
            #pragma unroll
            for (int rt = 0; rt < 2; rt++) {
                int r0 = wr * 32 + rt * 16 + g;
                a[rt][0] = *(const uint32_t*)(aS + r0 * 80 + kb);
                a[rt][1] = *(const uint32_t*)(aS + (r0 + 8) * 80 + kb);
                a[rt][2] = *(const uint32_t*)(aS + r0 * 80 + kb + 16);
                a[rt][3] = *(const uint32_t*)(aS + (r0 + 8) * 80 + kb + 16);
            }
            #pragma unroll
            for (int s = 0; s < 8; s++) {
                int n = wc * 64 + s * 8 + g;
                uint32_t b0 = *(const uint32_t*)(bS + n * 80 + kb);
                uint32_t b1 = *(const uint32_t*)(bS + n * 80 + kb + 16);
                mma16816(acc[0][s], a[0], b0, b1);
                mma16816(acc[1][s], a[1], b0, b1);
            }
        }
    }

    // epilogue: write Y as fp16
    #pragma unroll
    for (int rt = 0; rt < 2; rt++) {
        size_t r0 = rowBase + wr * 32 + rt * 16 + g;
        #pragma unroll
        for (int s = 0; s < 8; s++) {
            int cc = colBase + wc * 64 + s * 8 + 2 * tg;
            __half2 h0 = __floats2half2_rn(acc[rt][s][0], acc[rt][s][1]);
            __half2 h1 = __floats2half2_rn(acc[rt][s][2], acc[rt][s][3]);
            *(__half2*)(g_Y + r0 * HID + cc) = h0;
            *(__half2*)(g_Y + (r0 + 8) * HID + cc) = h1;
        }
    }
}

// ---- BN1 column stats over fp16 Y ----
__global__ __launch_bounds__(128) void k_bn1_reduce() {
    int col = blockIdx.x * 128 + threadIdx.x;
    size_t r0 = (size_t)blockIdx.y * 1024;
    const __half* p = g_Y + r0 * HID + col;
    float s = 0.f, q = 0.f;
    #pragma unroll 4
    for (int r = 0; r < 1024; r++) {
        float v = __half2float(p[(size_t)r * HID]);
        s += v; q += v * v;
    }
    atomicAdd(&g_colsum[col], s);
    atomicAdd(&g_colsq[col], q);
}

__global__ void k_bn1_fin(const float* __restrict__ g1, const float* __restrict__ b1) {
    int c = blockIdx.x * blockDim.x + threadIdx.x;
    if (c < HID) {
        float m = g_colsum[c] / (float)NR;
        float v = g_colsq[c] / (float)NR - m * m;
        float sc = g1[c] * rsqrtf(v + EPSV);
        g_bn1_scale[c] = sc;
        g_bn1_shift[c] = b1[c] - m * sc;
    }
}

// ---- GEMM2: out = relu(BN(Y)) @ W2 + b2 ----
__device__ __forceinline__ uint32_t bn_h2(uint32_t raw, float2 sc, float2 sh) {
    __half2 h = *(__half2*)&raw;
    float2 f = __half22float2(h);
    f.x = fmaxf(f.x * sc.x + sh.x, 0.f);
    f.y = fmaxf(f.y * sc.y + sh.y, 0.f);
    __half2 o = __floats2half2_rn(f.x, f.y);
    return *(uint32_t*)&o;
}

__device__ __forceinline__ void g2_load(uint32_t sbase, int s, const __half* Ag,
                                        int chunk, int t) {
    int k0 = chunk * 32;
    uint32_t aB = sbase + 8192 + s * STAGE2_B;
    uint32_t bB = aB + 10240;
    #pragma unroll
    for (int i = 0; i < 2; i++) {
        int idx = t + i * 256;
        int r = idx >> 2, c = idx & 3;
        cpa16(aB + r * 80 + c * 16, Ag + (size_t)r * HID + k0 + c * 8);
    }
    {
        int r = t >> 2, c = t & 3;   // r in 0..63 exactly
        cpa16(bB + r * 80 + c * 16, g_W2t + (size_t)r * HID + k0 + c * 8);
    }
}

__global__ __launch_bounds__(256) void k_gemm2(const float* __restrict__ b2,
                                               float* __restrict__ out) {
    extern __shared__ char sm2[];
    float* s_scale = (float*)sm2;
    float* s_shift = s_scale + 1024;
    uint32_t sbase = smem_u32(sm2);
    int t = threadIdx.x;
    int warp = t >> 5, lane = t & 31;
    int wr = warp >> 1, wc = warp & 1;      // 4x2 warps, tile 32x32
    int g = lane >> 2, tg = lane & 3;
    const size_t rowBase = (size_t)blockIdx.y * 128;
    const __half* Ag = g_Y + rowBase * HID;

    #pragma unroll
    for (int i = t; i < 1024; i += 256) {
        s_scale[i] = g_bn1_scale[i];
        s_shift[i] = g_bn1_shift[i];
    }

    float acc[2][4][4];
    #pragma unroll
    for (int i = 0; i < 2; i++)
        #pragma unroll
        for (int j = 0; j < 4; j++)
            #pragma unroll
            for (int c = 0; c < 4; c++) acc[i][j][c] = 0.f;

    g2_load(sbase, 0, Ag, 0, t); cpa_commit();
    g2_load(sbase, 1, Ag, 1, t); cpa_commit();

    const int NIT = HID / 32;  // 32
    for (int it = 0; it < NIT; ++it) {
        cpa_wait1();
        __syncthreads();
        if (it + 2 < NIT) g2_load(sbase, (it + 2) % 3, Ag, it + 2, t);
        cpa_commit();

        const char* aS = sm2 + 8192 + (it % 3) * STAGE2_B;
        const char* bS = aS + 10240;
        #pragma unroll
        for (int kk = 0; kk < 2; kk++) {
            int kloc = kk * 16 + 2 * tg;
            int kglob = it * 32 + kloc;
            float2 sc0 = *(float2*)(s_scale + kglob);
            float2 sh0 = *(float2*)(s_shift + kglob);
            float2 sc1 = *(float2*)(s_scale + kglob + 8);
            float2 sh1 = *(float2*)(s_shift + kglob + 8);
            int kb = kloc * 2;
            uint32_t a[2][4];
            #pragma unroll
            for (int rt = 0; rt < 2; rt++) {
                int r0 = wr * 32 + rt * 16 + g;
                a[rt][0] = bn_h2(*(const uint32_t*)(aS + r0 * 80 + kb), sc0, sh0);
                a[rt][1] = bn_h2(*(const uint32_t*)(aS + (r0 + 8) * 80 + kb), sc0, sh0);
                a[rt][2] = bn_h2(*(const uint32_t*)(aS + r0 * 80 + kb + 16), sc1, sh1);
                a[rt][3] = bn_h2(*(const uint32_t*)(aS + (r0 + 8) * 80 + kb + 16), sc1, sh1);
            }
            #pragma unroll
            for (int s = 0; s < 4; s++) {
                int n = wc * 32 + s * 8 + g;
                uint32_t b0 = *(const uint32_t*)(bS + n * 80 + kb);
                uint32_t b1 = *(const uint32_t*)(bS + n * 80 + kb + 16);
                mma16816(acc[0][s], a[0], b0, b1);
                mma16816(acc[1][s], a[1], b0, b1);
            }
        }
    }

    #pragma unroll
    for (int rt = 0; rt < 2; rt++) {
        size_t r0 = rowBase + wr * 32 + rt * 16 + g;
        #pragma unroll
        for (int s = 0; s < 4; s++) {
            int cc = wc * 32 + s * 8 + 2 * tg;
            if (cc < COUT) {
                float bb = __ldg(&b2[cc]);
                out[r0 * COUT + cc] = acc[rt][s][0] + bb;
                out[(r0 + 8) * COUT + cc] = acc[rt][s][2] + bb;
            }
            if (cc + 1 < COUT) {
                float bb = __ldg(&b2[cc + 1]);
                out[r0 * COUT + cc + 1] = acc[rt][s][1] + bb;
                out[(r0 + 8) * COUT + cc + 1] = acc[rt][s][3] + bb;
            }
        }
    }
}

extern "C" void kernel_launch(void* const* d_in, const int* in_sizes, int n_in,
                              void* d_out, int out_size) {
    const float* dist  = (const float*)d_in[0];
    const float* boxes = (const float*)d_in[1];
    const float* feat  = (const float*)d_in[2];
    const float* objW  = (const float*)d_in[3];
    const float* bn4g  = (const float*)d_in[4];
    const float* bn4b  = (const float*)d_in[5];
    const float* posW  = (const float*)d_in[6];
    const float* posB  = (const float*)d_in[7];
    const float* w1    = (const float*)d_in[8];
    // d_in[9] = dec_b1: cancels inside BatchNorm, unused
    const float* bn1g  = (const float*)d_in[10];
    const float* bn1b  = (const float*)d_in[11];
    const float* w2    = (const float*)d_in[12];
    const float* b2    = (const float*)d_in[13];
    float* out = (float*)d_out;

    cudaFuncSetAttribute(k_gemm1, cudaFuncAttributeMaxDynamicSharedMemorySize, SMEM_G1);
    cudaFuncSetAttribute(k_gemm2, cudaFuncAttributeMaxDynamicSharedMemorySize, SMEM_G2);

    k_init<<<4, 256>>>();
    k_bn4_reduce<<<256, 256>>>(boxes);
    k_bn4_fin<<<1, 32>>>(bn4g, bn4b);
    k_prep<<<NR, 256>>>(dist, boxes, feat, objW, posW, posB);
    k_transp_w1<<<dim3(KP / 32, HID / 32), dim3(32, 32)>>>(w1);
    k_transp_w2<<<(64 * HID + 255) / 256, 256>>>(w2);
    k_gemm1<<<dim3(HID / 128, NR / 128), 256, SMEM_G1>>>();
    k_bn1_reduce<<<dim3(HID / 128, 64), 128>>>();
    k_bn1_fin<<<4, 256>>>(bn1g, bn1b);
    k_gemm2<<<dim3(1, NR / 128), 256, SMEM_G2>>>(b2, out);
}

// round 5
// speedup vs baseline: 1.6861x; 1.0514x over previous
#include <cuda_runtime.h>
#include <cuda_fp16.h>
#include <cstdint>

#define NR 65536
#define KIN 2376
#define KP 2432          // K padded (multiple of 64)
#define HID 1024
#define COUT 37
#define EPSV 1e-5f

// GEMM1: block 256x128, BK=64, 8 warps of 64x64, ldmatrix + cp.async 3-stage
#define G1_BM 256
#define G1_BN 128
#define G1_BK 64
#define G1_STRIDE 144                     // 128B data + 16B pad per k-row
#define G1_ASZ (G1_BM * G1_STRIDE)        // 36864
#define G1_BSZ (G1_BN * G1_STRIDE)        // 18432
#define G1_STAGE (G1_ASZ + G1_BSZ)        // 55296
#define SMEM_G1 (3 * G1_STAGE)            // 165888
#define G1_NIT (KP / G1_BK)               // 38

// GEMM2: block 128x64, BK=32, 8 warps of 32x32
#define STAGE2_B 15360
#define SMEM_G2 (8192 + 3 * STAGE2_B)

// ---- scratch (static device globals; no allocation) ----
__device__ __half g_X[(size_t)NR * KP];
__device__ __half g_Y[(size_t)NR * HID];
__device__ __half g_W1t[(size_t)HID * KP];    // W1 [n][k] fp16, zero-padded k
__device__ __half g_W2t[(size_t)64 * HID];    // W2 [n][k] fp16, zero-padded n
__device__ float g_bn4_acc[8];
__device__ float g_bn4_scale[4];
__device__ float g_bn4_shift[4];
__device__ float g_colsum[HID];
__device__ float g_colsq[HID];
__device__ float g_bn1_scale[HID];
__device__ float g_bn1_shift[HID];

__device__ __forceinline__ uint32_t smem_u32(const void* p) {
    uint32_t a;
    asm("{ .reg .u64 t; cvta.to.shared.u64 t, %1; cvt.u32.u64 %0, t; }" : "=r"(a) : "l"(p));
    return a;
}
__device__ __forceinline__ void cpa16(uint32_t dst, const void* src) {
    asm volatile("cp.async.cg.shared.global [%0], [%1], 16;" :: "r"(dst), "l"(src));
}
__device__ __forceinline__ void cpa_commit() {
    asm volatile("cp.async.commit_group;" ::: "memory");
}
__device__ __forceinline__ void cpa_wait1() {
    asm volatile("cp.async.wait_group 1;" ::: "memory");
}
__device__ __forceinline__ void ldsm4(uint32_t* r, uint32_t addr) {
    asm volatile("ldmatrix.sync.aligned.m8n8.x4.shared.b16 {%0,%1,%2,%3}, [%4];"
                 : "=r"(r[0]), "=r"(r[1]), "=r"(r[2]), "=r"(r[3]) : "r"(addr));
}
__device__ __forceinline__ void mma16816(float* c, const uint32_t* a, uint32_t b0, uint32_t b1) {
    asm volatile(
        "mma.sync.aligned.m16n8k16.row.col.f32.f16.f16.f32 "
        "{%0,%1,%2,%3}, {%4,%5,%6,%7}, {%8,%9}, {%0,%1,%2,%3};"
        : "+f"(c[0]), "+f"(c[1]), "+f"(c[2]), "+f"(c[3])
        : "r"(a[0]), "r"(a[1]), "r"(a[2]), "r"(a[3]), "r"(b0), "r"(b1));
}

// ---- init ----
__global__ void k_init() {
    int t = blockIdx.x * blockDim.x + threadIdx.x;
    if (t < 8) g_bn4_acc[t] = 0.f;
    if (t < HID) { g_colsum[t] = 0.f; g_colsq[t] = 0.f; }
}

// ---- BN4 stats ----
__global__ void k_bn4_reduce(const float* __restrict__ boxes) {
    float s[4] = {0, 0, 0, 0}, q[4] = {0, 0, 0, 0};
    for (int i = blockIdx.x * blockDim.x + threadIdx.x; i < NR;
         i += gridDim.x * blockDim.x) {
        const float* b = boxes + (size_t)i * 5;
        float x1 = b[1], y1 = b[2], x2 = b[3], y2 = b[4];
        float w = x2 - x1, h = y2 - y1;
        float v0 = x1 + 0.5f * w, v1 = y1 + 0.5f * h, v2 = w, v3 = h;
        s[0] += v0; s[1] += v1; s[2] += v2; s[3] += v3;
        q[0] += v0 * v0; q[1] += v1 * v1; q[2] += v2 * v2; q[3] += v3 * v3;
    }
    #pragma unroll
    for (int o = 16; o; o >>= 1) {
        #pragma unroll
        for (int j = 0; j < 4; j++) {
            s[j] += __shfl_down_sync(0xFFFFFFFFu, s[j], o);
            q[j] += __shfl_down_sync(0xFFFFFFFFu, q[j], o);
        }
    }
    __shared__ float sm[8][8];
    int warp = threadIdx.x >> 5, lane = threadIdx.x & 31;
    if (lane == 0) {
        #pragma unroll
        for (int j = 0; j < 4; j++) { sm[warp][j] = s[j]; sm[warp][4 + j] = q[j]; }
    }
    __syncthreads();
    if (threadIdx.x == 0) {
        float a[8] = {0, 0, 0, 0, 0, 0, 0, 0};
        for (int w2 = 0; w2 < 8; w2++)
            for (int j = 0; j < 8; j++) a[j] += sm[w2][j];
        for (int j = 0; j < 8; j++) atomicAdd(&g_bn4_acc[j], a[j]);
    }
}

__global__ void k_bn4_fin(const float* __restrict__ g4, const float* __restrict__ b4) {
    int j = threadIdx.x;
    if (j < 4) {
        float m = g_bn4_acc[j] / (float)NR;
        float v = g_bn4_acc[4 + j] / (float)NR - m * m;
        float sc = g4[j] * rsqrtf(v + EPSV);
        g_bn4_scale[j] = sc;
        g_bn4_shift[j] = b4[j] - m * sc;
    }
}

// ---- feat streaming convert: X[:, 0:2048] = fp16(feat) ----
__global__ __launch_bounds__(256) void k_feat(const float* __restrict__ feat) {
    int nth = gridDim.x * 256;
    for (int cid = blockIdx.x * 256 + threadIdx.x; cid < NR * 256; cid += nth) {
        int row = cid >> 8, c = cid & 255;
        const float4* s = (const float4*)(feat + (size_t)row * 2048 + c * 8);
        float4 v0 = s[0], v1 = s[1];
        __half2 h0 = __floats2half2_rn(v0.x, v0.y);
        __half2 h1 = __floats2half2_rn(v0.z, v0.w);
        __half2 h2 = __floats2half2_rn(v1.x, v1.y);
        __half2 h3 = __floats2half2_rn(v1.z, v1.w);
        uint4 u;
        u.x = *(uint32_t*)&h0; u.y = *(uint32_t*)&h1;
        u.z = *(uint32_t*)&h2; u.w = *(uint32_t*)&h3;
        *(uint4*)(g_X + (size_t)row * KP + c * 8) = u;
    }
}

// ---- embed + pos + zero pad: X[:, 2048:2432]; one warp per row ----
__global__ __launch_bounds__(256) void k_embed(
    const float* __restrict__ dist, const float* __restrict__ boxes,
    const float* __restrict__ objW, const float* __restrict__ posW,
    const float* __restrict__ posB) {
    __shared__ float sd[8][36];
    int warp = threadIdx.x >> 5, lane = threadIdx.x & 31;
    size_t row = (size_t)blockIdx.x * 8 + warp;
    for (int j = lane; j < 36; j += 32) sd[warp][j] = dist[row * 36 + j];
    __syncwarp();
    __half* xr = g_X + row * KP;
    for (int c = lane; c < 200; c += 32) {
        float acc = 0.f;
        #pragma unroll
        for (int k = 0; k < 36; k++) acc += sd[warp][k] * __ldg(&objW[k * 200 + c]);
        xr[2048 + c] = __float2half(acc);
    }
    const float* b = boxes + row * 5;
    float x1 = __ldg(b + 1), y1 = __ldg(b + 2), x2 = __ldg(b + 3), y2 = __ldg(b + 4);
    float w = x2 - x1, h = y2 - y1;
    float s4[4] = {x1 + 0.5f * w, y1 + 0.5f * h, w, h};
    #pragma unroll
    for (int j = 0; j < 4; j++) s4[j] = s4[j] * g_bn4_scale[j] + g_bn4_shift[j];
    for (int c = lane; c < 128; c += 32) {
        float acc = __ldg(&posB[c]);
        #pragma unroll
        for (int k = 0; k < 4; k++) acc += s4[k] * __ldg(&posW[k * 128 + c]);
        xr[2248 + c] = __float2half(fmaxf(acc, 0.f));
    }
    for (int c = lane; c < KP - KIN; c += 32) xr[KIN + c] = __float2half(0.f);
}

// ---- W1 transpose to fp16 [n][k=KP] ----
__global__ void k_transp_w1(const float* __restrict__ w1) {
    __shared__ float sm[32][33];
    int k0 = blockIdx.x * 32, n0 = blockIdx.y * 32;
    int tx = threadIdx.x, ty = threadIdx.y;
    int k = k0 + ty, n = n0 + tx;
    sm[ty][tx] = (k < KIN) ? w1[(size_t)k * HID + n] : 0.f;
    __syncthreads();
    g_W1t[(size_t)(n0 + ty) * KP + k0 + tx] = __float2half(sm[tx][ty]);
}

// ---- W2 transpose to fp16 [n=64][k=1024] ----
__global__ void k_transp_w2(const float* __restrict__ w2) {
    int idx = blockIdx.x * 256 + threadIdx.x;
    if (idx >= 64 * HID) return;
    int n = idx >> 10, k = idx & 1023;
    g_W2t[idx] = __float2half(n < COUT ? w2[(size_t)k * COUT + n] : 0.f);
}

// ---- GEMM1: Y = X @ W1, 256x128 blocks, ldmatrix, cp.async 3-stage ----
__device__ __forceinline__ void g1_load(uint32_t sbase, int slot, const __half* Ag,
                                        const __half* Bg, int chunk, int t) {
    int k0 = chunk * G1_BK;
    uint32_t aB = sbase + slot * G1_STAGE;
    uint32_t bB = aB + G1_ASZ;
    #pragma unroll
    for (int i = 0; i < 8; i++) {       // A: 256 rows x 8 chunks
        int idx = t + i * 256;
        int r = idx >> 3, c = idx & 7;
        cpa16(aB + r * G1_STRIDE + c * 16, Ag + (size_t)r * KP + k0 + c * 8);
    }
    #pragma unroll
    for (int i = 0; i < 4; i++) {       // B: 128 rows x 8 chunks
        int idx = t + i * 256;
        int r = idx >> 3, c = idx & 7;
        cpa16(bB + r * G1_STRIDE + c * 16, Bg + (size_t)r * KP + k0 + c * 8);
    }
}

__global__ __launch_bounds__(256, 1) void k_gemm1() {
    extern __shared__ char sm1[];
    uint32_t sbase = smem_u32(sm1);
    int t = threadIdx.x, warp = t >> 5, lane = t & 31;
    int wr = warp >> 1, wc = warp & 1;      // 4x2 warps, warp tile 64x64
    int g = lane >> 2, tg = lane & 3;
    const size_t rowBase = (size_t)blockIdx.y * G1_BM;
    const int colBase = blockIdx.x * G1_BN;
    const __half* Ag = g_X + rowBase * KP;
    const __half* Bg = g_W1t + (size_t)colBase * KP;

    float acc[4][8][4];
    #pragma unroll
    for (int i = 0; i < 4; i++)
        #pragma unroll
        for (int j = 0; j < 8; j++)
            #pragma unroll
            for (int c = 0; c < 4; c++) acc[i][j][c] = 0.f;

    // per-lane ldmatrix offsets (relative to stage base)
    const uint32_t aOff = (uint32_t)((wr * 64 + (lane & 15)) * G1_STRIDE + ((lane >> 4) << 4));
    const uint32_t bOff = (uint32_t)(G1_ASZ +
        (wc * 64 + (lane & 7) + ((lane >> 4) << 3)) * G1_STRIDE + (((lane >> 3) & 1) << 4));

    g1_load(sbase, 0, Ag, Bg, 0, t); cpa_commit();
    g1_load(sbase, 1, Ag, Bg, 1, t); cpa_commit();

    for (int it = 0; it < G1_NIT; ++it) {
        cpa_wait1();
        __syncthreads();
        if (it + 2 < G1_NIT) g1_load(sbase, (it + 2) % 3, Ag, Bg, it + 2, t);
        cpa_commit();

        uint32_t st = sbase + (it % 3) * G1_STAGE;
        #pragma unroll
        for (int kk = 0; kk < 4; kk++) {        // 4 x k16
            uint32_t a[4][4], b[4][4];
            #pragma unroll
            for (int mt = 0; mt < 4; mt++)
                ldsm4(a[mt], st + aOff + mt * (16 * G1_STRIDE) + kk * 32);
            #pragma unroll
            for (int ng = 0; ng < 4; ng++)
                ldsm4(b[ng], st + bOff + ng * (16 * G1_STRIDE) + kk * 32);
            #pragma unroll
            for (int mt = 0; mt < 4; mt++)
                #pragma unroll
                for (int s = 0; s < 8; s++)
                    mma16816(acc[mt][s], a[mt], b[s >> 1][(s & 1) * 2], b[s >> 1][(s & 1) * 2 + 1]);
        }
    }

    // epilogue: Y fp16
    #pragma unroll
    for (int mt = 0; mt < 4; mt++) {
        size_t r0 = rowBase + wr * 64 + mt * 16 + g;
        #pragma unroll
        for (int s = 0; s < 8; s++) {
            int cc = colBase + wc * 64 + s * 8 + 2 * tg;
            __half2 h0 = __floats2half2_rn(acc[mt][s][0], acc[mt][s][1]);
            __half2 h1 = __floats2half2_rn(acc[mt][s][2], acc[mt][s][3]);
            *(__half2*)(g_Y + r0 * HID + cc) = h0;
            *(__half2*)(g_Y + (r0 + 8) * HID + cc) = h1;
        }
    }
}

// ---- BN1 column stats over fp16 Y ----
__global__ __launch_bounds__(128) void k_bn1_reduce() {
    int col = blockIdx.x * 128 + threadIdx.x;
    size_t r0 = (size_t)blockIdx.y * 1024;
    const __half* p = g_Y + r0 * HID + col;
    float s = 0.f, q = 0.f;
    #pragma unroll 4
    for (int r = 0; r < 1024; r++) {
        float v = __half2float(p[(size_t)r * HID]);
        s += v; q += v * v;
    }
    atomicAdd(&g_colsum[col], s);
    atomicAdd(&g_colsq[col], q);
}

__global__ void k_bn1_fin(const float* __restrict__ g1, const float* __restrict__ b1) {
    int c = blockIdx.x * blockDim.x + threadIdx.x;
    if (c < HID) {
        float m = g_colsum[c] / (float)NR;
        float v = g_colsq[c] / (float)NR - m * m;
        float sc = g1[c] * rsqrtf(v + EPSV);
        g_bn1_scale[c] = sc;
        g_bn1_shift[c] = b1[c] - m * sc;
    }
}

// ---- GEMM2: out = relu(BN(Y)) @ W2 + b2 ----
__device__ __forceinline__ uint32_t bn_h2(uint32_t raw, float2 sc, float2 sh) {
    __half2 h = *(__half2*)&raw;
    float2 f = __half22float2(h);
    f.x = fmaxf(f.x * sc.x + sh.x, 0.f);
    f.y = fmaxf(f.y * sc.y + sh.y, 0.f);
    __half2 o = __floats2half2_rn(f.x, f.y);
    return *(uint32_t*)&o;
}

__device__ __forceinline__ void g2_load(uint32_t sbase, int s, const __half* Ag,
                                        int chunk, int t) {
    int k0 = chunk * 32;
    uint32_t aB = sbase + 8192 + s * STAGE2_B;
    uint32_t bB = aB + 10240;
    #pragma unroll
    for (int i = 0; i < 2; i++) {
        int idx = t + i * 256;
        int r = idx >> 2, c = idx & 3;
        cpa16(aB + r * 80 + c * 16, Ag + (size_t)r * HID + k0 + c * 8);
    }
    {
        int r = t >> 2, c = t & 3;
        cpa16(bB + r * 80 + c * 16, g_W2t + (size_t)r * HID + k0 + c * 8);
    }
}

__global__ __launch_bounds__(256) void k_gemm2(const float* __restrict__ b2,
                                               float* __restrict__ out) {
    extern __shared__ char sm2[];
    float* s_scale = (float*)sm2;
    float* s_shift = s_scale + 1024;
    uint32_t sbase = smem_u32(sm2);
    int t = threadIdx.x;
    int warp = t >> 5, lane = t & 31;
    int wr = warp >> 1, wc = warp & 1;
    int g = lane >> 2, tg = lane & 3;
    const size_t rowBase = (size_t)blockIdx.y * 128;
    const __half* Ag = g_Y + rowBase * HID;

    #pragma unroll
    for (int i = t; i < 1024; i += 256) {
        s_scale[i] = g_bn1_scale[i];
        s_shift[i] = g_bn1_shift[i];
    }

    float acc[2][4][4];
    #pragma unroll
    for (int i = 0; i < 2; i++)
        #pragma unroll
        for (int j = 0; j < 4; j++)
            #pragma unroll
            for (int c = 0; c < 4; c++) acc[i][j][c] = 0.f;

    g2_load(sbase, 0, Ag, 0, t); cpa_commit();
    g2_load(sbase, 1, Ag, 1, t); cpa_commit();

    const int NIT = HID / 32;
    for (int it = 0; it < NIT; ++it) {
        cpa_wait1();
        __syncthreads();
        if (it + 2 < NIT) g2_load(sbase, (it + 2) % 3, Ag, it + 2, t);
        cpa_commit();

        const char* aS = sm2 + 8192 + (it % 3) * STAGE2_B;
        const char* bS = aS + 10240;
        #pragma unroll
        for (int kk = 0; kk < 2; kk++) {
            int kloc = kk * 16 + 2 * tg;
            int kglob = it * 32 + kloc;
            float2 sc0 = *(float2*)(s_scale + kglob);
            float2 sh0 = *(float2*)(s_shift + kglob);
            float2 sc1 = *(float2*)(s_scale + kglob + 8);
            float2 sh1 = *(float2*)(s_shift + kglob + 8);
            int kb = kloc * 2;
            uint32_t a[2][4];
            #pragma unroll
            for (int rt = 0; rt < 2; rt++) {
                int r0 = wr * 32 + rt * 16 + g;
                a[rt][0] = bn_h2(*(const uint32_t*)(aS + r0 * 80 + kb), sc0, sh0);
                a[rt][1] = bn_h2(*(const uint32_t*)(aS + (r0 + 8) * 80 + kb), sc0, sh0);
                a[rt][2] = bn_h2(*(const uint32_t*)(aS + r0 * 80 + kb + 16), sc1, sh1);
                a[rt][3] = bn_h2(*(const uint32_t*)(aS + (r0 + 8) * 80 + kb + 16), sc1, sh1);
            }
            #pragma unroll
            for (int s = 0; s < 4; s++) {
                int n = wc * 32 + s * 8 + g;
                uint32_t b0 = *(const uint32_t*)(bS + n * 80 + kb);
                uint32_t b1 = *(const uint32_t*)(bS + n * 80 + kb + 16);
                mma16816(acc[0][s], a[0], b0, b1);
                mma16816(acc[1][s], a[1], b0, b1);
            }
        }
    }

    #pragma unroll
    for (int rt = 0; rt < 2; rt++) {
        size_t r0 = rowBase + wr * 32 + rt * 16 + g;
        #pragma unroll
        for (int s = 0; s < 4; s++) {
            int cc = wc * 32 + s * 8 + 2 * tg;
            if (cc < COUT) {
                float bb = __ldg(&b2[cc]);
                out[r0 * COUT + cc] = acc[rt][s][0] + bb;
                out[(r0 + 8) * COUT + cc] = acc[rt][s][2] + bb;
            }
            if (cc + 1 < COUT) {
                float bb = __ldg(&b2[cc + 1]);
                out[r0 * COUT + cc + 1] = acc[rt][s][1] + bb;
                out[(r0 + 8) * COUT + cc + 1] = acc[rt][s][3] + bb;
            }
        }
    }
}

extern "C" void kernel_launch(void* const* d_in, const int* in_sizes, int n_in,
                              void* d_out, int out_size) {
    const float* dist  = (const float*)d_in[0];
    const float* boxes = (const float*)d_in[1];
    const float* feat  = (const float*)d_in[2];
    const float* objW  = (const float*)d_in[3];
    const float* bn4g  = (const float*)d_in[4];
    const float* bn4b  = (const float*)d_in[5];
    const float* posW  = (const float*)d_in[6];
    const float* posB  = (const float*)d_in[7];
    const float* w1    = (const float*)d_in[8];
    // d_in[9] = dec_b1: cancels inside BatchNorm, unused
    const float* bn1g  = (const float*)d_in[10];
    const float* bn1b  = (const float*)d_in[11];
    const float* w2    = (const float*)d_in[12];
    const float* b2    = (const float*)d_in[13];
    float* out = (float*)d_out;

    cudaFuncSetAttribute(k_gemm1, cudaFuncAttributeMaxDynamicSharedMemorySize, SMEM_G1);
    cudaFuncSetAttribute(k_gemm2, cudaFuncAttributeMaxDynamicSharedMemorySize, SMEM_G2);

    k_init<<<4, 256>>>();
    k_bn4_reduce<<<256, 256>>>(boxes);
    k_bn4_fin<<<1, 32>>>(bn4g, bn4b);
    k_feat<<<4096, 256>>>(feat);
    k_embed<<<NR / 8, 256>>>(dist, boxes, objW, posW, posB);
    k_transp_w1<<<dim3(KP / 32, HID / 32), dim3(32, 32)>>>(w1);
    k_transp_w2<<<(64 * HID + 255) / 256, 256>>>(w2);
    k_gemm1<<<dim3(HID / G1_BN, NR / G1_BM), 256, SMEM_G1>>>();
    k_bn1_reduce<<<dim3(HID / 128, 64), 128>>>();
    k_bn1_fin<<<4, 256>>>(bn1g, bn1b);
    k_gemm2<<<dim3(1, NR / 128), 256, SMEM_G2>>>(b2, out);
}

// round 6
// speedup vs baseline: 1.8031x; 1.0694x over previous
#include <cuda_runtime.h>
#include <cuda_fp16.h>
#include <cstdint>

#define NR 65536
#define HID 1024
#define COUT 37
#define EPSV 1e-5f
#define KP2 2240         // folded K: 2048 feat + 36 dist + 128 pos + 28 pad

// GEMM1: block 128x256, BK=64, 8 warps of 32x128, ldmatrix + cp.async 4-stage
#define G1_BM 128
#define G1_BN 256
#define G1_BK 64
#define G1_STRIDE 144                     // 128B data + 16B pad per k-row
#define G1_ASZ (G1_BM * G1_STRIDE)        // 18432
#define G1_BSZ (G1_BN * G1_STRIDE)        // 36864
#define G1_STAGE (G1_ASZ + G1_BSZ)        // 55296
#define G1_STAGES 4
#define SMEM_G1 (G1_STAGES * G1_STAGE)    // 221184
#define G1_NIT (KP2 / G1_BK)              // 35

// GEMM2: block 128x64, BK=32, 8 warps of 32x32
#define STAGE2_B 15360
#define SMEM_G2 (8192 + 3 * STAGE2_B)

// ---- scratch (static device globals; no allocation) ----
__device__ __half g_X[(size_t)NR * KP2];
__device__ __half g_Y[(size_t)NR * HID];
__device__ __half g_W1t[(size_t)HID * KP2];   // W1' [n][k] fp16 (embed folded via M36)
__device__ __half g_W2t[(size_t)64 * HID];    // W2 [n][k] fp16, zero-padded n
__device__ float g_bn4_scale[4];
__device__ float g_bn4_shift[4];
__device__ float g_colsum[HID];
__device__ float g_colsq[HID];
__device__ float g_bn1_scale[HID];
__device__ float g_bn1_shift[HID];

__device__ __forceinline__ uint32_t smem_u32(const void* p) {
    uint32_t a;
    asm("{ .reg .u64 t; cvta.to.shared.u64 t, %1; cvt.u32.u64 %0, t; }" : "=r"(a) : "l"(p));
    return a;
}
__device__ __forceinline__ void cpa16(uint32_t dst, const void* src) {
    asm volatile("cp.async.cg.shared.global [%0], [%1], 16;" :: "r"(dst), "l"(src));
}
__device__ __forceinline__ void cpa_commit() {
    asm volatile("cp.async.commit_group;" ::: "memory");
}
__device__ __forceinline__ void cpa_wait2() {
    asm volatile("cp.async.wait_group 2;" ::: "memory");
}
__device__ __forceinline__ void cpa_wait1() {
    asm volatile("cp.async.wait_group 1;" ::: "memory");
}
__device__ __forceinline__ void ldsm4(uint32_t* r, uint32_t addr) {
    asm volatile("ldmatrix.sync.aligned.m8n8.x4.shared.b16 {%0,%1,%2,%3}, [%4];"
                 : "=r"(r[0]), "=r"(r[1]), "=r"(r[2]), "=r"(r[3]) : "r"(addr));
}
__device__ __forceinline__ void mma16816(float* c, const uint32_t* a, uint32_t b0, uint32_t b1) {
    asm volatile(
        "mma.sync.aligned.m16n8k16.row.col.f32.f16.f16.f32 "
        "{%0,%1,%2,%3}, {%4,%5,%6,%7}, {%8,%9}, {%0,%1,%2,%3};"
        : "+f"(c[0]), "+f"(c[1]), "+f"(c[2]), "+f"(c[3])
        : "r"(a[0]), "r"(a[1]), "r"(a[2]), "r"(a[3]), "r"(b0), "r"(b1));
}

// ============ k_pre: fused feat-convert + W1 transpose + M36 fold + W2 + init =======
// roles by blockIdx.x:
//  [0,4096)       feat fp32->fp16 streaming into X[:,0:2048]
//  [4096,6272)    W1 transpose 32x32 tiles (feat rows 0..2047 -> k same;
//                 pos rows 2248..2375 -> k 2084..2211)
//  [6272,6304)    M36 = objW @ W1[2048:2248,:]  -> W1t k 2048..2083; zero pad k 2212..2239
//  [6304]         zero colsum/colsq
//  [6305,6561)    W2 transpose [n=64][k=1024]
#define RB_TR 4096
#define RB_M36 6272
#define RB_INIT 6304
#define RB_W2 6305
#define PRE_GRID 6561

__global__ __launch_bounds__(256) void k_pre(
    const float* __restrict__ feat, const float* __restrict__ w1,
    const float* __restrict__ objW, const float* __restrict__ w2) {
    int b = blockIdx.x, t = threadIdx.x;
    if (b < RB_TR) {
        for (size_t cid = (size_t)b * 256 + t; cid < (size_t)NR * 256; cid += (size_t)RB_TR * 256) {
            size_t row = cid >> 8;
            int c = (int)(cid & 255);
            const float4* s = (const float4*)(feat + row * 2048 + c * 8);
            float4 v0 = s[0], v1 = s[1];
            __half2 h0 = __floats2half2_rn(v0.x, v0.y);
            __half2 h1 = __floats2half2_rn(v0.z, v0.w);
            __half2 h2 = __floats2half2_rn(v1.x, v1.y);
            __half2 h3 = __floats2half2_rn(v1.z, v1.w);
            uint4 u;
            u.x = *(uint32_t*)&h0; u.y = *(uint32_t*)&h1;
            u.z = *(uint32_t*)&h2; u.w = *(uint32_t*)&h3;
            *(uint4*)(g_X + row * KP2 + c * 8) = u;
        }
    } else if (b < RB_M36) {
        __shared__ float sm[32][33];
        int tile = b - RB_TR;
        int kt = tile % 68, nt = tile / 68;
        int n0 = nt * 32;
        int k0 = (kt < 64) ? kt * 32 : 2248 + (kt - 64) * 32;     // source row in W1
        int dk0 = (kt < 64) ? kt * 32 : 2084 + (kt - 64) * 32;    // dest k in W1t
        int tx = t & 31, tyb = t >> 5;
        #pragma unroll
        for (int p = 0; p < 4; p++) {
            int ty = tyb + p * 8;
            sm[ty][tx] = w1[(size_t)(k0 + ty) * HID + n0 + tx];
        }
        __syncthreads();
        #pragma unroll
        for (int p = 0; p < 4; p++) {
            int ty = tyb + p * 8;
            g_W1t[(size_t)(n0 + ty) * KP2 + dk0 + tx] = __float2half(sm[tx][ty]);
        }
    } else if (b < RB_INIT) {
        int n = (b - RB_M36) * 32 + (t & 31);
        for (int j = t >> 5; j < 36; j += 8) {
            float acc = 0.f;
            for (int p = 0; p < 200; p++)
                acc += __ldg(&objW[j * 200 + p]) * __ldg(&w1[(size_t)(2048 + p) * HID + n]);
            g_W1t[(size_t)n * KP2 + 2048 + j] = __float2half(acc);
        }
        for (int k = 2212 + (t >> 5); k < KP2; k += 8)
            g_W1t[(size_t)n * KP2 + k] = __float2half(0.f);
    } else if (b == RB_INIT) {
        for (int i = t; i < HID; i += 256) { g_colsum[i] = 0.f; g_colsq[i] = 0.f; }
    } else {
        int idx = (b - RB_W2) * 256 + t;
        int n = idx >> 10, k = idx & 1023;
        g_W2t[idx] = __float2half(n < COUT ? w2[(size_t)k * COUT + n] : 0.f);
    }
}

// ============ k_bn4: single-block full BN stats over center_size(boxes) =============
__global__ __launch_bounds__(1024) void k_bn4(
    const float* __restrict__ boxes, const float* __restrict__ g4,
    const float* __restrict__ b4) {
    float s[4] = {0, 0, 0, 0}, q[4] = {0, 0, 0, 0};
    int t = threadIdx.x;
    for (int i = t; i < NR; i += 1024) {
        const float* b = boxes + (size_t)i * 5;
        float x1 = b[1], y1 = b[2], x2 = b[3], y2 = b[4];
        float w = x2 - x1, h = y2 - y1;
        float v0 = x1 + 0.5f * w, v1 = y1 + 0.5f * h;
        s[0] += v0; s[1] += v1; s[2] += w; s[3] += h;
        q[0] += v0 * v0; q[1] += v1 * v1; q[2] += w * w; q[3] += h * h;
    }
    #pragma unroll
    for (int o = 16; o; o >>= 1) {
        #pragma unroll
        for (int j = 0; j < 4; j++) {
            s[j] += __shfl_down_sync(0xFFFFFFFFu, s[j], o);
            q[j] += __shfl_down_sync(0xFFFFFFFFu, q[j], o);
        }
    }
    __shared__ float sm[32][8];
    int warp = t >> 5, lane = t & 31;
    if (lane == 0) {
        #pragma unroll
        for (int j = 0; j < 4; j++) { sm[warp][j] = s[j]; sm[warp][4 + j] = q[j]; }
    }
    __syncthreads();
    if (t == 0) {
        float a[8] = {0, 0, 0, 0, 0, 0, 0, 0};
        for (int w2 = 0; w2 < 32; w2++)
            for (int j = 0; j < 8; j++) a[j] += sm[w2][j];
        #pragma unroll
        for (int j = 0; j < 4; j++) {
            float m = a[j] / (float)NR;
            float v = a[4 + j] / (float)NR - m * m;
            float sc = g4[j] * rsqrtf(v + EPSV);
            g_bn4_scale[j] = sc;
            g_bn4_shift[j] = b4[j] - m * sc;
        }
    }
}

// ============ k_embed: X[:,2048:2240] = [dist_fp16 | pos | 0]; one warp/row =========
__global__ __launch_bounds__(256) void k_embed(
    const float* __restrict__ dist, const float* __restrict__ boxes,
    const float* __restrict__ posW, const float* __restrict__ posB) {
    int warp = threadIdx.x >> 5, lane = threadIdx.x & 31;
    size_t row = (size_t)blockIdx.x * 8 + warp;
    __half* xr = g_X + row * KP2;
    for (int j = lane; j < 36; j += 32)
        xr[2048 + j] = __float2half(dist[row * 36 + j]);
    const float* b = boxes + row * 5;
    float x1 = __ldg(b + 1), y1 = __ldg(b + 2), x2 = __ldg(b + 3), y2 = __ldg(b + 4);
    float w = x2 - x1, h = y2 - y1;
    float s4[4] = {x1 + 0.5f * w, y1 + 0.5f * h, w, h};
    #pragma unroll
    for (int j = 0; j < 4; j++) s4[j] = s4[j] * g_bn4_scale[j] + g_bn4_shift[j];
    for (int c = lane; c < 128; c += 32) {
        float acc = __ldg(&posB[c]);
        #pragma unroll
        for (int k = 0; k < 4; k++) acc += s4[k] * __ldg(&posW[k * 128 + c]);
        xr[2084 + c] = __float2half(fmaxf(acc, 0.f));
    }
    for (int c = lane; c < KP2 - 2212; c += 32) xr[2212 + c] = __float2half(0.f);
}

// ============ GEMM1: Y = X @ W1t', 128x256 blocks, ldmatrix, cp.async 4-stage =======
__device__ __forceinline__ void g1_load(uint32_t sbase, int slot, const __half* Ag,
                                        const __half* Bg, int chunk, int t) {
    int k0 = chunk * G1_BK;
    uint32_t aB = sbase + slot * G1_STAGE;
    uint32_t bB = aB + G1_ASZ;
    #pragma unroll
    for (int i = 0; i < 4; i++) {       // A: 128 rows x 8 chunks
        int idx = t + i * 256;
        int r = idx >> 3, c = idx & 7;
        cpa16(aB + r * G1_STRIDE + c * 16, Ag + (size_t)r * KP2 + k0 + c * 8);
    }
    #pragma unroll
    for (int i = 0; i < 8; i++) {       // B: 256 rows x 8 chunks
        int idx = t + i * 256;
        int r = idx >> 3, c = idx & 7;
        cpa16(bB + r * G1_STRIDE + c * 16, Bg + (size_t)r * KP2 + k0 + c * 8);
    }
}

__global__ __launch_bounds__(256, 1) void k_gemm1() {
    extern __shared__ char sm1[];
    uint32_t sbase = smem_u32(sm1);
    int t = threadIdx.x, warp = t >> 5, lane = t & 31;
    int wr = warp >> 1, wc = warp & 1;      // 4x2 warps, warp tile 32x128
    int g = lane >> 2, tg = lane & 3;
    const size_t rowBase = (size_t)blockIdx.y * G1_BM;
    const int colBase = blockIdx.x * G1_BN;
    const __half* Ag = g_X + rowBase * KP2;
    const __half* Bg = g_W1t + (size_t)colBase * KP2;

    float acc[2][16][4];
    #pragma unroll
    for (int i = 0; i < 2; i++)
        #pragma unroll
        for (int j = 0; j < 16; j++)
            #pragma unroll
            for (int c = 0; c < 4; c++) acc[i][j][c] = 0.f;

    const uint32_t aOff = (uint32_t)((wr * 32 + (lane & 15)) * G1_STRIDE + ((lane >> 4) << 4));
    const uint32_t bOff = (uint32_t)(G1_ASZ +
        (wc * 128 + (lane & 7) + ((lane >> 4) << 3)) * G1_STRIDE + (((lane >> 3) & 1) << 4));

    g1_load(sbase, 0, Ag, Bg, 0, t); cpa_commit();
    g1_load(sbase, 1, Ag, Bg, 1, t); cpa_commit();
    g1_load(sbase, 2, Ag, Bg, 2, t); cpa_commit();

    for (int it = 0; it < G1_NIT; ++it) {
        cpa_wait2();
        __syncthreads();
        if (it + 3 < G1_NIT) g1_load(sbase, (it + 3) & 3, Ag, Bg, it + 3, t);
        cpa_commit();

        uint32_t st = sbase + (it & 3) * G1_STAGE;
        #pragma unroll
        for (int kk = 0; kk < 4; kk++) {        // 4 x k16
            uint32_t a[2][4], b[8][4];
            #pragma unroll
            for (int mt = 0; mt < 2; mt++)
                ldsm4(a[mt], st + aOff + mt * (16 * G1_STRIDE) + kk * 32);
            #pragma unroll
            for (int ng = 0; ng < 8; ng++)
                ldsm4(b[ng], st + bOff + ng * (16 * G1_STRIDE) + kk * 32);
            #pragma unroll
            for (int mt = 0; mt < 2; mt++)
                #pragma unroll
                for (int s = 0; s < 16; s++)
                    mma16816(acc[mt][s], a[mt], b[s >> 1][(s & 1) * 2], b[s >> 1][(s & 1) * 2 + 1]);
        }
    }

    // epilogue: Y fp16
    #pragma unroll
    for (int mt = 0; mt < 2; mt++) {
        size_t r0 = rowBase + wr * 32 + mt * 16 + g;
        #pragma unroll
        for (int s = 0; s < 16; s++) {
            int cc = colBase + wc * 128 + s * 8 + 2 * tg;
            __half2 h0 = __floats2half2_rn(acc[mt][s][0], acc[mt][s][1]);
            __half2 h1 = __floats2half2_rn(acc[mt][s][2], acc[mt][s][3]);
            *(__half2*)(g_Y + r0 * HID + cc) = h0;
            *(__half2*)(g_Y + (r0 + 8) * HID + cc) = h1;
        }
    }
}

// ---- BN1 column stats over fp16 Y ----
__global__ __launch_bounds__(128) void k_bn1_reduce() {
    int col = blockIdx.x * 128 + threadIdx.x;
    size_t r0 = (size_t)blockIdx.y * 1024;
    const __half* p = g_Y + r0 * HID + col;
    float s = 0.f, q = 0.f;
    #pragma unroll 4
    for (int r = 0; r < 1024; r++) {
        float v = __half2float(p[(size_t)r * HID]);
        s += v; q += v * v;
    }
    atomicAdd(&g_colsum[col], s);
    atomicAdd(&g_colsq[col], q);
}

__global__ void k_bn1_fin(const float* __restrict__ g1, const float* __restrict__ b1) {
    int c = blockIdx.x * blockDim.x + threadIdx.x;
    if (c < HID) {
        float m = g_colsum[c] / (float)NR;
        float v = g_colsq[c] / (float)NR - m * m;
        float sc = g1[c] * rsqrtf(v + EPSV);
        g_bn1_scale[c] = sc;
        g_bn1_shift[c] = b1[c] - m * sc;
    }
}

// ---- GEMM2: out = relu(BN(Y)) @ W2 + b2 ----
__device__ __forceinline__ uint32_t bn_h2(uint32_t raw, float2 sc, float2 sh) {
    __half2 h = *(__half2*)&raw;
    float2 f = __half22float2(h);
    f.x = fmaxf(f.x * sc.x + sh.x, 0.f);
    f.y = fmaxf(f.y * sc.y + sh.y, 0.f);
    __half2 o = __floats2half2_rn(f.x, f.y);
    return *(uint32_t*)&o;
}

__device__ __forceinline__ void g2_load(uint32_t sbase, int s, const __half* Ag,
                                        int chunk, int t) {
    int k0 = chunk * 32;
    uint32_t aB = sbase + 8192 + s * STAGE2_B;
    uint32_t bB = aB + 10240;
    #pragma unroll
    for (int i = 0; i < 2; i++) {
        int idx = t + i * 256;
        int r = idx >> 2, c = idx & 3;
        cpa16(aB + r * 80 + c * 16, Ag + (size_t)r * HID + k0 + c * 8);
    }
    {
        int r = t >> 2, c = t & 3;
        cpa16(bB + r * 80 + c * 16, g_W2t + (size_t)r * HID + k0 + c * 8);
    }
}

__global__ __launch_bounds__(256) void k_gemm2(const float* __restrict__ b2,
                                               float* __restrict__ out) {
    extern __shared__ char sm2[];
    float* s_scale = (float*)sm2;
    float* s_shift = s_scale + 1024;
    uint32_t sbase = smem_u32(sm2);
    int t = threadIdx.x;
    int warp = t >> 5, lane = t & 31;
    int wr = warp >> 1, wc = warp & 1;
    int g = lane >> 2, tg = lane & 3;
    const size_t rowBase = (size_t)blockIdx.y * 128;
    const __half* Ag = g_Y + rowBase * HID;

    #pragma unroll
    for (int i = t; i < 1024; i += 256) {
        s_scale[i] = g_bn1_scale[i];
        s_shift[i] = g_bn1_shift[i];
    }

    float acc[2][4][4];
    #pragma unroll
    for (int i = 0; i < 2; i++)
        #pragma unroll
        for (int j = 0; j < 4; j++)
            #pragma unroll
            for (int c = 0; c < 4; c++) acc[i][j][c] = 0.f;

    g2_load(sbase, 0, Ag, 0, t); cpa_commit();
    g2_load(sbase, 1, Ag, 1, t); cpa_commit();

    const int NIT = HID / 32;
    for (int it = 0; it < NIT; ++it) {
        cpa_wait1();
        __syncthreads();
        if (it + 2 < NIT) g2_load(sbase, (it + 2) % 3, Ag, it + 2, t);
        cpa_commit();

        const char* aS = sm2 + 8192 + (it % 3) * STAGE2_B;
        const char* bS = aS + 10240;
        #pragma unroll
        for (int kk = 0; kk < 2; kk++) {
            int kloc = kk * 16 + 2 * tg;
            int kglob = it * 32 + kloc;
            float2 sc0 = *(float2*)(s_scale + kglob);
            float2 sh0 = *(float2*)(s_shift + kglob);
            float2 sc1 = *(float2*)(s_scale + kglob + 8);
            float2 sh1 = *(float2*)(s_shift + kglob + 8);
            int kb = kloc * 2;
            uint32_t a[2][4];
            #pragma unroll
            for (int rt = 0; rt < 2; rt++) {
                int r0 = wr * 32 + rt * 16 + g;
                a[rt][0] = bn_h2(*(const uint32_t*)(aS + r0 * 80 + kb), sc0, sh0);
                a[rt][1] = bn_h2(*(const uint32_t*)(aS + (r0 + 8) * 80 + kb), sc0, sh0);
                a[rt][2] = bn_h2(*(const uint32_t*)(aS + r0 * 80 + kb + 16), sc1, sh1);
                a[rt][3] = bn_h2(*(const uint32_t*)(aS + (r0 + 8) * 80 + kb + 16), sc1, sh1);
            }
            #pragma unroll
            for (int s = 0; s < 4; s++) {
                int n = wc * 32 + s * 8 + g;
                uint32_t b0 = *(const uint32_t*)(bS + n * 80 + kb);
                uint32_t b1 = *(const uint32_t*)(bS + n * 80 + kb + 16);
                mma16816(acc[0][s], a[0], b0, b1);
                mma16816(acc[1][s], a[1], b0, b1);
            }
        }
    }

    #pragma unroll
    for (int rt = 0; rt < 2; rt++) {
        size_t r0 = rowBase + wr * 32 + rt * 16 + g;
        #pragma unroll
        for (int s = 0; s < 4; s++) {
            int cc = wc * 32 + s * 8 + 2 * tg;
            if (cc < COUT) {
                float bb = __ldg(&b2[cc]);
                out[r0 * COUT + cc] = acc[rt][s][0] + bb;
                out[(r0 + 8) * COUT + cc] = acc[rt][s][2] + bb;
            }
            if (cc + 1 < COUT) {
                float bb = __ldg(&b2[cc + 1]);
                out[r0 * COUT + cc + 1] = acc[rt][s][1] + bb;
                out[(r0 + 8) * COUT + cc + 1] = acc[rt][s][3] + bb;
            }
        }
    }
}

extern "C" void kernel_launch(void* const* d_in, const int* in_sizes, int n_in,
                              void* d_out, int out_size) {
    const float* dist  = (const float*)d_in[0];
    const float* boxes = (const float*)d_in[1];
    const float* feat  = (const float*)d_in[2];
    const float* objW  = (const float*)d_in[3];
    const float* bn4g  = (const float*)d_in[4];
    const float* bn4b  = (const float*)d_in[5];
    const float* posW  = (const float*)d_in[6];
    const float* posB  = (const float*)d_in[7];
    const float* w1    = (const float*)d_in[8];
    // d_in[9] = dec_b1: cancels inside BatchNorm, unused
    const float* bn1g  = (const float*)d_in[10];
    const float* bn1b  = (const float*)d_in[11];
    const float* w2    = (const float*)d_in[12];
    const float* b2    = (const float*)d_in[13];
    float* out = (float*)d_out;

    cudaFuncSetAttribute(k_gemm1, cudaFuncAttributeMaxDynamicSharedMemorySize, SMEM_G1);
    cudaFuncSetAttribute(k_gemm2, cudaFuncAttributeMaxDynamicSharedMemorySize, SMEM_G2);

    k_pre<<<PRE_GRID, 256>>>(feat, w1, objW, w2);
    k_bn4<<<1, 1024>>>(boxes, bn4g, bn4b);
    k_embed<<<NR / 8, 256>>>(dist, boxes, posW, posB);
    k_gemm1<<<dim3(HID / G1_BN, NR / G1_BM), 256, SMEM_G1>>>();
    k_bn1_reduce<<<dim3(HID / 128, 64), 128>>>();
    k_bn1_fin<<<4, 256>>>(bn1g, bn1b);
    k_gemm2<<<dim3(1, NR / 128), 256, SMEM_G2>>>(b2, out);
}

// round 7
// speedup vs baseline: 1.9562x; 1.0849x over previous
#include <cuda_runtime.h>
#include <cuda_fp16.h>
#include <cstdint>

#define NR 65536
#define HID 1024
#define COUT 37
#define EPSV 1e-5f
#define KP2 2240         // folded K: 2048 feat + 36 dist + 128 pos + 28 pad

// GEMM1: block 128x128, BK=64, 8 warps of 32x64, ldmatrix, cp.async 3-stage, 2 CTA/SM
#define G1_BM 128
#define G1_BN 128
#define G1_BK 64
#define G1_STRIDE 144                     // 128B data + 16B pad per k-row
#define G1_ASZ (G1_BM * G1_STRIDE)        // 18432
#define G1_BSZ (G1_BN * G1_STRIDE)        // 18432
#define G1_STAGE (G1_ASZ + G1_BSZ)        // 36864
#define SMEM_G1 (3 * G1_STAGE)            // 110592
#define G1_NIT (KP2 / G1_BK)              // 35

// GEMM2: block 128x64, BK=32, 8 warps of 32x32
#define STAGE2_B 15360
#define SMEM_G2 (8192 + 3 * STAGE2_B)

// ---- scratch (static device globals; no allocation) ----
__device__ __half g_X[(size_t)NR * KP2];
__device__ __half g_Y[(size_t)NR * HID];
__device__ __half g_W1t[(size_t)HID * KP2];   // W1' [n][k] fp16 (embed folded via M36)
__device__ __half g_W2t[(size_t)64 * HID];    // W2 [n][k] fp16, zero-padded n
__device__ float g_bn4_scale[4];
__device__ float g_bn4_shift[4];
__device__ float g_colsum[HID];
__device__ float g_colsq[HID];
__device__ float g_bn1_scale[HID];
__device__ float g_bn1_shift[HID];

__device__ __forceinline__ uint32_t smem_u32(const void* p) {
    uint32_t a;
    asm("{ .reg .u64 t; cvta.to.shared.u64 t, %1; cvt.u32.u64 %0, t; }" : "=r"(a) : "l"(p));
    return a;
}
__device__ __forceinline__ void cpa16(uint32_t dst, const void* src) {
    asm volatile("cp.async.cg.shared.global [%0], [%1], 16;" :: "r"(dst), "l"(src));
}
__device__ __forceinline__ void cpa_commit() {
    asm volatile("cp.async.commit_group;" ::: "memory");
}
__device__ __forceinline__ void cpa_wait1() {
    asm volatile("cp.async.wait_group 1;" ::: "memory");
}
__device__ __forceinline__ void ldsm4(uint32_t* r, uint32_t addr) {
    asm volatile("ldmatrix.sync.aligned.m8n8.x4.shared.b16 {%0,%1,%2,%3}, [%4];"
                 : "=r"(r[0]), "=r"(r[1]), "=r"(r[2]), "=r"(r[3]) : "r"(addr));
}
__device__ __forceinline__ void mma16816(float* c, const uint32_t* a, uint32_t b0, uint32_t b1) {
    asm volatile(
        "mma.sync.aligned.m16n8k16.row.col.f32.f16.f16.f32 "
        "{%0,%1,%2,%3}, {%4,%5,%6,%7}, {%8,%9}, {%0,%1,%2,%3};"
        : "+f"(c[0]), "+f"(c[1]), "+f"(c[2]), "+f"(c[3])
        : "r"(a[0]), "r"(a[1]), "r"(a[2]), "r"(a[3]), "r"(b0), "r"(b1));
}

// ============ k_bn4: single-block BN stats over center_size(boxes) — runs FIRST ====
__global__ __launch_bounds__(1024) void k_bn4(
    const float* __restrict__ boxes, const float* __restrict__ g4,
    const float* __restrict__ b4) {
    float s[4] = {0, 0, 0, 0}, q[4] = {0, 0, 0, 0};
    int t = threadIdx.x;
    for (int i = t; i < NR; i += 1024) {
        const float* b = boxes + (size_t)i * 5;
        float x1 = b[1], y1 = b[2], x2 = b[3], y2 = b[4];
        float w = x2 - x1, h = y2 - y1;
        float v0 = x1 + 0.5f * w, v1 = y1 + 0.5f * h;
        s[0] += v0; s[1] += v1; s[2] += w; s[3] += h;
        q[0] += v0 * v0; q[1] += v1 * v1; q[2] += w * w; q[3] += h * h;
    }
    #pragma unroll
    for (int o = 16; o; o >>= 1) {
        #pragma unroll
        for (int j = 0; j < 4; j++) {
            s[j] += __shfl_down_sync(0xFFFFFFFFu, s[j], o);
            q[j] += __shfl_down_sync(0xFFFFFFFFu, q[j], o);
        }
    }
    __shared__ float sm[32][8];
    int warp = t >> 5, lane = t & 31;
    if (lane == 0) {
        #pragma unroll
        for (int j = 0; j < 4; j++) { sm[warp][j] = s[j]; sm[warp][4 + j] = q[j]; }
    }
    __syncthreads();
    if (t == 0) {
        float a[8] = {0, 0, 0, 0, 0, 0, 0, 0};
        for (int w2 = 0; w2 < 32; w2++)
            for (int j = 0; j < 8; j++) a[j] += sm[w2][j];
        #pragma unroll
        for (int j = 0; j < 4; j++) {
            float m = a[j] / (float)NR;
            float v = a[4 + j] / (float)NR - m * m;
            float sc = g4[j] * rsqrtf(v + EPSV);
            g_bn4_scale[j] = sc;
            g_bn4_shift[j] = b4[j] - m * sc;
        }
    }
}

// ============ k_pre: fused prep (feat cvt + W1 transpose + M36 + W2 + init + embed) =
// roles by blockIdx.x:
//  [0,4096)             feat fp32->fp16 streaming into X[:,0:2048]
//  [4096,6272)          W1 transpose 32x32 tiles
//  [6272,6304)          M36 = objW @ W1[2048:2248,:] + zero pad k>=2212
//  [6304]               zero colsum/colsq
//  [6305,6561)          W2 transpose
//  [6561,14753)         embed: X[:,2048:2240] = [dist | pos | 0], one warp per row
#define RB_TR 4096
#define RB_M36 6272
#define RB_INIT 6304
#define RB_W2 6305
#define RB_EMB 6561
#define PRE_GRID (RB_EMB + NR / 8)

__global__ __launch_bounds__(256) void k_pre(
    const float* __restrict__ feat, const float* __restrict__ w1,
    const float* __restrict__ objW, const float* __restrict__ w2,
    const float* __restrict__ dist, const float* __restrict__ boxes,
    const float* __restrict__ posW, const float* __restrict__ posB) {
    int b = blockIdx.x, t = threadIdx.x;
    if (b < RB_TR) {
        for (size_t cid = (size_t)b * 256 + t; cid < (size_t)NR * 256; cid += (size_t)RB_TR * 256) {
            size_t row = cid >> 8;
            int c = (int)(cid & 255);
            const float4* s = (const float4*)(feat + row * 2048 + c * 8);
            float4 v0 = s[0], v1 = s[1];
            __half2 h0 = __floats2half2_rn(v0.x, v0.y);
            __half2 h1 = __floats2half2_rn(v0.z, v0.w);
            __half2 h2 = __floats2half2_rn(v1.x, v1.y);
            __half2 h3 = __floats2half2_rn(v1.z, v1.w);
            uint4 u;
            u.x = *(uint32_t*)&h0; u.y = *(uint32_t*)&h1;
            u.z = *(uint32_t*)&h2; u.w = *(uint32_t*)&h3;
            *(uint4*)(g_X + row * KP2 + c * 8) = u;
        }
    } else if (b < RB_M36) {
        __shared__ float sm[32][33];
        int tile = b - RB_TR;
        int kt = tile % 68, nt = tile / 68;
        int n0 = nt * 32;
        int k0 = (kt < 64) ? kt * 32 : 2248 + (kt - 64) * 32;
        int dk0 = (kt < 64) ? kt * 32 : 2084 + (kt - 64) * 32;
        int tx = t & 31, tyb = t >> 5;
        #pragma unroll
        for (int p = 0; p < 4; p++) {
            int ty = tyb + p * 8;
            sm[ty][tx] = w1[(size_t)(k0 + ty) * HID + n0 + tx];
        }
        __syncthreads();
        #pragma unroll
        for (int p = 0; p < 4; p++) {
            int ty = tyb + p * 8;
            g_W1t[(size_t)(n0 + ty) * KP2 + dk0 + tx] = __float2half(sm[tx][ty]);
        }
    } else if (b < RB_INIT) {
        int n = (b - RB_M36) * 32 + (t & 31);
        for (int j = t >> 5; j < 36; j += 8) {
            float acc = 0.f;
            for (int p = 0; p < 200; p++)
                acc += __ldg(&objW[j * 200 + p]) * __ldg(&w1[(size_t)(2048 + p) * HID + n]);
            g_W1t[(size_t)n * KP2 + 2048 + j] = __float2half(acc);
        }
        for (int k = 2212 + (t >> 5); k < KP2; k += 8)
            g_W1t[(size_t)n * KP2 + k] = __float2half(0.f);
    } else if (b == RB_INIT) {
        for (int i = t; i < HID; i += 256) { g_colsum[i] = 0.f; g_colsq[i] = 0.f; }
    } else if (b < RB_EMB) {
        int idx = (b - RB_W2) * 256 + t;
        int n = idx >> 10, k = idx & 1023;
        g_W2t[idx] = __float2half(n < COUT ? w2[(size_t)k * COUT + n] : 0.f);
    } else {
        int warp = t >> 5, lane = t & 31;
        size_t row = (size_t)(b - RB_EMB) * 8 + warp;
        __half* xr = g_X + row * KP2;
        for (int j = lane; j < 36; j += 32)
            xr[2048 + j] = __float2half(dist[row * 36 + j]);
        const float* bx = boxes + row * 5;
        float x1 = __ldg(bx + 1), y1 = __ldg(bx + 2), x2 = __ldg(bx + 3), y2 = __ldg(bx + 4);
        float w = x2 - x1, h = y2 - y1;
        float s4[4] = {x1 + 0.5f * w, y1 + 0.5f * h, w, h};
        #pragma unroll
        for (int j = 0; j < 4; j++) s4[j] = s4[j] * g_bn4_scale[j] + g_bn4_shift[j];
        for (int c = lane; c < 128; c += 32) {
            float acc = __ldg(&posB[c]);
            #pragma unroll
            for (int k = 0; k < 4; k++) acc += s4[k] * __ldg(&posW[k * 128 + c]);
            xr[2084 + c] = __float2half(fmaxf(acc, 0.f));
        }
        for (int c = lane; c < KP2 - 2212; c += 32) xr[2212 + c] = __float2half(0.f);
    }
}

// ============ GEMM1: Y = X @ W1t', 128x128 blocks, 3-stage, 2 CTA/SM ===============
__device__ __forceinline__ void g1_load(uint32_t sbase, int slot, const __half* Ag,
                                        const __half* Bg, int chunk, int t) {
    int k0 = chunk * G1_BK;
    uint32_t aB = sbase + slot * G1_STAGE;
    uint32_t bB = aB + G1_ASZ;
    #pragma unroll
    for (int i = 0; i < 4; i++) {       // A: 128 rows x 8 chunks
        int idx = t + i * 256;
        int r = idx >> 3, c = idx & 7;
        cpa16(aB + r * G1_STRIDE + c * 16, Ag + (size_t)r * KP2 + k0 + c * 8);
    }
    #pragma unroll
    for (int i = 0; i < 4; i++) {       // B: 128 rows x 8 chunks
        int idx = t + i * 256;
        int r = idx >> 3, c = idx & 7;
        cpa16(bB + r * G1_STRIDE + c * 16, Bg + (size_t)r * KP2 + k0 + c * 8);
    }
}

__global__ __launch_bounds__(256, 2) void k_gemm1() {
    extern __shared__ char sm1[];
    uint32_t sbase = smem_u32(sm1);
    int t = threadIdx.x, warp = t >> 5, lane = t & 31;
    int wr = warp >> 1, wc = warp & 1;      // 4x2 warps, warp tile 32x64
    int g = lane >> 2, tg = lane & 3;
    const size_t rowBase = (size_t)blockIdx.y * G1_BM;
    const int colBase = blockIdx.x * G1_BN;
    const __half* Ag = g_X + rowBase * KP2;
    const __half* Bg = g_W1t + (size_t)colBase * KP2;

    float acc[2][8][4];
    #pragma unroll
    for (int i = 0; i < 2; i++)
        #pragma unroll
        for (int j = 0; j < 8; j++)
            #pragma unroll
            for (int c = 0; c < 4; c++) acc[i][j][c] = 0.f;

    const uint32_t aOff = (uint32_t)((wr * 32 + (lane & 15)) * G1_STRIDE + ((lane >> 4) << 4));
    const uint32_t bOff = (uint32_t)(G1_ASZ +
        (wc * 64 + (lane & 7) + ((lane >> 4) << 3)) * G1_STRIDE + (((lane >> 3) & 1) << 4));

    g1_load(sbase, 0, Ag, Bg, 0, t); cpa_commit();
    g1_load(sbase, 1, Ag, Bg, 1, t); cpa_commit();

    int slot = 0;
    for (int it = 0; it < G1_NIT; ++it) {
        cpa_wait1();
        __syncthreads();
        if (it + 2 < G1_NIT) {
            int ns = slot + 2; if (ns >= 3) ns -= 3;
            g1_load(sbase, ns, Ag, Bg, it + 2, t);
        }
        cpa_commit();

        uint32_t st = sbase + slot * G1_STAGE;
        #pragma unroll
        for (int kk = 0; kk < 4; kk++) {        // 4 x k16
            uint32_t a[2][4], b[4][4];
            #pragma unroll
            for (int mt = 0; mt < 2; mt++)
                ldsm4(a[mt], st + aOff + mt * (16 * G1_STRIDE) + kk * 32);
            #pragma unroll
            for (int ng = 0; ng < 4; ng++)
                ldsm4(b[ng], st + bOff + ng * (16 * G1_STRIDE) + kk * 32);
            #pragma unroll
            for (int mt = 0; mt < 2; mt++)
                #pragma unroll
                for (int s = 0; s < 8; s++)
                    mma16816(acc[mt][s], a[mt], b[s >> 1][(s & 1) * 2], b[s >> 1][(s & 1) * 2 + 1]);
        }
        if (++slot == 3) slot = 0;
    }

    // epilogue: Y fp16
    #pragma unroll
    for (int mt = 0; mt < 2; mt++) {
        size_t r0 = rowBase + wr * 32 + mt * 16 + g;
        #pragma unroll
        for (int s = 0; s < 8; s++) {
            int cc = colBase + wc * 64 + s * 8 + 2 * tg;
            __half2 h0 = __floats2half2_rn(acc[mt][s][0], acc[mt][s][1]);
            __half2 h1 = __floats2half2_rn(acc[mt][s][2], acc[mt][s][3]);
            *(__half2*)(g_Y + r0 * HID + cc) = h0;
            *(__half2*)(g_Y + (r0 + 8) * HID + cc) = h1;
        }
    }
}

// ---- BN1 column stats over fp16 Y ----
__global__ __launch_bounds__(128) void k_bn1_reduce() {
    int col = blockIdx.x * 128 + threadIdx.x;
    size_t r0 = (size_t)blockIdx.y * 1024;
    const __half* p = g_Y + r0 * HID + col;
    float s = 0.f, q = 0.f;
    #pragma unroll 4
    for (int r = 0; r < 1024; r++) {
        float v = __half2float(p[(size_t)r * HID]);
        s += v; q += v * v;
    }
    atomicAdd(&g_colsum[col], s);
    atomicAdd(&g_colsq[col], q);
}

__global__ void k_bn1_fin(const float* __restrict__ g1, const float* __restrict__ b1) {
    int c = blockIdx.x * blockDim.x + threadIdx.x;
    if (c < HID) {
        float m = g_colsum[c] / (float)NR;
        float v = g_colsq[c] / (float)NR - m * m;
        float sc = g1[c] * rsqrtf(v + EPSV);
        g_bn1_scale[c] = sc;
        g_bn1_shift[c] = b1[c] - m * sc;
    }
}

// ---- GEMM2: out = relu(BN(Y)) @ W2 + b2 ----
__device__ __forceinline__ uint32_t bn_h2(uint32_t raw, float2 sc, float2 sh) {
    __half2 h = *(__half2*)&raw;
    float2 f = __half22float2(h);
    f.x = fmaxf(f.x * sc.x + sh.x, 0.f);
    f.y = fmaxf(f.y * sc.y + sh.y, 0.f);
    __half2 o = __floats2half2_rn(f.x, f.y);
    return *(uint32_t*)&o;
}

__device__ __forceinline__ void g2_load(uint32_t sbase, int s, const __half* Ag,
                                        int chunk, int t) {
    int k0 = chunk * 32;
    uint32_t aB = sbase + 8192 + s * STAGE2_B;
    uint32_t bB = aB + 10240;
    #pragma unroll
    for (int i = 0; i < 2; i++) {
        int idx = t + i * 256;
        int r = idx >> 2, c = idx & 3;
        cpa16(aB + r * 80 + c * 16, Ag + (size_t)r * HID + k0 + c * 8);
    }
    {
        int r = t >> 2, c = t & 3;
        cpa16(bB + r * 80 + c * 16, g_W2t + (size_t)r * HID + k0 + c * 8);
    }
}

__global__ __launch_bounds__(256) void k_gemm2(const float* __restrict__ b2,
                                               float* __restrict__ out) {
    extern __shared__ char sm2[];
    float* s_scale = (float*)sm2;
    float* s_shift = s_scale + 1024;
    uint32_t sbase = smem_u32(sm2);
    int t = threadIdx.x;
    int warp = t >> 5, lane = t & 31;
    int wr = warp >> 1, wc = warp & 1;
    int g = lane >> 2, tg = lane & 3;
    const size_t rowBase = (size_t)blockIdx.y * 128;
    const __half* Ag = g_Y + rowBase * HID;

    #pragma unroll
    for (int i = t; i < 1024; i += 256) {
        s_scale[i] = g_bn1_scale[i];
        s_shift[i] = g_bn1_shift[i];
    }

    float acc[2][4][4];
    #pragma unroll
    for (int i = 0; i < 2; i++)
        #pragma unroll
        for (int j = 0; j < 4; j++)
            #pragma unroll
            for (int c = 0; c < 4; c++) acc[i][j][c] = 0.f;

    g2_load(sbase, 0, Ag, 0, t); cpa_commit();
    g2_load(sbase, 1, Ag, 1, t); cpa_commit();

    const int NIT = HID / 32;
    for (int it = 0; it < NIT; ++it) {
        cpa_wait1();
        __syncthreads();
        if (it + 2 < NIT) g2_load(sbase, (it + 2) % 3, Ag, it + 2, t);
        cpa_commit();

        const char* aS = sm2 + 8192 + (it % 3) * STAGE2_B;
        const char* bS = aS + 10240;
        #pragma unroll
        for (int kk = 0; kk < 2; kk++) {
            int kloc = kk * 16 + 2 * tg;
            int kglob = it * 32 + kloc;
            float2 sc0 = *(float2*)(s_scale + kglob);
            float2 sh0 = *(float2*)(s_shift + kglob);
            float2 sc1 = *(float2*)(s_scale + kglob + 8);
            float2 sh1 = *(float2*)(s_shift + kglob + 8);
            int kb = kloc * 2;
            uint32_t a[2][4];
            #pragma unroll
            for (int rt = 0; rt < 2; rt++) {
                int r0 = wr * 32 + rt * 16 + g;
                a[rt][0] = bn_h2(*(const uint32_t*)(aS + r0 * 80 + kb), sc0, sh0);
                a[rt][1] = bn_h2(*(const uint32_t*)(aS + (r0 + 8) * 80 + kb), sc0, sh0);
                a[rt][2] = bn_h2(*(const uint32_t*)(aS + r0 * 80 + kb + 16), sc1, sh1);
                a[rt][3] = bn_h2(*(const uint32_t*)(aS + (r0 + 8) * 80 + kb + 16), sc1, sh1);
            }
            #pragma unroll
            for (int s = 0; s < 4; s++) {
                int n = wc * 32 + s * 8 + g;
                uint32_t b0 = *(const uint32_t*)(bS + n * 80 + kb);
                uint32_t b1 = *(const uint32_t*)(bS + n * 80 + kb + 16);
                mma16816(acc[0][s], a[0], b0, b1);
                mma16816(acc[1][s], a[1], b0, b1);
            }
        }
    }

    #pragma unroll
    for (int rt = 0; rt < 2; rt++) {
        size_t r0 = rowBase + wr * 32 + rt * 16 + g;
        #pragma unroll
        for (int s = 0; s < 4; s++) {
            int cc = wc * 32 + s * 8 + 2 * tg;
            if (cc < COUT) {
                float bb = __ldg(&b2[cc]);
                out[r0 * COUT + cc] = acc[rt][s][0] + bb;
                out[(r0 + 8) * COUT + cc] = acc[rt][s][2] + bb;
            }
            if (cc + 1 < COUT) {
                float bb = __ldg(&b2[cc + 1]);
                out[r0 * COUT + cc + 1] = acc[rt][s][1] + bb;
                out[(r0 + 8) * COUT + cc + 1] = acc[rt][s][3] + bb;
            }
        }
    }
}

extern "C" void kernel_launch(void* const* d_in, const int* in_sizes, int n_in,
                              void* d_out, int out_size) {
    const float* dist  = (const float*)d_in[0];
    const float* boxes = (const float*)d_in[1];
    const float* feat  = (const float*)d_in[2];
    const float* objW  = (const float*)d_in[3];
    const float* bn4g  = (const float*)d_in[4];
    const float* bn4b  = (const float*)d_in[5];
    const float* posW  = (const float*)d_in[6];
    const float* posB  = (const float*)d_in[7];
    const float* w1    = (const float*)d_in[8];
    // d_in[9] = dec_b1: cancels inside BatchNorm, unused
    const float* bn1g  = (const float*)d_in[10];
    const float* bn1b  = (const float*)d_in[11];
    const float* w2    = (const float*)d_in[12];
    const float* b2    = (const float*)d_in[13];
    float* out = (float*)d_out;

    cudaFuncSetAttribute(k_gemm1, cudaFuncAttributeMaxDynamicSharedMemorySize, SMEM_G1);
    cudaFuncSetAttribute(k_gemm2, cudaFuncAttributeMaxDynamicSharedMemorySize, SMEM_G2);

    k_bn4<<<1, 1024>>>(boxes, bn4g, bn4b);
    k_pre<<<PRE_GRID, 256>>>(feat, w1, objW, w2, dist, boxes, posW, posB);
    k_gemm1<<<dim3(HID / G1_BN, NR / G1_BM), 256, SMEM_G1>>>();
    k_bn1_reduce<<<dim3(HID / 128, 64), 128>>>();
    k_bn1_fin<<<4, 256>>>(bn1g, bn1b);
    k_gemm2<<<dim3(1, NR / 128), 256, SMEM_G2>>>(b2, out);
}

// round 8
// speedup vs baseline: 2.1484x; 1.0983x over previous
#include <cuda_runtime.h>
#include <cuda_fp16.h>
#include <cstdint>

#define NR 65536
#define HID 1024
#define COUT 37
#define EPSV 1e-5f
#define KP2 2240         // folded K: 2048 feat + 36 dist + 128 pos + 28 pad

// GEMM1: block 128x128, BK=64, 8 warps of 32x64, ldmatrix, cp.async 3-stage, 2 CTA/SM
#define G1_BM 128
#define G1_BN 128
#define G1_BK 64
#define G1_STRIDE 144                     // 128B data + 16B pad per k-row
#define G1_ASZ (G1_BM * G1_STRIDE)        // 18432
#define G1_BSZ (G1_BN * G1_STRIDE)        // 18432
#define G1_STAGE (G1_ASZ + G1_BSZ)        // 36864
#define SMEM_G1 (3 * G1_STAGE)            // 110592
#define G1_NIT (KP2 / G1_BK)              // 35

// GEMM2: block 128x64, BK=32, 8 warps of 32x32
#define STAGE2_B 15360
#define SMEM_G2 (8192 + 3 * STAGE2_B)

// ---- scratch (static device globals; no allocation) ----
__device__ __half g_X[(size_t)NR * KP2];
__device__ __half g_Y[(size_t)NR * HID];
__device__ __half g_W1t[(size_t)HID * KP2];   // W1' [n][k] fp16 (embed folded via M36)
__device__ __half g_W2t[(size_t)64 * HID];    // W2 [n][k] fp16, zero-padded n
__device__ float g_bn4_scale[4];
__device__ float g_bn4_shift[4];
__device__ float g_colsum[HID];
__device__ float g_colsq[HID];
__device__ float g_bn1_scale[HID];
__device__ float g_bn1_shift[HID];

__device__ __forceinline__ uint32_t smem_u32(const void* p) {
    uint32_t a;
    asm("{ .reg .u64 t; cvta.to.shared.u64 t, %1; cvt.u32.u64 %0, t; }" : "=r"(a) : "l"(p));
    return a;
}
__device__ __forceinline__ void cpa16(uint32_t dst, const void* src) {
    asm volatile("cp.async.cg.shared.global [%0], [%1], 16;" :: "r"(dst), "l"(src));
}
__device__ __forceinline__ void cpa_commit() {
    asm volatile("cp.async.commit_group;" ::: "memory");
}
__device__ __forceinline__ void cpa_wait1() {
    asm volatile("cp.async.wait_group 1;" ::: "memory");
}
__device__ __forceinline__ void ldsm4(uint32_t* r, uint32_t addr) {
    asm volatile("ldmatrix.sync.aligned.m8n8.x4.shared.b16 {%0,%1,%2,%3}, [%4];"
                 : "=r"(r[0]), "=r"(r[1]), "=r"(r[2]), "=r"(r[3]) : "r"(addr));
}
__device__ __forceinline__ void mma16816(float* c, const uint32_t* a, uint32_t b0, uint32_t b1) {
    asm volatile(
        "mma.sync.aligned.m16n8k16.row.col.f32.f16.f16.f32 "
        "{%0,%1,%2,%3}, {%4,%5,%6,%7}, {%8,%9}, {%0,%1,%2,%3};"
        : "+f"(c[0]), "+f"(c[1]), "+f"(c[2]), "+f"(c[3])
        : "r"(a[0]), "r"(a[1]), "r"(a[2]), "r"(a[3]), "r"(b0), "r"(b1));
}

// ============ k_bn4: single-block BN stats over center_size(boxes) — runs FIRST ====
__global__ __launch_bounds__(1024) void k_bn4(
    const float* __restrict__ boxes, const float* __restrict__ g4,
    const float* __restrict__ b4) {
    float s[4] = {0, 0, 0, 0}, q[4] = {0, 0, 0, 0};
    int t = threadIdx.x;
    for (int i = t; i < NR; i += 1024) {
        const float* b = boxes + (size_t)i * 5;
        float x1 = b[1], y1 = b[2], x2 = b[3], y2 = b[4];
        float w = x2 - x1, h = y2 - y1;
        float v0 = x1 + 0.5f * w, v1 = y1 + 0.5f * h;
        s[0] += v0; s[1] += v1; s[2] += w; s[3] += h;
        q[0] += v0 * v0; q[1] += v1 * v1; q[2] += w * w; q[3] += h * h;
    }
    #pragma unroll
    for (int o = 16; o; o >>= 1) {
        #pragma unroll
        for (int j = 0; j < 4; j++) {
            s[j] += __shfl_down_sync(0xFFFFFFFFu, s[j], o);
            q[j] += __shfl_down_sync(0xFFFFFFFFu, q[j], o);
        }
    }
    __shared__ float sm[32][8];
    int warp = t >> 5, lane = t & 31;
    if (lane == 0) {
        #pragma unroll
        for (int j = 0; j < 4; j++) { sm[warp][j] = s[j]; sm[warp][4 + j] = q[j]; }
    }
    __syncthreads();
    if (t == 0) {
        float a[8] = {0, 0, 0, 0, 0, 0, 0, 0};
        for (int w2 = 0; w2 < 32; w2++)
            for (int j = 0; j < 8; j++) a[j] += sm[w2][j];
        #pragma unroll
        for (int j = 0; j < 4; j++) {
            float m = a[j] / (float)NR;
            float v = a[4 + j] / (float)NR - m * m;
            float sc = g4[j] * rsqrtf(v + EPSV);
            g_bn4_scale[j] = sc;
            g_bn4_shift[j] = b4[j] - m * sc;
        }
    }
}

// ============ k_pre: fused prep (feat cvt + W1 transpose + M36 + W2 + init + embed) =
#define RB_TR 4096
#define RB_M36 6272
#define RB_INIT 6304
#define RB_W2 6305
#define RB_EMB 6561
#define PRE_GRID (RB_EMB + NR / 8)

__global__ __launch_bounds__(256) void k_pre(
    const float* __restrict__ feat, const float* __restrict__ w1,
    const float* __restrict__ objW, const float* __restrict__ w2,
    const float* __restrict__ dist, const float* __restrict__ boxes,
    const float* __restrict__ posW, const float* __restrict__ posB) {
    int b = blockIdx.x, t = threadIdx.x;
    if (b < RB_TR) {
        for (size_t cid = (size_t)b * 256 + t; cid < (size_t)NR * 256; cid += (size_t)RB_TR * 256) {
            size_t row = cid >> 8;
            int c = (int)(cid & 255);
            const float4* s = (const float4*)(feat + row * 2048 + c * 8);
            float4 v0 = s[0], v1 = s[1];
            __half2 h0 = __floats2half2_rn(v0.x, v0.y);
            __half2 h1 = __floats2half2_rn(v0.z, v0.w);
            __half2 h2 = __floats2half2_rn(v1.x, v1.y);
            __half2 h3 = __floats2half2_rn(v1.z, v1.w);
            uint4 u;
            u.x = *(uint32_t*)&h0; u.y = *(uint32_t*)&h1;
            u.z = *(uint32_t*)&h2; u.w = *(uint32_t*)&h3;
            *(uint4*)(g_X + row * KP2 + c * 8) = u;
        }
    } else if (b < RB_M36) {
        __shared__ float sm[32][33];
        int tile = b - RB_TR;
        int kt = tile % 68, nt = tile / 68;
        int n0 = nt * 32;
        int k0 = (kt < 64) ? kt * 32 : 2248 + (kt - 64) * 32;
        int dk0 = (kt < 64) ? kt * 32 : 2084 + (kt - 64) * 32;
        int tx = t & 31, tyb = t >> 5;
        #pragma unroll
        for (int p = 0; p < 4; p++) {
            int ty = tyb + p * 8;
            sm[ty][tx] = w1[(size_t)(k0 + ty) * HID + n0 + tx];
        }
        __syncthreads();
        #pragma unroll
        for (int p = 0; p < 4; p++) {
            int ty = tyb + p * 8;
            g_W1t[(size_t)(n0 + ty) * KP2 + dk0 + tx] = __float2half(sm[tx][ty]);
        }
    } else if (b < RB_INIT) {
        int n = (b - RB_M36) * 32 + (t & 31);
        for (int j = t >> 5; j < 36; j += 8) {
            float acc = 0.f;
            for (int p = 0; p < 200; p++)
                acc += __ldg(&objW[j * 200 + p]) * __ldg(&w1[(size_t)(2048 + p) * HID + n]);
            g_W1t[(size_t)n * KP2 + 2048 + j] = __float2half(acc);
        }
        for (int k = 2212 + (t >> 5); k < KP2; k += 8)
            g_W1t[(size_t)n * KP2 + k] = __float2half(0.f);
    } else if (b == RB_INIT) {
        for (int i = t; i < HID; i += 256) { g_colsum[i] = 0.f; g_colsq[i] = 0.f; }
    } else if (b < RB_EMB) {
        int idx = (b - RB_W2) * 256 + t;
        int n = idx >> 10, k = idx & 1023;
        g_W2t[idx] = __float2half(n < COUT ? w2[(size_t)k * COUT + n] : 0.f);
    } else {
        int warp = t >> 5, lane = t & 31;
        size_t row = (size_t)(b - RB_EMB) * 8 + warp;
        __half* xr = g_X + row * KP2;
        for (int j = lane; j < 36; j += 32)
            xr[2048 + j] = __float2half(dist[row * 36 + j]);
        const float* bx = boxes + row * 5;
        float x1 = __ldg(bx + 1), y1 = __ldg(bx + 2), x2 = __ldg(bx + 3), y2 = __ldg(bx + 4);
        float w = x2 - x1, h = y2 - y1;
        float s4[4] = {x1 + 0.5f * w, y1 + 0.5f * h, w, h};
        #pragma unroll
        for (int j = 0; j < 4; j++) s4[j] = s4[j] * g_bn4_scale[j] + g_bn4_shift[j];
        for (int c = lane; c < 128; c += 32) {
            float acc = __ldg(&posB[c]);
            #pragma unroll
            for (int k = 0; k < 4; k++) acc += s4[k] * __ldg(&posW[k * 128 + c]);
            xr[2084 + c] = __float2half(fmaxf(acc, 0.f));
        }
        for (int c = lane; c < KP2 - 2212; c += 32) xr[2212 + c] = __float2half(0.f);
    }
}

// ============ GEMM1: Y = X @ W1t', 128x128 blocks, 3-stage, 2 CTA/SM ===============
// Epilogue additionally folds BN1 column sum / sum-of-squares (fp32 accumulators).
__device__ __forceinline__ void g1_load(uint32_t sbase, int slot, const __half* Ag,
                                        const __half* Bg, int chunk, int t) {
    int k0 = chunk * G1_BK;
    uint32_t aB = sbase + slot * G1_STAGE;
    uint32_t bB = aB + G1_ASZ;
    #pragma unroll
    for (int i = 0; i < 4; i++) {
        int idx = t + i * 256;
        int r = idx >> 3, c = idx & 7;
        cpa16(aB + r * G1_STRIDE + c * 16, Ag + (size_t)r * KP2 + k0 + c * 8);
    }
    #pragma unroll
    for (int i = 0; i < 4; i++) {
        int idx = t + i * 256;
        int r = idx >> 3, c = idx & 7;
        cpa16(bB + r * G1_STRIDE + c * 16, Bg + (size_t)r * KP2 + k0 + c * 8);
    }
}

__global__ __launch_bounds__(256, 2) void k_gemm1() {
    extern __shared__ char sm1[];
    uint32_t sbase = smem_u32(sm1);
    int t = threadIdx.x, warp = t >> 5, lane = t & 31;
    int wr = warp >> 1, wc = warp & 1;      // 4x2 warps, warp tile 32x64
    int g = lane >> 2, tg = lane & 3;
    const size_t rowBase = (size_t)blockIdx.y * G1_BM;
    const int colBase = blockIdx.x * G1_BN;
    const __half* Ag = g_X + rowBase * KP2;
    const __half* Bg = g_W1t + (size_t)colBase * KP2;

    float acc[2][8][4];
    #pragma unroll
    for (int i = 0; i < 2; i++)
        #pragma unroll
        for (int j = 0; j < 8; j++)
            #pragma unroll
            for (int c = 0; c < 4; c++) acc[i][j][c] = 0.f;

    const uint32_t aOff = (uint32_t)((wr * 32 + (lane & 15)) * G1_STRIDE + ((lane >> 4) << 4));
    const uint32_t bOff = (uint32_t)(G1_ASZ +
        (wc * 64 + (lane & 7) + ((lane >> 4) << 3)) * G1_STRIDE + (((lane >> 3) & 1) << 4));

    g1_load(sbase, 0, Ag, Bg, 0, t); cpa_commit();
    g1_load(sbase, 1, Ag, Bg, 1, t); cpa_commit();

    int slot = 0;
    for (int it = 0; it < G1_NIT; ++it) {
        cpa_wait1();
        __syncthreads();
        if (it + 2 < G1_NIT) {
            int ns = slot + 2; if (ns >= 3) ns -= 3;
            g1_load(sbase, ns, Ag, Bg, it + 2, t);
        }
        cpa_commit();

        uint32_t st = sbase + slot * G1_STAGE;
        #pragma unroll
        for (int kk = 0; kk < 4; kk++) {
            uint32_t a[2][4], b[4][4];
            #pragma unroll
            for (int mt = 0; mt < 2; mt++)
                ldsm4(a[mt], st + aOff + mt * (16 * G1_STRIDE) + kk * 32);
            #pragma unroll
            for (int ng = 0; ng < 4; ng++)
                ldsm4(b[ng], st + bOff + ng * (16 * G1_STRIDE) + kk * 32);
            #pragma unroll
            for (int mt = 0; mt < 2; mt++)
                #pragma unroll
                for (int s = 0; s < 8; s++)
                    mma16816(acc[mt][s], a[mt], b[s >> 1][(s & 1) * 2], b[s >> 1][(s & 1) * 2 + 1]);
        }
        if (++slot == 3) slot = 0;
    }

    // ---- epilogue: Y fp16 + fused BN1 column stats ----
    #pragma unroll
    for (int mt = 0; mt < 2; mt++) {
        size_t r0 = rowBase + wr * 32 + mt * 16 + g;
        #pragma unroll
        for (int s = 0; s < 8; s++) {
            int cc = colBase + wc * 64 + s * 8 + 2 * tg;
            __half2 h0 = __floats2half2_rn(acc[mt][s][0], acc[mt][s][1]);
            __half2 h1 = __floats2half2_rn(acc[mt][s][2], acc[mt][s][3]);
            *(__half2*)(g_Y + r0 * HID + cc) = h0;
            *(__half2*)(g_Y + (r0 + 8) * HID + cc) = h1;
        }
    }

    // column stats: reuse stage smem as [128 sum][128 sq]
    __syncthreads();
    float* s_sum = (float*)sm1;
    float* s_sq = s_sum + 128;
    if (t < 128) { s_sum[t] = 0.f; s_sq[t] = 0.f; }
    __syncthreads();

    #pragma unroll
    for (int s = 0; s < 8; s++) {
        #pragma unroll
        for (int j = 0; j < 2; j++) {
            float v0 = acc[0][s][j], v1 = acc[0][s][j + 2];
            float v2 = acc[1][s][j], v3 = acc[1][s][j + 2];
            float sv = v0 + v1 + v2 + v3;
            float qv = v0 * v0 + v1 * v1 + v2 * v2 + v3 * v3;
            #pragma unroll
            for (int o = 4; o < 32; o <<= 1) {
                sv += __shfl_xor_sync(0xFFFFFFFFu, sv, o);
                qv += __shfl_xor_sync(0xFFFFFFFFu, qv, o);
            }
            if (g == 0) {
                int cl = wc * 64 + s * 8 + 2 * tg + j;   // 0..127 within block
                atomicAdd(&s_sum[cl], sv);
                atomicAdd(&s_sq[cl], qv);
            }
        }
    }
    __syncthreads();
    if (t < 128) {
        atomicAdd(&g_colsum[colBase + t], s_sum[t]);
        atomicAdd(&g_colsq[colBase + t], s_sq[t]);
    }
}

__global__ void k_bn1_fin(const float* __restrict__ g1, const float* __restrict__ b1) {
    int c = blockIdx.x * blockDim.x + threadIdx.x;
    if (c < HID) {
        float m = g_colsum[c] / (float)NR;
        float v = g_colsq[c] / (float)NR - m * m;
        float sc = g1[c] * rsqrtf(v + EPSV);
        g_bn1_scale[c] = sc;
        g_bn1_shift[c] = b1[c] - m * sc;
    }
}

// ---- GEMM2: out = relu(BN(Y)) @ W2 + b2 ----
__device__ __forceinline__ uint32_t bn_h2(uint32_t raw, float2 sc, float2 sh) {
    __half2 h = *(__half2*)&raw;
    float2 f = __half22float2(h);
    f.x = fmaxf(f.x * sc.x + sh.x, 0.f);
    f.y = fmaxf(f.y * sc.y + sh.y, 0.f);
    __half2 o = __floats2half2_rn(f.x, f.y);
    return *(uint32_t*)&o;
}

__device__ __forceinline__ void g2_load(uint32_t sbase, int s, const __half* Ag,
                                        int chunk, int t) {
    int k0 = chunk * 32;
    uint32_t aB = sbase + 8192 + s * STAGE2_B;
    uint32_t bB = aB + 10240;
    #pragma unroll
    for (int i = 0; i < 2; i++) {
        int idx = t + i * 256;
        int r = idx >> 2, c = idx & 3;
        cpa16(aB + r * 80 + c * 16, Ag + (size_t)r * HID + k0 + c * 8);
    }
    {
        int r = t >> 2, c = t & 3;
        cpa16(bB + r * 80 + c * 16, g_W2t + (size_t)r * HID + k0 + c * 8);
    }
}

__global__ __launch_bounds__(256) void k_gemm2(const float* __restrict__ b2,
                                               float* __restrict__ out) {
    extern __shared__ char sm2[];
    float* s_scale = (float*)sm2;
    float* s_shift = s_scale + 1024;
    uint32_t sbase = smem_u32(sm2);
    int t = threadIdx.x;
    int warp = t >> 5, lane = t & 31;
    int wr = warp >> 1, wc = warp & 1;
    int g = lane >> 2, tg = lane & 3;
    const size_t rowBase = (size_t)blockIdx.y * 128;
    const __half* Ag = g_Y + rowBase * HID;

    #pragma unroll
    for (int i = t; i < 1024; i += 256) {
        s_scale[i] = g_bn1_scale[i];
        s_shift[i] = g_bn1_shift[i];
    }

    float acc[2][4][4];
    #pragma unroll
    for (int i = 0; i < 2; i++)
        #pragma unroll
        for (int j = 0; j < 4; j++)
            #pragma unroll
            for (int c = 0; c < 4; c++) acc[i][j][c] = 0.f;

    g2_load(sbase, 0, Ag, 0, t); cpa_commit();
    g2_load(sbase, 1, Ag, 1, t); cpa_commit();

    const int NIT = HID / 32;
    for (int it = 0; it < NIT; ++it) {
        cpa_wait1();
        __syncthreads();
        if (it + 2 < NIT) g2_load(sbase, (it + 2) % 3, Ag, it + 2, t);
        cpa_commit();

        const char* aS = sm2 + 8192 + (it % 3) * STAGE2_B;
        const char* bS = aS + 10240;
        #pragma unroll
        for (int kk = 0; kk < 2; kk++) {
            int kloc = kk * 16 + 2 * tg;
            int kglob = it * 32 + kloc;
            float2 sc0 = *(float2*)(s_scale + kglob);
            float2 sh0 = *(float2*)(s_shift + kglob);
            float2 sc1 = *(float2*)(s_scale + kglob + 8);
            float2 sh1 = *(float2*)(s_shift + kglob + 8);
            int kb = kloc * 2;
            uint32_t a[2][4];
            #pragma unroll
            for (int rt = 0; rt < 2; rt++) {
                int r0 = wr * 32 + rt * 16 + g;
                a[rt][0] = bn_h2(*(const uint32_t*)(aS + r0 * 80 + kb), sc0, sh0);
                a[rt][1] = bn_h2(*(const uint32_t*)(aS + (r0 + 8) * 80 + kb), sc0, sh0);
                a[rt][2] = bn_h2(*(const uint32_t*)(aS + r0 * 80 + kb + 16), sc1, sh1);
                a[rt][3] = bn_h2(*(const uint32_t*)(aS + (r0 + 8) * 80 + kb + 16), sc1, sh1);
            }
            #pragma unroll
            for (int s = 0; s < 4; s++) {
                int n = wc * 32 + s * 8 + g;
                uint32_t b0 = *(const uint32_t*)(bS + n * 80 + kb);
                uint32_t b1 = *(const uint32_t*)(bS + n * 80 + kb + 16);
                mma16816(acc[0][s], a[0], b0, b1);
                mma16816(acc[1][s], a[1], b0, b1);
            }
        }
    }

    #pragma unroll
    for (int rt = 0; rt < 2; rt++) {
        size_t r0 = rowBase + wr * 32 + rt * 16 + g;
        #pragma unroll
        for (int s = 0; s < 4; s++) {
            int cc = wc * 32 + s * 8 + 2 * tg;
            if (cc < COUT) {
                float bb = __ldg(&b2[cc]);
                out[r0 * COUT + cc] = acc[rt][s][0] + bb;
                out[(r0 + 8) * COUT + cc] = acc[rt][s][2] + bb;
            }
            if (cc + 1 < COUT) {
                float bb = __ldg(&b2[cc + 1]);
                out[r0 * COUT + cc + 1] = acc[rt][s][1] + bb;
                out[(r0 + 8) * COUT + cc + 1] = acc[rt][s][3] + bb;
            }
        }
    }
}

extern "C" void kernel_launch(void* const* d_in, const int* in_sizes, int n_in,
                              void* d_out, int out_size) {
    const float* dist  = (const float*)d_in[0];
    const float* boxes = (const float*)d_in[1];
    const float* feat  = (const float*)d_in[2];
    const float* objW  = (const float*)d_in[3];
    const float* bn4g  = (const float*)d_in[4];
    const float* bn4b  = (const float*)d_in[5];
    const float* posW  = (const float*)d_in[6];
    const float* posB  = (const float*)d_in[7];
    const float* w1    = (const float*)d_in[8];
    // d_in[9] = dec_b1: cancels inside BatchNorm, unused
    const float* bn1g  = (const float*)d_in[10];
    const float* bn1b  = (const float*)d_in[11];
    const float* w2    = (const float*)d_in[12];
    const float* b2    = (const float*)d_in[13];
    float* out = (float*)d_out;

    cudaFuncSetAttribute(k_gemm1, cudaFuncAttributeMaxDynamicSharedMemorySize, SMEM_G1);
    cudaFuncSetAttribute(k_gemm2, cudaFuncAttributeMaxDynamicSharedMemorySize, SMEM_G2);

    k_bn4<<<1, 1024>>>(boxes, bn4g, bn4b);
    k_pre<<<PRE_GRID, 256>>>(feat, w1, objW, w2, dist, boxes, posW, posB);
    k_gemm1<<<dim3(HID / G1_BN, NR / G1_BM), 256, SMEM_G1>>>();
    k_bn1_fin<<<4, 256>>>(bn1g, bn1b);
    k_gemm2<<<dim3(1, NR / 128), 256, SMEM_G2>>>(b2, out);
}

// round 9
// speedup vs baseline: 2.1728x; 1.0114x over previous
#include <cuda_runtime.h>
#include <cuda_fp16.h>
#include <cstdint>

#define NR 65536
#define HID 1024
#define COUT 37
#define EPSV 1e-5f
#define KP2 2240         // folded K: 2048 feat + 36 dist + 128 pos + 28 pad

// GEMM1: block 128x128, BK=64, 8 warps of 32x64, ldmatrix, cp.async 3-stage, 2 CTA/SM
#define G1_BM 128
#define G1_BN 128
#define G1_BK 64
#define G1_STRIDE 144                     // 128B data + 16B pad per k-row
#define G1_ASZ (G1_BM * G1_STRIDE)        // 18432
#define G1_BSZ (G1_BN * G1_STRIDE)        // 18432
#define G1_STAGE (G1_ASZ + G1_BSZ)        // 36864
#define SMEM_G1 (3 * G1_STAGE)            // 110592
#define G1_NIT (KP2 / G1_BK)              // 35

// GEMM2: block 128x64, BK=32, 8 warps of 32x32, 2 CTA/SM
#define STAGE2_B 15360
#define SMEM_G2 (8192 + 3 * STAGE2_B)

#define BN4_BLOCKS 264

// ---- scratch (static device globals; no allocation) ----
__device__ __half g_X[(size_t)NR * KP2];
__device__ __half g_Y[(size_t)NR * HID];
__device__ __half g_W1t[(size_t)HID * KP2];   // W1' [n][k] fp16 (embed folded via M36)
__device__ __half g_W2t[(size_t)64 * HID];    // W2 [n][k] fp16, zero-padded n
__device__ float g_bn4_part[BN4_BLOCKS][8];
__device__ float g_bn4_scale[4];
__device__ float g_bn4_shift[4];
__device__ float g_colsum[HID];
__device__ float g_colsq[HID];
__device__ float g_bn1_scale[HID];
__device__ float g_bn1_shift[HID];

__device__ __forceinline__ uint32_t smem_u32(const void* p) {
    uint32_t a;
    asm("{ .reg .u64 t; cvta.to.shared.u64 t, %1; cvt.u32.u64 %0, t; }" : "=r"(a) : "l"(p));
    return a;
}
__device__ __forceinline__ void cpa16(uint32_t dst, const void* src) {
    asm volatile("cp.async.cg.shared.global [%0], [%1], 16;" :: "r"(dst), "l"(src));
}
__device__ __forceinline__ void cpa_commit() {
    asm volatile("cp.async.commit_group;" ::: "memory");
}
__device__ __forceinline__ void cpa_wait1() {
    asm volatile("cp.async.wait_group 1;" ::: "memory");
}
__device__ __forceinline__ void ldsm4(uint32_t* r, uint32_t addr) {
    asm volatile("ldmatrix.sync.aligned.m8n8.x4.shared.b16 {%0,%1,%2,%3}, [%4];"
                 : "=r"(r[0]), "=r"(r[1]), "=r"(r[2]), "=r"(r[3]) : "r"(addr));
}
__device__ __forceinline__ void mma16816(float* c, const uint32_t* a, uint32_t b0, uint32_t b1) {
    asm volatile(
        "mma.sync.aligned.m16n8k16.row.col.f32.f16.f16.f32 "
        "{%0,%1,%2,%3}, {%4,%5,%6,%7}, {%8,%9}, {%0,%1,%2,%3};"
        : "+f"(c[0]), "+f"(c[1]), "+f"(c[2]), "+f"(c[3])
        : "r"(a[0]), "r"(a[1]), "r"(a[2]), "r"(a[3]), "r"(b0), "r"(b1));
}

// ============ k_bn4_reduce: per-block partial sums (no init needed) ================
__global__ __launch_bounds__(256) void k_bn4_reduce(const float* __restrict__ boxes) {
    float s[4] = {0, 0, 0, 0}, q[4] = {0, 0, 0, 0};
    for (int i = blockIdx.x * 256 + threadIdx.x; i < NR; i += BN4_BLOCKS * 256) {
        const float* b = boxes + (size_t)i * 5;
        float x1 = b[1], y1 = b[2], x2 = b[3], y2 = b[4];
        float w = x2 - x1, h = y2 - y1;
        float v0 = x1 + 0.5f * w, v1 = y1 + 0.5f * h;
        s[0] += v0; s[1] += v1; s[2] += w; s[3] += h;
        q[0] += v0 * v0; q[1] += v1 * v1; q[2] += w * w; q[3] += h * h;
    }
    #pragma unroll
    for (int o = 16; o; o >>= 1) {
        #pragma unroll
        for (int j = 0; j < 4; j++) {
            s[j] += __shfl_down_sync(0xFFFFFFFFu, s[j], o);
            q[j] += __shfl_down_sync(0xFFFFFFFFu, q[j], o);
        }
    }
    __shared__ float sm[8][8];
    int warp = threadIdx.x >> 5, lane = threadIdx.x & 31;
    if (lane == 0) {
        #pragma unroll
        for (int j = 0; j < 4; j++) { sm[warp][j] = s[j]; sm[warp][4 + j] = q[j]; }
    }
    __syncthreads();
    if (threadIdx.x < 8) {
        float a = 0.f;
        #pragma unroll
        for (int w2 = 0; w2 < 8; w2++) a += sm[w2][threadIdx.x];
        g_bn4_part[blockIdx.x][threadIdx.x] = a;
    }
}

__global__ void k_bn4_fin(const float* __restrict__ g4, const float* __restrict__ b4) {
    int t = threadIdx.x;          // 64 threads: t&7 = component, t>>3 = chunk
    __shared__ float acc[8][8];
    int j = t & 7, ch = t >> 3;
    float a = 0.f;
    for (int i = ch; i < BN4_BLOCKS; i += 8) a += g_bn4_part[i][j];
    acc[ch][j] = a;
    __syncthreads();
    if (t < 4) {
        float ms = 0.f, qs = 0.f;
        #pragma unroll
        for (int c = 0; c < 8; c++) { ms += acc[c][t]; qs += acc[c][t + 4]; }
        float m = ms / (float)NR;
        float v = qs / (float)NR - m * m;
        float sc = g4[t] * rsqrtf(v + EPSV);
        g_bn4_scale[t] = sc;
        g_bn4_shift[t] = b4[t] - m * sc;
    }
}

// ============ k_pre: fused prep (feat cvt + W1 transpose + M36 + W2 + init + embed) =
#define RB_TR 4096
#define RB_M36 6272
#define RB_INIT 6304
#define RB_W2 6305
#define RB_EMB 6561
#define PRE_GRID (RB_EMB + NR / 8)

__global__ __launch_bounds__(256) void k_pre(
    const float* __restrict__ feat, const float* __restrict__ w1,
    const float* __restrict__ objW, const float* __restrict__ w2,
    const float* __restrict__ dist, const float* __restrict__ boxes,
    const float* __restrict__ posW, const float* __restrict__ posB) {
    int b = blockIdx.x, t = threadIdx.x;
    if (b < RB_TR) {
        for (size_t cid = (size_t)b * 256 + t; cid < (size_t)NR * 256; cid += (size_t)RB_TR * 256) {
            size_t row = cid >> 8;
            int c = (int)(cid & 255);
            const float4* s = (const float4*)(feat + row * 2048 + c * 8);
            float4 v0 = s[0], v1 = s[1];
            __half2 h0 = __floats2half2_rn(v0.x, v0.y);
            __half2 h1 = __floats2half2_rn(v0.z, v0.w);
            __half2 h2 = __floats2half2_rn(v1.x, v1.y);
            __half2 h3 = __floats2half2_rn(v1.z, v1.w);
            uint4 u;
            u.x = *(uint32_t*)&h0; u.y = *(uint32_t*)&h1;
            u.z = *(uint32_t*)&h2; u.w = *(uint32_t*)&h3;
            *(uint4*)(g_X + row * KP2 + c * 8) = u;
        }
    } else if (b < RB_M36) {
        __shared__ float sm[32][33];
        int tile = b - RB_TR;
        int kt = tile % 68, nt = tile / 68;
        int n0 = nt * 32;
        int k0 = (kt < 64) ? kt * 32 : 2248 + (kt - 64) * 32;
        int dk0 = (kt < 64) ? kt * 32 : 2084 + (kt - 64) * 32;
        int tx = t & 31, tyb = t >> 5;
        #pragma unroll
        for (int p = 0; p < 4; p++) {
            int ty = tyb + p * 8;
            sm[ty][tx] = w1[(size_t)(k0 + ty) * HID + n0 + tx];
        }
        __syncthreads();
        #pragma unroll
        for (int p = 0; p < 4; p++) {
            int ty = tyb + p * 8;
            g_W1t[(size_t)(n0 + ty) * KP2 + dk0 + tx] = __float2half(sm[tx][ty]);
        }
    } else if (b < RB_INIT) {
        int n = (b - RB_M36) * 32 + (t & 31);
        for (int j = t >> 5; j < 36; j += 8) {
            float acc = 0.f;
            for (int p = 0; p < 200; p++)
                acc += __ldg(&objW[j * 200 + p]) * __ldg(&w1[(size_t)(2048 + p) * HID + n]);
            g_W1t[(size_t)n * KP2 + 2048 + j] = __float2half(acc);
        }
        for (int k = 2212 + (t >> 5); k < KP2; k += 8)
            g_W1t[(size_t)n * KP2 + k] = __float2half(0.f);
    } else if (b == RB_INIT) {
        for (int i = t; i < HID; i += 256) { g_colsum[i] = 0.f; g_colsq[i] = 0.f; }
    } else if (b < RB_EMB) {
        int idx = (b - RB_W2) * 256 + t;
        int n = idx >> 10, k = idx & 1023;
        g_W2t[idx] = __float2half(n < COUT ? w2[(size_t)k * COUT + n] : 0.f);
    } else {
        int warp = t >> 5, lane = t & 31;
        size_t row = (size_t)(b - RB_EMB) * 8 + warp;
        __half* xr = g_X + row * KP2;
        for (int j = lane; j < 36; j += 32)
            xr[2048 + j] = __float2half(dist[row * 36 + j]);
        const float* bx = boxes + row * 5;
        float x1 = __ldg(bx + 1), y1 = __ldg(bx + 2), x2 = __ldg(bx + 3), y2 = __ldg(bx + 4);
        float w = x2 - x1, h = y2 - y1;
        float s4[4] = {x1 + 0.5f * w, y1 + 0.5f * h, w, h};
        #pragma unroll
        for (int j = 0; j < 4; j++) s4[j] = s4[j] * g_bn4_scale[j] + g_bn4_shift[j];
        for (int c = lane; c < 128; c += 32) {
            float acc = __ldg(&posB[c]);
            #pragma unroll
            for (int k = 0; k < 4; k++) acc += s4[k] * __ldg(&posW[k * 128 + c]);
            xr[2084 + c] = __float2half(fmaxf(acc, 0.f));
        }
        for (int c = lane; c < KP2 - 2212; c += 32) xr[2212 + c] = __float2half(0.f);
    }
}

// ============ GEMM1: Y = X @ W1t', 128x128 blocks, 3-stage, 2 CTA/SM ===============
__device__ __forceinline__ void g1_load(uint32_t sbase, int slot, const __half* Ag,
                                        const __half* Bg, int chunk, int t) {
    int k0 = chunk * G1_BK;
    uint32_t aB = sbase + slot * G1_STAGE;
    uint32_t bB = aB + G1_ASZ;
    #pragma unroll
    for (int i = 0; i < 4; i++) {
        int idx = t + i * 256;
        int r = idx >> 3, c = idx & 7;
        cpa16(aB + r * G1_STRIDE + c * 16, Ag + (size_t)r * KP2 + k0 + c * 8);
    }
    #pragma unroll
    for (int i = 0; i < 4; i++) {
        int idx = t + i * 256;
        int r = idx >> 3, c = idx & 7;
        cpa16(bB + r * G1_STRIDE + c * 16, Bg + (size_t)r * KP2 + k0 + c * 8);
    }
}

__global__ __launch_bounds__(256, 2) void k_gemm1() {
    extern __shared__ char sm1[];
    uint32_t sbase = smem_u32(sm1);
    int t = threadIdx.x, warp = t >> 5, lane = t & 31;
    int wr = warp >> 1, wc = warp & 1;      // 4x2 warps, warp tile 32x64
    int g = lane >> 2, tg = lane & 3;
    const size_t rowBase = (size_t)blockIdx.y * G1_BM;
    const int colBase = blockIdx.x * G1_BN;
    const __half* Ag = g_X + rowBase * KP2;
    const __half* Bg = g_W1t + (size_t)colBase * KP2;

    float acc[2][8][4];
    #pragma unroll
    for (int i = 0; i < 2; i++)
        #pragma unroll
        for (int j = 0; j < 8; j++)
            #pragma unroll
            for (int c = 0; c < 4; c++) acc[i][j][c] = 0.f;

    const uint32_t aOff = (uint32_t)((wr * 32 + (lane & 15)) * G1_STRIDE + ((lane >> 4) << 4));
    const uint32_t bOff = (uint32_t)(G1_ASZ +
        (wc * 64 + (lane & 7) + ((lane >> 4) << 3)) * G1_STRIDE + (((lane >> 3) & 1) << 4));

    g1_load(sbase, 0, Ag, Bg, 0, t); cpa_commit();
    g1_load(sbase, 1, Ag, Bg, 1, t); cpa_commit();

    int slot = 0;
    for (int it = 0; it < G1_NIT; ++it) {
        cpa_wait1();
        __syncthreads();
        if (it + 2 < G1_NIT) {
            int ns = slot + 2; if (ns >= 3) ns -= 3;
            g1_load(sbase, ns, Ag, Bg, it + 2, t);
        }
        cpa_commit();

        uint32_t st = sbase + slot * G1_STAGE;
        #pragma unroll
        for (int kk = 0; kk < 4; kk++) {
            uint32_t a[2][4], b[4][4];
            #pragma unroll
            for (int mt = 0; mt < 2; mt++)
                ldsm4(a[mt], st + aOff + mt * (16 * G1_STRIDE) + kk * 32);
            #pragma unroll
            for (int ng = 0; ng < 4; ng++)
                ldsm4(b[ng], st + bOff + ng * (16 * G1_STRIDE) + kk * 32);
            #pragma unroll
            for (int mt = 0; mt < 2; mt++)
                #pragma unroll
                for (int s = 0; s < 8; s++)
                    mma16816(acc[mt][s], a[mt], b[s >> 1][(s & 1) * 2], b[s >> 1][(s & 1) * 2 + 1]);
        }
        if (++slot == 3) slot = 0;
    }

    // ---- epilogue: Y fp16 + fused BN1 column stats ----
    // Zero stats buffer in slot-0 smem immediately: the final two mainloop
    // iterations (it=33 slot 0 compute finished before it=34's barrier; it=34
    // uses slot 1) — last compute touches slot 1 only, so bytes [0,1024) are free.
    float* s_sum = (float*)sm1;
    float* s_sq = s_sum + 128;
    if (t < 128) { s_sum[t] = 0.f; s_sq[t] = 0.f; }

    #pragma unroll
    for (int mt = 0; mt < 2; mt++) {
        size_t r0 = rowBase + wr * 32 + mt * 16 + g;
        #pragma unroll
        for (int s = 0; s < 8; s++) {
            int cc = colBase + wc * 64 + s * 8 + 2 * tg;
            __half2 h0 = __floats2half2_rn(acc[mt][s][0], acc[mt][s][1]);
            __half2 h1 = __floats2half2_rn(acc[mt][s][2], acc[mt][s][3]);
            *(__half2*)(g_Y + r0 * HID + cc) = h0;
            *(__half2*)(g_Y + (r0 + 8) * HID + cc) = h1;
        }
    }
    __syncthreads();   // zeros visible + all warps done with smem stage reads

    #pragma unroll
    for (int s = 0; s < 8; s++) {
        #pragma unroll
        for (int j = 0; j < 2; j++) {
            float v0 = acc[0][s][j], v1 = acc[0][s][j + 2];
            float v2 = acc[1][s][j], v3 = acc[1][s][j + 2];
            float sv = v0 + v1 + v2 + v3;
            float qv = v0 * v0 + v1 * v1 + v2 * v2 + v3 * v3;
            #pragma unroll
            for (int o = 4; o < 32; o <<= 1) {
                sv += __shfl_xor_sync(0xFFFFFFFFu, sv, o);
                qv += __shfl_xor_sync(0xFFFFFFFFu, qv, o);
            }
            if (g == 0) {
                int cl = wc * 64 + s * 8 + 2 * tg + j;
                atomicAdd(&s_sum[cl], sv);
                atomicAdd(&s_sq[cl], qv);
            }
        }
    }
    __syncthreads();
    if (t < 128) {
        atomicAdd(&g_colsum[colBase + t], s_sum[t]);
        atomicAdd(&g_colsq[colBase + t], s_sq[t]);
    }
}

__global__ void k_bn1_fin(const float* __restrict__ g1, const float* __restrict__ b1) {
    int c = blockIdx.x * blockDim.x + threadIdx.x;
    if (c < HID) {
        float m = g_colsum[c] / (float)NR;
        float v = g_colsq[c] / (float)NR - m * m;
        float sc = g1[c] * rsqrtf(v + EPSV);
        g_bn1_scale[c] = sc;
        g_bn1_shift[c] = b1[c] - m * sc;
    }
}

// ---- GEMM2: out = relu(BN(Y)) @ W2 + b2, 2 CTA/SM ----
__device__ __forceinline__ uint32_t bn_h2(uint32_t raw, float2 sc, float2 sh) {
    __half2 h = *(__half2*)&raw;
    float2 f = __half22float2(h);
    f.x = fmaxf(f.x * sc.x + sh.x, 0.f);
    f.y = fmaxf(f.y * sc.y + sh.y, 0.f);
    __half2 o = __floats2half2_rn(f.x, f.y);
    return *(uint32_t*)&o;
}

__device__ __forceinline__ void g2_load(uint32_t sbase, int s, const __half* Ag,
                                        int chunk, int t) {
    int k0 = chunk * 32;
    uint32_t aB = sbase + 8192 + s * STAGE2_B;
    uint32_t bB = aB + 10240;
    #pragma unroll
    for (int i = 0; i < 2; i++) {
        int idx = t + i * 256;
        int r = idx >> 2, c = idx & 3;
        cpa16(aB + r * 80 + c * 16, Ag + (size_t)r * HID + k0 + c * 8);
    }
    {
        int r = t >> 2, c = t & 3;
        cpa16(bB + r * 80 + c * 16, g_W2t + (size_t)r * HID + k0 + c * 8);
    }
}

__global__ __launch_bounds__(256, 2) void k_gemm2(const float* __restrict__ b2,
                                                  float* __restrict__ out) {
    extern __shared__ char sm2[];
    float* s_scale = (float*)sm2;
    float* s_shift = s_scale + 1024;
    uint32_t sbase = smem_u32(sm2);
    int t = threadIdx.x;
    int warp = t >> 5, lane = t & 31;
    int wr = warp >> 1, wc = warp & 1;
    int g = lane >> 2, tg = lane & 3;
    const size_t rowBase = (size_t)blockIdx.y * 128;
    const __half* Ag = g_Y + rowBase * HID;

    #pragma unroll
    for (int i = t; i < 1024; i += 256) {
        s_scale[i] = g_bn1_scale[i];
        s_shift[i] = g_bn1_shift[i];
    }

    float acc[2][4][4];
    #pragma unroll
    for (int i = 0; i < 2; i++)
        #pragma unroll
        for (int j = 0; j < 4; j++)
            #pragma unroll
            for (int c = 0; c < 4; c++) acc[i][j][c] = 0.f;

    g2_load(sbase, 0, Ag, 0, t); cpa_commit();
    g2_load(sbase, 1, Ag, 1, t); cpa_commit();

    const int NIT = HID / 32;
    for (int it = 0; it < NIT; ++it) {
        cpa_wait1();
        __syncthreads();
        if (it + 2 < NIT) g2_load(sbase, (it + 2) % 3, Ag, it + 2, t);
        cpa_commit();

        const char* aS = sm2 + 8192 + (it % 3) * STAGE2_B;
        const char* bS = aS + 10240;
        #pragma unroll
        for (int kk = 0; kk < 2; kk++) {
            int kloc = kk * 16 + 2 * tg;
            int kglob = it * 32 + kloc;
            float2 sc0 = *(float2*)(s_scale + kglob);
            float2 sh0 = *(float2*)(s_shift + kglob);
            float2 sc1 = *(float2*)(s_scale + kglob + 8);
            float2 sh1 = *(float2*)(s_shift + kglob + 8);
            int kb = kloc * 2;
            uint32_t a[2][4];
            #pragma unroll
            for (int rt = 0; rt < 2; rt++) {
                int r0 = wr * 32 + rt * 16 + g;
                a[rt][0] = bn_h2(*(const uint32_t*)(aS + r0 * 80 + kb), sc0, sh0);
                a[rt][1] = bn_h2(*(const uint32_t*)(aS + (r0 + 8) * 80 + kb), sc0, sh0);
                a[rt][2] = bn_h2(*(const uint32_t*)(aS + r0 * 80 + kb + 16), sc1, sh1);
                a[rt][3] = bn_h2(*(const uint32_t*)(aS + (r0 + 8) * 80 + kb + 16), sc1, sh1);
            }
            #pragma unroll
            for (int s = 0; s < 4; s++) {
                int n = wc * 32 + s * 8 + g;
                uint32_t b0 = *(const uint32_t*)(bS + n * 80 + kb);
                uint32_t b1 = *(const uint32_t*)(bS + n * 80 + kb + 16);
                mma16816(acc[0][s], a[0], b0, b1);
                mma16816(acc[1][s], a[1], b0, b1);
            }
        }
    }

    #pragma unroll
    for (int rt = 0; rt < 2; rt++) {
        size_t r0 = rowBase + wr * 32 + rt * 16 + g;
        #pragma unroll
        for (int s = 0; s < 4; s++) {
            int cc = wc * 32 + s * 8 + 2 * tg;
            if (cc < COUT) {
                float bb = __ldg(&b2[cc]);
                out[r0 * COUT + cc] = acc[rt][s][0] + bb;
                out[(r0 + 8) * COUT + cc] = acc[rt][s][2] + bb;
            }
            if (cc + 1 < COUT) {
                float bb = __ldg(&b2[cc + 1]);
                out[r0 * COUT + cc + 1] = acc[rt][s][1] + bb;
                out[(r0 + 8) * COUT + cc + 1] = acc[rt][s][3] + bb;
            }
        }
    }
}

extern "C" void kernel_launch(void* const* d_in, const int* in_sizes, int n_in,
                              void* d_out, int out_size) {
    const float* dist  = (const float*)d_in[0];
    const float* boxes = (const float*)d_in[1];
    const float* feat  = (const float*)d_in[2];
    const float* objW  = (const float*)d_in[3];
    const float* bn4g  = (const float*)d_in[4];
    const float* bn4b  = (const float*)d_in[5];
    const float* posW  = (const float*)d_in[6];
    const float* posB  = (const float*)d_in[7];
    const float* w1    = (const float*)d_in[8];
    // d_in[9] = dec_b1: cancels inside BatchNorm, unused
    const float* bn1g  = (const float*)d_in[10];
    const float* bn1b  = (const float*)d_in[11];
    const float* w2    = (const float*)d_in[12];
    const float* b2    = (const float*)d_in[13];
    float* out = (float*)d_out;

    cudaFuncSetAttribute(k_gemm1, cudaFuncAttributeMaxDynamicSharedMemorySize, SMEM_G1);
    cudaFuncSetAttribute(k_gemm2, cudaFuncAttributeMaxDynamicSharedMemorySize, SMEM_G2);

    k_bn4_reduce<<<BN4_BLOCKS, 256>>>(boxes);
    k_bn4_fin<<<1, 64>>>(bn4g, bn4b);
    k_pre<<<PRE_GRID, 256>>>(feat, w1, objW, w2, dist, boxes, posW, posB);
    k_gemm1<<<dim3(HID / G1_BN, NR / G1_BM), 256, SMEM_G1>>>();   // 4th launch -> ncu capture
    k_bn1_fin<<<4, 256>>>(bn1g, bn1b);
    k_gemm2<<<dim3(1, NR / 128), 256, SMEM_G2>>>(b2, out);
}

// round 11
// speedup vs baseline: 2.2806x; 1.0496x over previous
#include <cuda_runtime.h>
#include <cuda_fp16.h>
#include <cstdint>

#define NR 65536
#define HID 1024
#define COUT 37
#define EPSV 1e-5f
#define KP2 2240         // folded K: 2048 feat + 36 dist + 128 pos + 28 pad

// GEMM1: block 128x128, BK=64, 8 warps of 32x64, ldmatrix, mbarrier 3-slot pipeline, 2 CTA/SM
#define G1_BM 128
#define G1_BN 128
#define G1_BK 64
#define G1_STRIDE 144                     // 128B data + 16B pad per k-row
#define G1_ASZ (G1_BM * G1_STRIDE)        // 18432
#define G1_BSZ (G1_BN * G1_STRIDE)        // 18432
#define G1_STAGE (G1_ASZ + G1_BSZ)        // 36864
#define G1_MBAR_OFF (3 * G1_STAGE)        // 110592
#define G1_STATS_OFF (G1_MBAR_OFF + 64)   // 110656
#define SMEM_G1 (G1_STATS_OFF + 1024)     // 111680  (x2 CTA = 223360 <= 228KB)
#define G1_NIT (KP2 / G1_BK)              // 35

// GEMM2: block 128x64, BK=32, 8 warps of 32x32, 2 CTA/SM
#define STAGE2_B 15360
#define SMEM_G2 (8192 + 3 * STAGE2_B)

#define BN4_BLOCKS 264

// ---- scratch (static device globals; no allocation) ----
__device__ __half g_X[(size_t)NR * KP2];
__device__ __half g_Y[(size_t)NR * HID];
__device__ __half g_W1t[(size_t)HID * KP2];   // W1' [n][k] fp16 (embed folded via M36)
__device__ __half g_W2t[(size_t)64 * HID];    // W2 [n][k] fp16, zero-padded n
__device__ float g_bn4_part[BN4_BLOCKS][8];
__device__ float g_bn4_scale[4];
__device__ float g_bn4_shift[4];
__device__ float g_colsum[HID];
__device__ float g_colsq[HID];
__device__ float g_bn1_scale[HID];
__device__ float g_bn1_shift[HID];

__device__ __forceinline__ uint32_t smem_u32(const void* p) {
    uint32_t a;
    asm("{ .reg .u64 t; cvta.to.shared.u64 t, %1; cvt.u32.u64 %0, t; }" : "=r"(a) : "l"(p));
    return a;
}
__device__ __forceinline__ void cpa16(uint32_t dst, const void* src) {
    asm volatile("cp.async.cg.shared.global [%0], [%1], 16;" :: "r"(dst), "l"(src));
}
__device__ __forceinline__ void cpa_commit() {
    asm volatile("cp.async.commit_group;" ::: "memory");
}
__device__ __forceinline__ void cpa_wait1() {
    asm volatile("cp.async.wait_group 1;" ::: "memory");
}
__device__ __forceinline__ void ldsm4(uint32_t* r, uint32_t addr) {
    asm volatile("ldmatrix.sync.aligned.m8n8.x4.shared.b16 {%0,%1,%2,%3}, [%4];"
                 : "=r"(r[0]), "=r"(r[1]), "=r"(r[2]), "=r"(r[3]) : "r"(addr));
}
__device__ __forceinline__ void mma16816(float* c, const uint32_t* a, uint32_t b0, uint32_t b1) {
    asm volatile(
        "mma.sync.aligned.m16n8k16.row.col.f32.f16.f16.f32 "
        "{%0,%1,%2,%3}, {%4,%5,%6,%7}, {%8,%9}, {%0,%1,%2,%3};"
        : "+f"(c[0]), "+f"(c[1]), "+f"(c[2]), "+f"(c[3])
        : "r"(a[0]), "r"(a[1]), "r"(a[2]), "r"(a[3]), "r"(b0), "r"(b1));
}

// ---- mbarrier primitives ----
__device__ __forceinline__ void mbar_init(uint32_t a, uint32_t cnt) {
    asm volatile("mbarrier.init.shared.b64 [%0], %1;" :: "r"(a), "r"(cnt) : "memory");
}
__device__ __forceinline__ void mbar_arrive(uint32_t a) {
    asm volatile("mbarrier.arrive.shared.b64 _, [%0];" :: "r"(a) : "memory");
}
// .noinc: the async arrive CONSUMES one of the expected arrivals (without it,
// the pending count is incremented first -> net zero -> deadlock; R10 bug).
__device__ __forceinline__ void cpa_mbar_arrive(uint32_t a) {
    asm volatile("cp.async.mbarrier.arrive.noinc.shared.b64 [%0];" :: "r"(a) : "memory");
}
__device__ __forceinline__ void mbar_wait(uint32_t a, int parity) {
    asm volatile(
        "{\n\t.reg .pred P1;\n\t"
        "WL_%=:\n\t"
        "mbarrier.try_wait.parity.acquire.cta.shared::cta.b64 P1, [%0], %1, 0x989680;\n\t"
        "@P1 bra.uni WD_%=;\n\t"
        "bra.uni WL_%=;\n\t"
        "WD_%=:\n\t}"
        :: "r"(a), "r"(parity) : "memory");
}

// ============ k_bn4_reduce: per-block partial sums (no init needed) ================
__global__ __launch_bounds__(256) void k_bn4_reduce(const float* __restrict__ boxes) {
    float s[4] = {0, 0, 0, 0}, q[4] = {0, 0, 0, 0};
    for (int i = blockIdx.x * 256 + threadIdx.x; i < NR; i += BN4_BLOCKS * 256) {
        const float* b = boxes + (size_t)i * 5;
        float x1 = b[1], y1 = b[2], x2 = b[3], y2 = b[4];
        float w = x2 - x1, h = y2 - y1;
        float v0 = x1 + 0.5f * w, v1 = y1 + 0.5f * h;
        s[0] += v0; s[1] += v1; s[2] += w; s[3] += h;
        q[0] += v0 * v0; q[1] += v1 * v1; q[2] += w * w; q[3] += h * h;
    }
    #pragma unroll
    for (int o = 16; o; o >>= 1) {
        #pragma unroll
        for (int j = 0; j < 4; j++) {
            s[j] += __shfl_down_sync(0xFFFFFFFFu, s[j], o);
            q[j] += __shfl_down_sync(0xFFFFFFFFu, q[j], o);
        }
    }
    __shared__ float sm[8][8];
    int warp = threadIdx.x >> 5, lane = threadIdx.x & 31;
    if (lane == 0) {
        #pragma unroll
        for (int j = 0; j < 4; j++) { sm[warp][j] = s[j]; sm[warp][4 + j] = q[j]; }
    }
    __syncthreads();
    if (threadIdx.x < 8) {
        float a = 0.f;
        #pragma unroll
        for (int w2 = 0; w2 < 8; w2++) a += sm[w2][threadIdx.x];
        g_bn4_part[blockIdx.x][threadIdx.x] = a;
    }
}

__global__ void k_bn4_fin(const float* __restrict__ g4, const float* __restrict__ b4) {
    int t = threadIdx.x;
    __shared__ float acc[8][8];
    int j = t & 7, ch = t >> 3;
    float a = 0.f;
    for (int i = ch; i < BN4_BLOCKS; i += 8) a += g_bn4_part[i][j];
    acc[ch][j] = a;
    __syncthreads();
    if (t < 4) {
        float ms = 0.f, qs = 0.f;
        #pragma unroll
        for (int c = 0; c < 8; c++) { ms += acc[c][t]; qs += acc[c][t + 4]; }
        float m = ms / (float)NR;
        float v = qs / (float)NR - m * m;
        float sc = g4[t] * rsqrtf(v + EPSV);
        g_bn4_scale[t] = sc;
        g_bn4_shift[t] = b4[t] - m * sc;
    }
}

// ============ k_pre: fused prep (feat cvt + W1 transpose + M36 + W2 + init + embed) =
#define RB_TR 4096
#define RB_M36 6272
#define RB_INIT 6304
#define RB_W2 6305
#define RB_EMB 6561
#define PRE_GRID (RB_EMB + NR / 8)

__global__ __launch_bounds__(256) void k_pre(
    const float* __restrict__ feat, const float* __restrict__ w1,
    const float* __restrict__ objW, const float* __restrict__ w2,
    const float* __restrict__ dist, const float* __restrict__ boxes,
    const float* __restrict__ posW, const float* __restrict__ posB) {
    int b = blockIdx.x, t = threadIdx.x;
    if (b < RB_TR) {
        for (size_t cid = (size_t)b * 256 + t; cid < (size_t)NR * 256; cid += (size_t)RB_TR * 256) {
            size_t row = cid >> 8;
            int c = (int)(cid & 255);
            const float4* s = (const float4*)(feat + row * 2048 + c * 8);
            float4 v0 = s[0], v1 = s[1];
            __half2 h0 = __floats2half2_rn(v0.x, v0.y);
            __half2 h1 = __floats2half2_rn(v0.z, v0.w);
            __half2 h2 = __floats2half2_rn(v1.x, v1.y);
            __half2 h3 = __floats2half2_rn(v1.z, v1.w);
            uint4 u;
            u.x = *(uint32_t*)&h0; u.y = *(uint32_t*)&h1;
            u.z = *(uint32_t*)&h2; u.w = *(uint32_t*)&h3;
            *(uint4*)(g_X + row * KP2 + c * 8) = u;
        }
    } else if (b < RB_M36) {
        __shared__ float sm[32][33];
        int tile = b - RB_TR;
        int kt = tile % 68, nt = tile / 68;
        int n0 = nt * 32;
        int k0 = (kt < 64) ? kt * 32 : 2248 + (kt - 64) * 32;
        int dk0 = (kt < 64) ? kt * 32 : 2084 + (kt - 64) * 32;
        int tx = t & 31, tyb = t >> 5;
        #pragma unroll
        for (int p = 0; p < 4; p++) {
            int ty = tyb + p * 8;
            sm[ty][tx] = w1[(size_t)(k0 + ty) * HID + n0 + tx];
        }
        __syncthreads();
        #pragma unroll
        for (int p = 0; p < 4; p++) {
            int ty = tyb + p * 8;
            g_W1t[(size_t)(n0 + ty) * KP2 + dk0 + tx] = __float2half(sm[tx][ty]);
        }
    } else if (b < RB_INIT) {
        int n = (b - RB_M36) * 32 + (t & 31);
        for (int j = t >> 5; j < 36; j += 8) {
            float acc = 0.f;
            for (int p = 0; p < 200; p++)
                acc += __ldg(&objW[j * 200 + p]) * __ldg(&w1[(size_t)(2048 + p) * HID + n]);
            g_W1t[(size_t)n * KP2 + 2048 + j] = __float2half(acc);
        }
        for (int k = 2212 + (t >> 5); k < KP2; k += 8)
            g_W1t[(size_t)n * KP2 + k] = __float2half(0.f);
    } else if (b == RB_INIT) {
        for (int i = t; i < HID; i += 256) { g_colsum[i] = 0.f; g_colsq[i] = 0.f; }
    } else if (b < RB_EMB) {
        int idx = (b - RB_W2) * 256 + t;
        int n = idx >> 10, k = idx & 1023;
        g_W2t[idx] = __float2half(n < COUT ? w2[(size_t)k * COUT + n] : 0.f);
    } else {
        int warp = t >> 5, lane = t & 31;
        size_t row = (size_t)(b - RB_EMB) * 8 + warp;
        __half* xr = g_X + row * KP2;
        for (int j = lane; j < 36; j += 32)
            xr[2048 + j] = __float2half(dist[row * 36 + j]);
        const float* bx = boxes + row * 5;
        float x1 = __ldg(bx + 1), y1 = __ldg(bx + 2), x2 = __ldg(bx + 3), y2 = __ldg(bx + 4);
        float w = x2 - x1, h = y2 - y1;
        float s4[4] = {x1 + 0.5f * w, y1 + 0.5f * h, w, h};
        #pragma unroll
        for (int j = 0; j < 4; j++) s4[j] = s4[j] * g_bn4_scale[j] + g_bn4_shift[j];
        for (int c = lane; c < 128; c += 32) {
            float acc = __ldg(&posB[c]);
            #pragma unroll
            for (int k = 0; k < 4; k++) acc += s4[k] * __ldg(&posW[k * 128 + c]);
            xr[2084 + c] = __float2half(fmaxf(acc, 0.f));
        }
        for (int c = lane; c < KP2 - 2212; c += 32) xr[2212 + c] = __float2half(0.f);
    }
}

// ============ GEMM1: Y = X @ W1t', 128x128 blocks, mbarrier pipeline, 2 CTA/SM =====
__device__ __forceinline__ void g1_load(uint32_t sbase, int slot, const __half* Ag,
                                        const __half* Bg, int chunk, int t) {
    int k0 = chunk * G1_BK;
    uint32_t aB = sbase + slot * G1_STAGE;
    uint32_t bB = aB + G1_ASZ;
    #pragma unroll
    for (int i = 0; i < 4; i++) {
        int idx = t + i * 256;
        int r = idx >> 3, c = idx & 7;
        cpa16(aB + r * G1_STRIDE + c * 16, Ag + (size_t)r * KP2 + k0 + c * 8);
    }
    #pragma unroll
    for (int i = 0; i < 4; i++) {
        int idx = t + i * 256;
        int r = idx >> 3, c = idx & 7;
        cpa16(bB + r * G1_STRIDE + c * 16, Bg + (size_t)r * KP2 + k0 + c * 8);
    }
}

__device__ __forceinline__ void g1_compute(uint32_t st, uint32_t aOff, uint32_t bOff,
                                           float acc[2][8][4]) {
    #pragma unroll
    for (int kk = 0; kk < 4; kk++) {
        uint32_t a[2][4], b[4][4];
        #pragma unroll
        for (int mt = 0; mt < 2; mt++)
            ldsm4(a[mt], st + aOff + mt * (16 * G1_STRIDE) + kk * 32);
        #pragma unroll
        for (int ng = 0; ng < 4; ng++)
            ldsm4(b[ng], st + bOff + ng * (16 * G1_STRIDE) + kk * 32);
        #pragma unroll
        for (int mt = 0; mt < 2; mt++)
            #pragma unroll
            for (int s = 0; s < 8; s++)
                mma16816(acc[mt][s], a[mt], b[s >> 1][(s & 1) * 2], b[s >> 1][(s & 1) * 2 + 1]);
    }
}

// one pipeline step for compile-time slot S at runtime iteration IT
#define G1_STEP(S, IT, PF, PE) do {                                         \
    mbar_wait(mb + (S) * 8, PF); PF ^= 1;                                   \
    g1_compute(sbase + (S) * G1_STAGE, aOff, bOff, acc);                    \
    mbar_arrive(mb + 24 + (S) * 8);                                         \
    if ((IT) + 3 < G1_NIT) {                                                \
        mbar_wait(mb + 24 + (S) * 8, PE); PE ^= 1;                          \
        g1_load(sbase, (S), Ag, Bg, (IT) + 3, t);                           \
        cpa_mbar_arrive(mb + (S) * 8);                                      \
    }                                                                       \
} while (0)

__global__ __launch_bounds__(256, 2) void k_gemm1() {
    extern __shared__ char sm1[];
    uint32_t sbase = smem_u32(sm1);
    uint32_t mb = sbase + G1_MBAR_OFF;     // full[s] at mb+8s, empty[s] at mb+24+8s
    int t = threadIdx.x, warp = t >> 5, lane = t & 31;
    int wr = warp >> 1, wc = warp & 1;      // 4x2 warps, warp tile 32x64
    int g = lane >> 2, tg = lane & 3;
    const size_t rowBase = (size_t)blockIdx.y * G1_BM;
    const int colBase = blockIdx.x * G1_BN;
    const __half* Ag = g_X + rowBase * KP2;
    const __half* Bg = g_W1t + (size_t)colBase * KP2;

    if (t == 0) {
        #pragma unroll
        for (int s = 0; s < 3; s++) {
            mbar_init(mb + s * 8, 256);        // full
            mbar_init(mb + 24 + s * 8, 256);   // empty
        }
    }
    __syncthreads();

    float acc[2][8][4];
    #pragma unroll
    for (int i = 0; i < 2; i++)
        #pragma unroll
        for (int j = 0; j < 8; j++)
            #pragma unroll
            for (int c = 0; c < 4; c++) acc[i][j][c] = 0.f;

    const uint32_t aOff = (uint32_t)((wr * 32 + (lane & 15)) * G1_STRIDE + ((lane >> 4) << 4));
    const uint32_t bOff = (uint32_t)(G1_ASZ +
        (wc * 64 + (lane & 7) + ((lane >> 4) << 3)) * G1_STRIDE + (((lane >> 3) & 1) << 4));

    // prologue: fill all 3 slots
    g1_load(sbase, 0, Ag, Bg, 0, t); cpa_mbar_arrive(mb + 0);
    g1_load(sbase, 1, Ag, Bg, 1, t); cpa_mbar_arrive(mb + 8);
    g1_load(sbase, 2, Ag, Bg, 2, t); cpa_mbar_arrive(mb + 16);

    int pf0 = 0, pf1 = 0, pf2 = 0, pe0 = 0, pe1 = 0, pe2 = 0;
    int it = 0;
    #pragma unroll 1
    for (int blk = 0; blk < 11; blk++) {     // 33 iterations
        G1_STEP(0, it, pf0, pe0);
        G1_STEP(1, it + 1, pf1, pe1);
        G1_STEP(2, it + 2, pf2, pe2);
        it += 3;
    }
    G1_STEP(0, 33, pf0, pe0);                 // tail: iters 33, 34
    G1_STEP(1, 34, pf1, pe1);

    // ---- epilogue: Y fp16 + fused BN1 column stats (dedicated smem region) ----
    float* s_sum = (float*)(sm1 + G1_STATS_OFF);
    float* s_sq = s_sum + 128;
    if (t < 128) { s_sum[t] = 0.f; s_sq[t] = 0.f; }

    #pragma unroll
    for (int mt = 0; mt < 2; mt++) {
        size_t r0 = rowBase + wr * 32 + mt * 16 + g;
        #pragma unroll
        for (int s = 0; s < 8; s++) {
            int cc = colBase + wc * 64 + s * 8 + 2 * tg;
            __half2 h0 = __floats2half2_rn(acc[mt][s][0], acc[mt][s][1]);
            __half2 h1 = __floats2half2_rn(acc[mt][s][2], acc[mt][s][3]);
            *(__half2*)(g_Y + r0 * HID + cc) = h0;
            *(__half2*)(g_Y + (r0 + 8) * HID + cc) = h1;
        }
    }
    __syncthreads();   // zeros visible; all warps past mainloop

    #pragma unroll
    for (int s = 0; s < 8; s++) {
        #pragma unroll
        for (int j = 0; j < 2; j++) {
            float v0 = acc[0][s][j], v1 = acc[0][s][j + 2];
            float v2 = acc[1][s][j], v3 = acc[1][s][j + 2];
            float sv = v0 + v1 + v2 + v3;
            float qv = v0 * v0 + v1 * v1 + v2 * v2 + v3 * v3;
            #pragma unroll
            for (int o = 4; o < 32; o <<= 1) {
                sv += __shfl_xor_sync(0xFFFFFFFFu, sv, o);
                qv += __shfl_xor_sync(0xFFFFFFFFu, qv, o);
            }
            if (g == 0) {
                int cl = wc * 64 + s * 8 + 2 * tg + j;
                atomicAdd(&s_sum[cl], sv);
                atomicAdd(&s_sq[cl], qv);
            }
        }
    }
    __syncthreads();
    if (t < 128) {
        atomicAdd(&g_colsum[colBase + t], s_sum[t]);
        atomicAdd(&g_colsq[colBase + t], s_sq[t]);
    }
}

__global__ void k_bn1_fin(const float* __restrict__ g1, const float* __restrict__ b1) {
    int c = blockIdx.x * blockDim.x + threadIdx.x;
    if (c < HID) {
        float m = g_colsum[c] / (float)NR;
        float v = g_colsq[c] / (float)NR - m * m;
        float sc = g1[c] * rsqrtf(v + EPSV);
        g_bn1_scale[c] = sc;
        g_bn1_shift[c] = b1[c] - m * sc;
    }
}

// ---- GEMM2: out = relu(BN(Y)) @ W2 + b2, 2 CTA/SM ----
__device__ __forceinline__ uint32_t bn_h2(uint32_t raw, float2 sc, float2 sh) {
    __half2 h = *(__half2*)&raw;
    float2 f = __half22float2(h);
    f.x = fmaxf(f.x * sc.x + sh.x, 0.f);
    f.y = fmaxf(f.y * sc.y + sh.y, 0.f);
    __half2 o = __floats2half2_rn(f.x, f.y);
    return *(uint32_t*)&o;
}

__device__ __forceinline__ void g2_load(uint32_t sbase, int s, const __half* Ag,
                                        int chunk, int t) {
    int k0 = chunk * 32;
    uint32_t aB = sbase + 8192 + s * STAGE2_B;
    uint32_t bB = aB + 10240;
    #pragma unroll
    for (int i = 0; i < 2; i++) {
        int idx = t + i * 256;
        int r = idx >> 2, c = idx & 3;
        cpa16(aB + r * 80 + c * 16, Ag + (size_t)r * HID + k0 + c * 8);
    }
    {
        int r = t >> 2, c = t & 3;
        cpa16(bB + r * 80 + c * 16, g_W2t + (size_t)r * HID + k0 + c * 8);
    }
}

__global__ __launch_bounds__(256, 2) void k_gemm2(const float* __restrict__ b2,
                                                  float* __restrict__ out) {
    extern __shared__ char sm2[];
    float* s_scale = (float*)sm2;
    float* s_shift = s_scale + 1024;
    uint32_t sbase = smem_u32(sm2);
    int t = threadIdx.x;
    int warp = t >> 5, lane = t & 31;
    int wr = warp >> 1, wc = warp & 1;
    int g = lane >> 2, tg = lane & 3;
    const size_t rowBase = (size_t)blockIdx.y * 128;
    const __half* Ag = g_Y + rowBase * HID;

    #pragma unroll
    for (int i = t; i < 1024; i += 256) {
        s_scale[i] = g_bn1_scale[i];
        s_shift[i] = g_bn1_shift[i];
    }

    float acc[2][4][4];
    #pragma unroll
    for (int i = 0; i < 2; i++)
        #pragma unroll
        for (int j = 0; j < 4; j++)
            #pragma unroll
            for (int c = 0; c < 4; c++) acc[i][j][c] = 0.f;

    g2_load(sbase, 0, Ag, 0, t); cpa_commit();
    g2_load(sbase, 1, Ag, 1, t); cpa_commit();

    const int NIT = HID / 32;
    for (int it = 0; it < NIT; ++it) {
        cpa_wait1();
        __syncthreads();
        if (it + 2 < NIT) g2_load(sbase, (it + 2) % 3, Ag, it + 2, t);
        cpa_commit();

        const char* aS = sm2 + 8192 + (it % 3) * STAGE2_B;
        const char* bS = aS + 10240;
        #pragma unroll
        for (int kk = 0; kk < 2; kk++) {
            int kloc = kk * 16 + 2 * tg;
            int kglob = it * 32 + kloc;
            float2 sc0 = *(float2*)(s_scale + kglob);
            float2 sh0 = *(float2*)(s_shift + kglob);
            float2 sc1 = *(float2*)(s_scale + kglob + 8);
            float2 sh1 = *(float2*)(s_shift + kglob + 8);
            int kb = kloc * 2;
            uint32_t a[2][4];
            #pragma unroll
            for (int rt = 0; rt < 2; rt++) {
                int r0 = wr * 32 + rt * 16 + g;
                a[rt][0] = bn_h2(*(const uint32_t*)(aS + r0 * 80 + kb), sc0, sh0);
                a[rt][1] = bn_h2(*(const uint32_t*)(aS + (r0 + 8) * 80 + kb), sc0, sh0);
                a[rt][2] = bn_h2(*(const uint32_t*)(aS + r0 * 80 + kb + 16), sc1, sh1);
                a[rt][3] = bn_h2(*(const uint32_t*)(aS + (r0 + 8) * 80 + kb + 16), sc1, sh1);
            }
            #pragma unroll
            for (int s = 0; s < 4; s++) {
                int n = wc * 32 + s * 8 + g;
                uint32_t b0 = *(const uint32_t*)(bS + n * 80 + kb);
                uint32_t b1 = *(const uint32_t*)(bS + n * 80 + kb + 16);
                mma16816(acc[0][s], a[0], b0, b1);
                mma16816(acc[1][s], a[1], b0, b1);
            }
        }
    }

    #pragma unroll
    for (int rt = 0; rt < 2; rt++) {
        size_t r0 = rowBase + wr * 32 + rt * 16 + g;
        #pragma unroll
        for (int s = 0; s < 4; s++) {
            int cc = wc * 32 + s * 8 + 2 * tg;
            if (cc < COUT) {
                float bb = __ldg(&b2[cc]);
                out[r0 * COUT + cc] = acc[rt][s][0] + bb;
                out[(r0 + 8) * COUT + cc] = acc[rt][s][2] + bb;
            }
            if (cc + 1 < COUT) {
                float bb = __ldg(&b2[cc + 1]);
                out[r0 * COUT + cc + 1] = acc[rt][s][1] + bb;
                out[(r0 + 8) * COUT + cc + 1] = acc[rt][s][3] + bb;
            }
        }
    }
}

extern "C" void kernel_launch(void* const* d_in, const int* in_sizes, int n_in,
                              void* d_out, int out_size) {
    const float* dist  = (const float*)d_in[0];
    const float* boxes = (const float*)d_in[1];
    const float* feat  = (const float*)d_in[2];
    const float* objW  = (const float*)d_in[3];
    const float* bn4g  = (const float*)d_in[4];
    const float* bn4b  = (const float*)d_in[5];
    const float* posW  = (const float*)d_in[6];
    const float* posB  = (const float*)d_in[7];
    const float* w1    = (const float*)d_in[8];
    // d_in[9] = dec_b1: cancels inside BatchNorm, unused
    const float* bn1g  = (const float*)d_in[10];
    const float* bn1b  = (const float*)d_in[11];
    const float* w2    = (const float*)d_in[12];
    const float* b2    = (const float*)d_in[13];
    float* out = (float*)d_out;

    cudaFuncSetAttribute(k_gemm1, cudaFuncAttributeMaxDynamicSharedMemorySize, SMEM_G1);
    cudaFuncSetAttribute(k_gemm2, cudaFuncAttributeMaxDynamicSharedMemorySize, SMEM_G2);

    k_bn4_reduce<<<BN4_BLOCKS, 256>>>(boxes);
    k_bn4_fin<<<1, 64>>>(bn4g, bn4b);
    k_pre<<<PRE_GRID, 256>>>(feat, w1, objW, w2, dist, boxes, posW, posB);
    k_gemm1<<<dim3(HID / G1_BN, NR / G1_BM), 256, SMEM_G1>>>();   // 4th launch -> ncu capture
    k_bn1_fin<<<4, 256>>>(bn1g, bn1b);
    k_gemm2<<<dim3(1, NR / 128), 256, SMEM_G2>>>(b2, out);
}

// round 12
// speedup vs baseline: 2.3756x; 1.0417x over previous
#include <cuda_runtime.h>
#include <cuda_fp16.h>
#include <cstdint>

#define NR 65536
#define HID 1024
#define COUT 37
#define EPSV 1e-5f
#define KP2 2240         // folded K: 2048 feat + 36 dist + 128 pos + 28 pad

// GEMM1: block 128x128, BK=64, 8 warps of 32x64, ldmatrix, mbarrier 3-slot pipeline, 2 CTA/SM
#define G1_BM 128
#define G1_BN 128
#define G1_BK 64
#define G1_STRIDE 144                     // 128B data + 16B pad per k-row
#define G1_ASZ (G1_BM * G1_STRIDE)        // 18432
#define G1_BSZ (G1_BN * G1_STRIDE)        // 18432
#define G1_STAGE (G1_ASZ + G1_BSZ)        // 36864
#define G1_MBAR_OFF (3 * G1_STAGE)        // 110592
#define G1_STATS_OFF (G1_MBAR_OFF + 64)   // 110656
#define SMEM_G1 (G1_STATS_OFF + 1024)     // 111680  (x2 CTA = 223360 <= 228KB)
#define G1_NIT (KP2 / G1_BK)              // 35

// GEMM2: block 128x64, BK=32, 8 warps of 32x32, 2 CTA/SM
#define STAGE2_B 15360
#define SMEM_G2 (8192 + 3 * STAGE2_B)

#define BN4_BLOCKS 264

// ---- scratch (static device globals; no allocation) ----
__device__ __half g_X[(size_t)NR * KP2];
__device__ __half g_Y[(size_t)NR * HID];
__device__ __half g_W1t[(size_t)HID * KP2];   // W1' [n][k] fp16 (embed folded via M36)
__device__ __half g_W2t[(size_t)64 * HID];    // W2 [n][k] fp16, zero-padded n
__device__ float g_bn4_part[BN4_BLOCKS][8];
__device__ float g_bn4_scale[4];
__device__ float g_bn4_shift[4];
__device__ float g_colsum[HID];
__device__ float g_colsq[HID];
__device__ float g_bn1_scale[HID];
__device__ float g_bn1_shift[HID];

__device__ __forceinline__ uint32_t smem_u32(const void* p) {
    uint32_t a;
    asm("{ .reg .u64 t; cvta.to.shared.u64 t, %1; cvt.u32.u64 %0, t; }" : "=r"(a) : "l"(p));
    return a;
}
__device__ __forceinline__ void cpa16(uint32_t dst, const void* src) {
    asm volatile("cp.async.cg.shared.global [%0], [%1], 16;" :: "r"(dst), "l"(src));
}
__device__ __forceinline__ void cpa_commit() {
    asm volatile("cp.async.commit_group;" ::: "memory");
}
__device__ __forceinline__ void cpa_wait1() {
    asm volatile("cp.async.wait_group 1;" ::: "memory");
}
__device__ __forceinline__ void ldsm4(uint32_t* r, uint32_t addr) {
    asm volatile("ldmatrix.sync.aligned.m8n8.x4.shared.b16 {%0,%1,%2,%3}, [%4];"
                 : "=r"(r[0]), "=r"(r[1]), "=r"(r[2]), "=r"(r[3]) : "r"(addr));
}
__device__ __forceinline__ void mma16816(float* c, const uint32_t* a, uint32_t b0, uint32_t b1) {
    asm volatile(
        "mma.sync.aligned.m16n8k16.row.col.f32.f16.f16.f32 "
        "{%0,%1,%2,%3}, {%4,%5,%6,%7}, {%8,%9}, {%0,%1,%2,%3};"
        : "+f"(c[0]), "+f"(c[1]), "+f"(c[2]), "+f"(c[3])
        : "r"(a[0]), "r"(a[1]), "r"(a[2]), "r"(a[3]), "r"(b0), "r"(b1));
}

// ---- mbarrier primitives ----
__device__ __forceinline__ void mbar_init(uint32_t a, uint32_t cnt) {
    asm volatile("mbarrier.init.shared.b64 [%0], %1;" :: "r"(a), "r"(cnt) : "memory");
}
__device__ __forceinline__ void mbar_arrive(uint32_t a) {
    asm volatile("mbarrier.arrive.shared.b64 _, [%0];" :: "r"(a) : "memory");
}
// .noinc: async arrive consumes one expected arrival (R10 deadlock lesson)
__device__ __forceinline__ void cpa_mbar_arrive(uint32_t a) {
    asm volatile("cp.async.mbarrier.arrive.noinc.shared.b64 [%0];" :: "r"(a) : "memory");
}
__device__ __forceinline__ void mbar_wait_acq(uint32_t a, int parity) {
    asm volatile(
        "{\n\t.reg .pred P1;\n\t"
        "WL_%=:\n\t"
        "mbarrier.try_wait.parity.acquire.cta.shared::cta.b64 P1, [%0], %1, 0x989680;\n\t"
        "@P1 bra.uni WD_%=;\n\t"
        "bra.uni WL_%=;\n\t"
        "WD_%=:\n\t}"
        :: "r"(a), "r"(parity) : "memory");
}
// relaxed wait: producer-side only (post-wait smem accesses are cp.async = async proxy)
__device__ __forceinline__ void mbar_wait_rlx(uint32_t a, int parity) {
    asm volatile(
        "{\n\t.reg .pred P1;\n\t"
        "WL_%=:\n\t"
        "mbarrier.try_wait.parity.relaxed.cta.shared::cta.b64 P1, [%0], %1, 0x989680;\n\t"
        "@P1 bra.uni WD_%=;\n\t"
        "bra.uni WL_%=;\n\t"
        "WD_%=:\n\t}"
        :: "r"(a), "r"(parity) : "memory");
}

// ============ k_bn4_reduce: per-block partial sums (no init needed) ================
__global__ __launch_bounds__(256) void k_bn4_reduce(const float* __restrict__ boxes) {
    float s[4] = {0, 0, 0, 0}, q[4] = {0, 0, 0, 0};
    for (int i = blockIdx.x * 256 + threadIdx.x; i < NR; i += BN4_BLOCKS * 256) {
        const float* b = boxes + (size_t)i * 5;
        float x1 = b[1], y1 = b[2], x2 = b[3], y2 = b[4];
        float w = x2 - x1, h = y2 - y1;
        float v0 = x1 + 0.5f * w, v1 = y1 + 0.5f * h;
        s[0] += v0; s[1] += v1; s[2] += w; s[3] += h;
        q[0] += v0 * v0; q[1] += v1 * v1; q[2] += w * w; q[3] += h * h;
    }
    #pragma unroll
    for (int o = 16; o; o >>= 1) {
        #pragma unroll
        for (int j = 0; j < 4; j++) {
            s[j] += __shfl_down_sync(0xFFFFFFFFu, s[j], o);
            q[j] += __shfl_down_sync(0xFFFFFFFFu, q[j], o);
        }
    }
    __shared__ float sm[8][8];
    int warp = threadIdx.x >> 5, lane = threadIdx.x & 31;
    if (lane == 0) {
        #pragma unroll
        for (int j = 0; j < 4; j++) { sm[warp][j] = s[j]; sm[warp][4 + j] = q[j]; }
    }
    __syncthreads();
    if (threadIdx.x < 8) {
        float a = 0.f;
        #pragma unroll
        for (int w2 = 0; w2 < 8; w2++) a += sm[w2][threadIdx.x];
        g_bn4_part[blockIdx.x][threadIdx.x] = a;
    }
}

__global__ void k_bn4_fin(const float* __restrict__ g4, const float* __restrict__ b4) {
    int t = threadIdx.x;
    __shared__ float acc[8][8];
    int j = t & 7, ch = t >> 3;
    float a = 0.f;
    for (int i = ch; i < BN4_BLOCKS; i += 8) a += g_bn4_part[i][j];
    acc[ch][j] = a;
    __syncthreads();
    if (t < 4) {
        float ms = 0.f, qs = 0.f;
        #pragma unroll
        for (int c = 0; c < 8; c++) { ms += acc[c][t]; qs += acc[c][t + 4]; }
        float m = ms / (float)NR;
        float v = qs / (float)NR - m * m;
        float sc = g4[t] * rsqrtf(v + EPSV);
        g_bn4_scale[t] = sc;
        g_bn4_shift[t] = b4[t] - m * sc;
    }
}

// ============ k_pre: fused prep (feat cvt + W1 transpose + M36 + W2 + init + embed) =
#define RB_TR 4096
#define RB_M36 6272
#define RB_INIT 6304
#define RB_W2 6305
#define RB_EMB 6561
#define PRE_GRID (RB_EMB + NR / 8)

__global__ __launch_bounds__(256) void k_pre(
    const float* __restrict__ feat, const float* __restrict__ w1,
    const float* __restrict__ objW, const float* __restrict__ w2,
    const float* __restrict__ dist, const float* __restrict__ boxes,
    const float* __restrict__ posW, const float* __restrict__ posB) {
    int b = blockIdx.x, t = threadIdx.x;
    if (b < RB_TR) {
        for (size_t cid = (size_t)b * 256 + t; cid < (size_t)NR * 256; cid += (size_t)RB_TR * 256) {
            size_t row = cid >> 8;
            int c = (int)(cid & 255);
            const float4* s = (const float4*)(feat + row * 2048 + c * 8);
            float4 v0 = s[0], v1 = s[1];
            __half2 h0 = __floats2half2_rn(v0.x, v0.y);
            __half2 h1 = __floats2half2_rn(v0.z, v0.w);
            __half2 h2 = __floats2half2_rn(v1.x, v1.y);
            __half2 h3 = __floats2half2_rn(v1.z, v1.w);
            uint4 u;
            u.x = *(uint32_t*)&h0; u.y = *(uint32_t*)&h1;
            u.z = *(uint32_t*)&h2; u.w = *(uint32_t*)&h3;
            *(uint4*)(g_X + row * KP2 + c * 8) = u;
        }
    } else if (b < RB_M36) {
        __shared__ float sm[32][33];
        int tile = b - RB_TR;
        int kt = tile % 68, nt = tile / 68;
        int n0 = nt * 32;
        int k0 = (kt < 64) ? kt * 32 : 2248 + (kt - 64) * 32;
        int dk0 = (kt < 64) ? kt * 32 : 2084 + (kt - 64) * 32;
        int tx = t & 31, tyb = t >> 5;
        #pragma unroll
        for (int p = 0; p < 4; p++) {
            int ty = tyb + p * 8;
            sm[ty][tx] = w1[(size_t)(k0 + ty) * HID + n0 + tx];
        }
        __syncthreads();
        #pragma unroll
        for (int p = 0; p < 4; p++) {
            int ty = tyb + p * 8;
            g_W1t[(size_t)(n0 + ty) * KP2 + dk0 + tx] = __float2half(sm[tx][ty]);
        }
    } else if (b < RB_INIT) {
        int n = (b - RB_M36) * 32 + (t & 31);
        for (int j = t >> 5; j < 36; j += 8) {
            float acc = 0.f;
            for (int p = 0; p < 200; p++)
                acc += __ldg(&objW[j * 200 + p]) * __ldg(&w1[(size_t)(2048 + p) * HID + n]);
            g_W1t[(size_t)n * KP2 + 2048 + j] = __float2half(acc);
        }
        for (int k = 2212 + (t >> 5); k < KP2; k += 8)
            g_W1t[(size_t)n * KP2 + k] = __float2half(0.f);
    } else if (b == RB_INIT) {
        for (int i = t; i < HID; i += 256) { g_colsum[i] = 0.f; g_colsq[i] = 0.f; }
    } else if (b < RB_EMB) {
        int idx = (b - RB_W2) * 256 + t;
        int n = idx >> 10, k = idx & 1023;
        g_W2t[idx] = __float2half(n < COUT ? w2[(size_t)k * COUT + n] : 0.f);
    } else {
        int warp = t >> 5, lane = t & 31;
        size_t row = (size_t)(b - RB_EMB) * 8 + warp;
        __half* xr = g_X + row * KP2;
        for (int j = lane; j < 36; j += 32)
            xr[2048 + j] = __float2half(dist[row * 36 + j]);
        const float* bx = boxes + row * 5;
        float x1 = __ldg(bx + 1), y1 = __ldg(bx + 2), x2 = __ldg(bx + 3), y2 = __ldg(bx + 4);
        float w = x2 - x1, h = y2 - y1;
        float s4[4] = {x1 + 0.5f * w, y1 + 0.5f * h, w, h};
        #pragma unroll
        for (int j = 0; j < 4; j++) s4[j] = s4[j] * g_bn4_scale[j] + g_bn4_shift[j];
        for (int c = lane; c < 128; c += 32) {
            float acc = __ldg(&posB[c]);
            #pragma unroll
            for (int k = 0; k < 4; k++) acc += s4[k] * __ldg(&posW[k * 128 + c]);
            xr[2084 + c] = __float2half(fmaxf(acc, 0.f));
        }
        for (int c = lane; c < KP2 - 2212; c += 32) xr[2212 + c] = __float2half(0.f);
    }
}

// ============ GEMM1: Y = X @ W1t', 128x128 blocks, mbarrier pipeline, 2 CTA/SM =====
__device__ __forceinline__ void g1_load(uint32_t sbase, int slot, const __half* Ag,
                                        const __half* Bg, int chunk, int t) {
    int k0 = chunk * G1_BK;
    uint32_t aB = sbase + slot * G1_STAGE;
    uint32_t bB = aB + G1_ASZ;
    #pragma unroll
    for (int i = 0; i < 4; i++) {
        int idx = t + i * 256;
        int r = idx >> 3, c = idx & 7;
        cpa16(aB + r * G1_STRIDE + c * 16, Ag + (size_t)r * KP2 + k0 + c * 8);
    }
    #pragma unroll
    for (int i = 0; i < 4; i++) {
        int idx = t + i * 256;
        int r = idx >> 3, c = idx & 7;
        cpa16(bB + r * G1_STRIDE + c * 16, Bg + (size_t)r * KP2 + k0 + c * 8);
    }
}

__device__ __forceinline__ void g1_compute(uint32_t st, uint32_t aOff, uint32_t bOff,
                                           float acc[2][8][4]) {
    #pragma unroll
    for (int kk = 0; kk < 4; kk++) {
        uint32_t a[2][4], b[4][4];
        #pragma unroll
        for (int mt = 0; mt < 2; mt++)
            ldsm4(a[mt], st + aOff + mt * (16 * G1_STRIDE) + kk * 32);
        #pragma unroll
        for (int ng = 0; ng < 4; ng++)
            ldsm4(b[ng], st + bOff + ng * (16 * G1_STRIDE) + kk * 32);
        #pragma unroll
        for (int mt = 0; mt < 2; mt++)
            #pragma unroll
            for (int s = 0; s < 8; s++)
                mma16816(acc[mt][s], a[mt], b[s >> 1][(s & 1) * 2], b[s >> 1][(s & 1) * 2 + 1]);
    }
}

// one pipeline step for compile-time slot S at runtime iteration IT
// full[s]: 256 cp.async.noinc arrivals. empty[s]: 8 arrivals (lane 0 per warp).
#define G1_STEP(S, IT, PF, PE) do {                                         \
    mbar_wait_acq(mb + (S) * 8, PF); PF ^= 1;                               \
    g1_compute(sbase + (S) * G1_STAGE, aOff, bOff, acc);                    \
    if (lane == 0) mbar_arrive(mb + 24 + (S) * 8);                          \
    if ((IT) + 3 < G1_NIT) {                                                \
        mbar_wait_rlx(mb + 24 + (S) * 8, PE); PE ^= 1;                      \
        g1_load(sbase, (S), Ag, Bg, (IT) + 3, t);                           \
        cpa_mbar_arrive(mb + (S) * 8);                                      \
    }                                                                       \
} while (0)

__global__ __launch_bounds__(256, 2) void k_gemm1() {
    extern __shared__ char sm1[];
    uint32_t sbase = smem_u32(sm1);
    uint32_t mb = sbase + G1_MBAR_OFF;     // full[s] at mb+8s, empty[s] at mb+24+8s
    int t = threadIdx.x, warp = t >> 5, lane = t & 31;
    int wr = warp >> 1, wc = warp & 1;      // 4x2 warps, warp tile 32x64
    int g = lane >> 2, tg = lane & 3;
    const size_t rowBase = (size_t)blockIdx.y * G1_BM;
    const int colBase = blockIdx.x * G1_BN;
    const __half* Ag = g_X + rowBase * KP2;
    const __half* Bg = g_W1t + (size_t)colBase * KP2;

    if (t == 0) {
        #pragma unroll
        for (int s = 0; s < 3; s++) {
            mbar_init(mb + s * 8, 256);        // full: per-thread cp.async arrives
            mbar_init(mb + 24 + s * 8, 8);     // empty: one arrive per warp
        }
    }
    __syncthreads();

    float acc[2][8][4];
    #pragma unroll
    for (int i = 0; i < 2; i++)
        #pragma unroll
        for (int j = 0; j < 8; j++)
            #pragma unroll
            for (int c = 0; c < 4; c++) acc[i][j][c] = 0.f;

    const uint32_t aOff = (uint32_t)((wr * 32 + (lane & 15)) * G1_STRIDE + ((lane >> 4) << 4));
    const uint32_t bOff = (uint32_t)(G1_ASZ +
        (wc * 64 + (lane & 7) + ((lane >> 4) << 3)) * G1_STRIDE + (((lane >> 3) & 1) << 4));

    // prologue: fill all 3 slots
    g1_load(sbase, 0, Ag, Bg, 0, t); cpa_mbar_arrive(mb + 0);
    g1_load(sbase, 1, Ag, Bg, 1, t); cpa_mbar_arrive(mb + 8);
    g1_load(sbase, 2, Ag, Bg, 2, t); cpa_mbar_arrive(mb + 16);

    int pf0 = 0, pf1 = 0, pf2 = 0, pe0 = 0, pe1 = 0, pe2 = 0;
    int it = 0;
    #pragma unroll 1
    for (int blk = 0; blk < 11; blk++) {     // 33 iterations
        G1_STEP(0, it, pf0, pe0);
        G1_STEP(1, it + 1, pf1, pe1);
        G1_STEP(2, it + 2, pf2, pe2);
        it += 3;
    }
    G1_STEP(0, 33, pf0, pe0);                 // tail: iters 33, 34
    G1_STEP(1, 34, pf1, pe1);

    // ---- epilogue: Y fp16 + fused BN1 column stats (dedicated smem region) ----
    float* s_sum = (float*)(sm1 + G1_STATS_OFF);
    float* s_sq = s_sum + 128;
    if (t < 128) { s_sum[t] = 0.f; s_sq[t] = 0.f; }

    #pragma unroll
    for (int mt = 0; mt < 2; mt++) {
        size_t r0 = rowBase + wr * 32 + mt * 16 + g;
        #pragma unroll
        for (int s = 0; s < 8; s++) {
            int cc = colBase + wc * 64 + s * 8 + 2 * tg;
            __half2 h0 = __floats2half2_rn(acc[mt][s][0], acc[mt][s][1]);
            __half2 h1 = __floats2half2_rn(acc[mt][s][2], acc[mt][s][3]);
            *(__half2*)(g_Y + r0 * HID + cc) = h0;
            *(__half2*)(g_Y + (r0 + 8) * HID + cc) = h1;
        }
    }
    __syncthreads();   // zeros visible; all warps past mainloop

    #pragma unroll
    for (int s = 0; s < 8; s++) {
        #pragma unroll
        for (int j = 0; j < 2; j++) {
            float v0 = acc[0][s][j], v1 = acc[0][s][j + 2];
            float v2 = acc[1][s][j], v3 = acc[1][s][j + 2];
            float sv = v0 + v1 + v2 + v3;
            float qv = v0 * v0 + v1 * v1 + v2 * v2 + v3 * v3;
            #pragma unroll
            for (int o = 4; o < 32; o <<= 1) {
                sv += __shfl_xor_sync(0xFFFFFFFFu, sv, o);
                qv += __shfl_xor_sync(0xFFFFFFFFu, qv, o);
            }
            if (g == 0) {
                int cl = wc * 64 + s * 8 + 2 * tg + j;
                atomicAdd(&s_sum[cl], sv);
                atomicAdd(&s_sq[cl], qv);
            }
        }
    }
    __syncthreads();
    if (t < 128) {
        atomicAdd(&g_colsum[colBase + t], s_sum[t]);
        atomicAdd(&g_colsq[colBase + t], s_sq[t]);
    }
}

__global__ void k_bn1_fin(const float* __restrict__ g1, const float* __restrict__ b1) {
    int c = blockIdx.x * blockDim.x + threadIdx.x;
    if (c < HID) {
        float m = g_colsum[c] / (float)NR;
        float v = g_colsq[c] / (float)NR - m * m;
        float sc = g1[c] * rsqrtf(v + EPSV);
        g_bn1_scale[c] = sc;
        g_bn1_shift[c] = b1[c] - m * sc;
    }
}

// ---- GEMM2: out = relu(BN(Y)) @ W2 + b2, 2 CTA/SM ----
__device__ __forceinline__ uint32_t bn_h2(uint32_t raw, float2 sc, float2 sh) {
    __half2 h = *(__half2*)&raw;
    float2 f = __half22float2(h);
    f.x = fmaxf(f.x * sc.x + sh.x, 0.f);
    f.y = fmaxf(f.y * sc.y + sh.y, 0.f);
    __half2 o = __floats2half2_rn(f.x, f.y);
    return *(uint32_t*)&o;
}

__device__ __forceinline__ void g2_load(uint32_t sbase, int s, const __half* Ag,
                                        int chunk, int t) {
    int k0 = chunk * 32;
    uint32_t aB = sbase + 8192 + s * STAGE2_B;
    uint32_t bB = aB + 10240;
    #pragma unroll
    for (int i = 0; i < 2; i++) {
        int idx = t + i * 256;
        int r = idx >> 2, c = idx & 3;
        cpa16(aB + r * 80 + c * 16, Ag + (size_t)r * HID + k0 + c * 8);
    }
    {
        int r = t >> 2, c = t & 3;
        cpa16(bB + r * 80 + c * 16, g_W2t + (size_t)r * HID + k0 + c * 8);
    }
}

__global__ __launch_bounds__(256, 2) void k_gemm2(const float* __restrict__ b2,
                                                  float* __restrict__ out) {
    extern __shared__ char sm2[];
    float* s_scale = (float*)sm2;
    float* s_shift = s_scale + 1024;
    uint32_t sbase = smem_u32(sm2);
    int t = threadIdx.x;
    int warp = t >> 5, lane = t & 31;
    int wr = warp >> 1, wc = warp & 1;
    int g = lane >> 2, tg = lane & 3;
    const size_t rowBase = (size_t)blockIdx.y * 128;
    const __half* Ag = g_Y + rowBase * HID;

    #pragma unroll
    for (int i = t; i < 1024; i += 256) {
        s_scale[i] = g_bn1_scale[i];
        s_shift[i] = g_bn1_shift[i];
    }

    float acc[2][4][4];
    #pragma unroll
    for (int i = 0; i < 2; i++)
        #pragma unroll
        for (int j = 0; j < 4; j++)
            #pragma unroll
            for (int c = 0; c < 4; c++) acc[i][j][c] = 0.f;

    g2_load(sbase, 0, Ag, 0, t); cpa_commit();
    g2_load(sbase, 1, Ag, 1, t); cpa_commit();

    const int NIT = HID / 32;
    for (int it = 0; it < NIT; ++it) {
        cpa_wait1();
        __syncthreads();
        if (it + 2 < NIT) g2_load(sbase, (it + 2) % 3, Ag, it + 2, t);
        cpa_commit();

        const char* aS = sm2 + 8192 + (it % 3) * STAGE2_B;
        const char* bS = aS + 10240;
        #pragma unroll
        for (int kk = 0; kk < 2; kk++) {
            int kloc = kk * 16 + 2 * tg;
            int kglob = it * 32 + kloc;
            float2 sc0 = *(float2*)(s_scale + kglob);
            float2 sh0 = *(float2*)(s_shift + kglob);
            float2 sc1 = *(float2*)(s_scale + kglob + 8);
            float2 sh1 = *(float2*)(s_shift + kglob + 8);
            int kb = kloc * 2;
            uint32_t a[2][4];
            #pragma unroll
            for (int rt = 0; rt < 2; rt++) {
                int r0 = wr * 32 + rt * 16 + g;
                a[rt][0] = bn_h2(*(const uint32_t*)(aS + r0 * 80 + kb), sc0, sh0);
                a[rt][1] = bn_h2(*(const uint32_t*)(aS + (r0 + 8) * 80 + kb), sc0, sh0);
                a[rt][2] = bn_h2(*(const uint32_t*)(aS + r0 * 80 + kb + 16), sc1, sh1);
                a[rt][3] = bn_h2(*(const uint32_t*)(aS + (r0 + 8) * 80 + kb + 16), sc1, sh1);
            }
            #pragma unroll
            for (int s = 0; s < 4; s++) {
                int n = wc * 32 + s * 8 + g;
                uint32_t b0 = *(const uint32_t*)(bS + n * 80 + kb);
                uint32_t b1 = *(const uint32_t*)(bS + n * 80 + kb + 16);
                mma16816(acc[0][s], a[0], b0, b1);
                mma16816(acc[1][s], a[1], b0, b1);
            }
        }
    }

    #pragma unroll
    for (int rt = 0; rt < 2; rt++) {
        size_t r0 = rowBase + wr * 32 + rt * 16 + g;
        #pragma unroll
        for (int s = 0; s < 4; s++) {
            int cc = wc * 32 + s * 8 + 2 * tg;
            if (cc < COUT) {
                float bb = __ldg(&b2[cc]);
                out[r0 * COUT + cc] = acc[rt][s][0] + bb;
                out[(r0 + 8) * COUT + cc] = acc[rt][s][2] + bb;
            }
            if (cc + 1 < COUT) {
                float bb = __ldg(&b2[cc + 1]);
                out[r0 * COUT + cc + 1] = acc[rt][s][1] + bb;
                out[(r0 + 8) * COUT + cc + 1] = acc[rt][s][3] + bb;
            }
        }
    }
}

extern "C" void kernel_launch(void* const* d_in, const int* in_sizes, int n_in,
                              void* d_out, int out_size) {
    const float* dist  = (const float*)d_in[0];
    const float* boxes = (const float*)d_in[1];
    const float* feat  = (const float*)d_in[2];
    const float* objW  = (const float*)d_in[3];
    const float* bn4g  = (const float*)d_in[4];
    const float* bn4b  = (const float*)d_in[5];
    const float* posW  = (const float*)d_in[6];
    const float* posB  = (const float*)d_in[7];
    const float* w1    = (const float*)d_in[8];
    // d_in[9] = dec_b1: cancels inside BatchNorm, unused
    const float* bn1g  = (const float*)d_in[10];
    const float* bn1b  = (const float*)d_in[11];
    const float* w2    = (const float*)d_in[12];
    const float* b2    = (const float*)d_in[13];
    float* out = (float*)d_out;

    cudaFuncSetAttribute(k_gemm1, cudaFuncAttributeMaxDynamicSharedMemorySize, SMEM_G1);
    cudaFuncSetAttribute(k_gemm2, cudaFuncAttributeMaxDynamicSharedMemorySize, SMEM_G2);

    k_bn4_reduce<<<BN4_BLOCKS, 256>>>(boxes);
    k_bn4_fin<<<1, 64>>>(bn4g, bn4b);
    k_pre<<<PRE_GRID, 256>>>(feat, w1, objW, w2, dist, boxes, posW, posB);
    k_gemm1<<<dim3(HID / G1_BN, NR / G1_BM), 256, SMEM_G1>>>();   // 4th launch -> ncu capture
    k_bn1_fin<<<4, 256>>>(bn1g, bn1b);
    k_gemm2<<<dim3(1, NR / 128), 256, SMEM_G2>>>(b2, out);
}